// round 1
// baseline (speedup 1.0000x reference)
#include <cuda_runtime.h>
#include <cuda_bf16.h>
#include <math.h>

// Problem constants
#define BB 2
#define TT 2048
#define DD 2048
#define HH 16
#define KK 8
#define HD 128
#define MTOT (BB*TT)   // 4096

// Scratch (device globals; no allocation allowed)
__device__ float g_q_raw[(size_t)MTOT * (HH*HD)];   // (b,t,h,d)  4096 x 2048
__device__ float g_k_raw[(size_t)MTOT * (KK*HD)];   // (b,t,kh,d) 4096 x 1024
__device__ float g_v_raw[(size_t)MTOT * (KK*HD)];   // (b,t,kh,d) 4096 x 1024
__device__ float g_o    [(size_t)MTOT * (HH*HD)];   // (b,t,h,d)  4096 x 2048

// ---------------------------------------------------------------------------
// SGEMM: C[M,N] = A[M,K] @ B[K,N], fp32, 128x128 block, 8x8 per thread
// ---------------------------------------------------------------------------
__global__ __launch_bounds__(256)
void sgemm128(const float* __restrict__ A, const float* __restrict__ Bm,
              float* __restrict__ C, int M, int N, int Kd) {
    __shared__ float As[8][132];   // transposed A tile, padded
    __shared__ float Bs[8][132];

    int tid = threadIdx.x;
    int tx = tid & 15;
    int ty = tid >> 4;
    int row0 = blockIdx.y * 128;
    int col0 = blockIdx.x * 128;

    int arow = tid >> 1;            // 0..127
    int acol = (tid & 1) * 4;       // 0 or 4
    int brow = tid >> 5;            // 0..7
    int bcol = (tid & 31) * 4;      // 0..124

    const float* Aptr = A + (size_t)(row0 + arow) * Kd + acol;
    const float* Bptr = Bm + (size_t)brow * N + col0 + bcol;

    float acc[8][8];
#pragma unroll
    for (int i = 0; i < 8; ++i)
#pragma unroll
        for (int j = 0; j < 8; ++j) acc[i][j] = 0.0f;

    for (int k0 = 0; k0 < Kd; k0 += 8) {
        float4 a4 = *(const float4*)Aptr;
        As[acol + 0][arow] = a4.x;
        As[acol + 1][arow] = a4.y;
        As[acol + 2][arow] = a4.z;
        As[acol + 3][arow] = a4.w;
        *(float4*)&Bs[brow][bcol] = *(const float4*)Bptr;
        __syncthreads();

#pragma unroll
        for (int k = 0; k < 8; ++k) {
            float ra[8], rb[8];
            *(float4*)&ra[0] = *(const float4*)&As[k][ty * 8];
            *(float4*)&ra[4] = *(const float4*)&As[k][ty * 8 + 4];
            *(float4*)&rb[0] = *(const float4*)&Bs[k][tx * 8];
            *(float4*)&rb[4] = *(const float4*)&Bs[k][tx * 8 + 4];
#pragma unroll
            for (int i = 0; i < 8; ++i)
#pragma unroll
                for (int j = 0; j < 8; ++j)
                    acc[i][j] += ra[i] * rb[j];
        }
        __syncthreads();
        Aptr += 8;
        Bptr += (size_t)8 * N;
    }

#pragma unroll
    for (int i = 0; i < 8; ++i) {
        float* crow = C + (size_t)(row0 + ty * 8 + i) * N + col0 + tx * 8;
        *(float4*)crow       = make_float4(acc[i][0], acc[i][1], acc[i][2], acc[i][3]);
        *(float4*)(crow + 4) = make_float4(acc[i][4], acc[i][5], acc[i][6], acc[i][7]);
    }
}

// ---------------------------------------------------------------------------
// Fused RMSNorm + RoPE, in-place. One warp per (b,t,head) 128-dim vector.
// ---------------------------------------------------------------------------
__global__ __launch_bounds__(256)
void normrope_kernel(float* __restrict__ q, float* __restrict__ k,
                     const float* __restrict__ qn, const float* __restrict__ kn,
                     const float* __restrict__ sinp, const float* __restrict__ cosp) {
    int warp = (blockIdx.x * blockDim.x + threadIdx.x) >> 5;
    int lane = threadIdx.x & 31;
    const int NQ = MTOT * HH;          // 65536
    const int NTOT = NQ + MTOT * KK;   // 98304
    if (warp >= NTOT) return;

    float* ptr;
    const float* w;
    int t;
    if (warp < NQ) {
        int bt = warp >> 4;
        int h = warp & 15;
        ptr = q + (size_t)bt * (HH * HD) + h * HD;
        w = qn;
        t = bt & (TT - 1);
    } else {
        int v2 = warp - NQ;
        int bt = v2 >> 3;
        int kh = v2 & 7;
        ptr = k + (size_t)bt * (KK * HD) + kh * HD;
        w = kn;
        t = bt & (TT - 1);
    }

    // lane handles pairs (2l,2l+1) and (64+2l,65+2l)
    float2 a  = *(const float2*)(ptr + 2 * lane);
    float2 b2 = *(const float2*)(ptr + 64 + 2 * lane);

    float ss = a.x * a.x + a.y * a.y + b2.x * b2.x + b2.y * b2.y;
#pragma unroll
    for (int off = 16; off; off >>= 1) ss += __shfl_xor_sync(0xFFFFFFFFu, ss, off);
    float rinv = rsqrtf(ss * (1.0f / 128.0f) + 1e-6f);

    float w0 = w[2 * lane], w1 = w[2 * lane + 1];
    float w2 = w[64 + 2 * lane], w3 = w[65 + 2 * lane];
    float n0 = a.x * rinv * w0, n1 = a.y * rinv * w1;
    float n2 = b2.x * rinv * w2, n3 = b2.y * rinv * w3;

    // RoPE: out[j] = x1[j]*c - x2[j]*s ; out[64+j] = x1[j]*s + x2[j]*c
    // j = lane uses pair (n0,n1); j = lane+32 uses pair (n2,n3)
    float s0 = sinp[t * 64 + lane],      c0 = cosp[t * 64 + lane];
    float s1 = sinp[t * 64 + lane + 32], c1 = cosp[t * 64 + lane + 32];
    float o0 = n0 * c0 - n1 * s0;   // out[lane]
    float o1 = n2 * c1 - n3 * s1;   // out[lane+32]
    float o2 = n0 * s0 + n1 * c0;   // out[64+lane]
    float o3 = n2 * s1 + n3 * c1;   // out[96+lane]

    __syncwarp();
    ptr[lane]      = o0;
    ptr[lane + 32] = o1;
    ptr[lane + 64] = o2;
    ptr[lane + 96] = o3;
}

// ---------------------------------------------------------------------------
// Flash attention (fp32, causal, online softmax). 64x64 tiles, Hd=128.
// Grid: (T/64, B*H). 256 threads. Q layout (b,t,h,d); K/V layout (b,t,kh,d).
// Output to (b,t,h,d).
// ---------------------------------------------------------------------------
#define FA_QS_STRIDE 132
#define FA_S_STRIDE  68
#define FA_SMEM_FLOATS (64*FA_QS_STRIDE /*Qs*/ + 64*FA_QS_STRIDE /*Ks*/ + \
                        64*128 /*Vs*/ + 64*FA_S_STRIDE /*S*/ + 3*64 /*m,l,a*/)
#define FA_SMEM_BYTES (FA_SMEM_FLOATS * 4)

__global__ __launch_bounds__(256)
void flash_kernel(const float* __restrict__ Q, const float* __restrict__ K,
                  const float* __restrict__ V, float* __restrict__ O) {
    extern __shared__ float sm[];
    float* Qs   = sm;                       // [64][132]
    float* Ks   = Qs + 64 * FA_QS_STRIDE;   // [64][132]
    float* Vs   = Ks + 64 * FA_QS_STRIDE;   // [64][128]
    float* Sb   = Vs + 64 * 128;            // [64][68]
    float* mrow = Sb + 64 * FA_S_STRIDE;    // [64]
    float* lrow = mrow + 64;                // [64]
    float* arow = lrow + 64;                // [64]

    const int qt = blockIdx.x;
    const int bh = blockIdx.y;
    const int b = bh >> 4;
    const int h = bh & 15;
    const int kh = h >> 1;                  // GQA: 2 q heads per kv head

    const int tid = threadIdx.x;
    const int tx = tid & 15;
    const int ty = tid >> 4;
    const float scale = 0.08838834764831845f;  // 1/sqrt(128)

    // Load Q tile (scaled)
    {
        const float* qbase = Q + ((size_t)(b * TT + qt * 64)) * (HH * HD) + h * HD;
        for (int i = tid; i < 64 * 32; i += 256) {
            int r = i >> 5, c4 = (i & 31) * 4;
            float4 v4 = *(const float4*)(qbase + (size_t)r * (HH * HD) + c4);
            v4.x *= scale; v4.y *= scale; v4.z *= scale; v4.w *= scale;
            *(float4*)&Qs[r * FA_QS_STRIDE + c4] = v4;
        }
    }
    if (tid < 64) { mrow[tid] = -INFINITY; lrow[tid] = 0.0f; }

    float o[4][8];
#pragma unroll
    for (int i = 0; i < 4; ++i)
#pragma unroll
        for (int c = 0; c < 8; ++c) o[i][c] = 0.0f;

    __syncthreads();

    for (int kt = 0; kt <= qt; ++kt) {
        // Load K, V tiles
        {
            const float* kb = K + ((size_t)(b * TT + kt * 64)) * (KK * HD) + kh * HD;
            const float* vb = V + ((size_t)(b * TT + kt * 64)) * (KK * HD) + kh * HD;
            for (int i = tid; i < 64 * 32; i += 256) {
                int r = i >> 5, c4 = (i & 31) * 4;
                *(float4*)&Ks[r * FA_QS_STRIDE + c4] = *(const float4*)(kb + (size_t)r * (KK * HD) + c4);
                *(float4*)&Vs[r * 128 + c4]          = *(const float4*)(vb + (size_t)r * (KK * HD) + c4);
            }
        }
        __syncthreads();

        // S = Q @ K^T. Thread owns rows ty*4+i, cols tx+16*j (strided -> conflict-free)
        float s[4][4];
#pragma unroll
        for (int i = 0; i < 4; ++i)
#pragma unroll
            for (int j = 0; j < 4; ++j) s[i][j] = 0.0f;

        for (int d4 = 0; d4 < 32; ++d4) {
            float4 qa[4], kb4[4];
#pragma unroll
            for (int i = 0; i < 4; ++i)
                qa[i] = *(const float4*)&Qs[(ty * 4 + i) * FA_QS_STRIDE + d4 * 4];
#pragma unroll
            for (int j = 0; j < 4; ++j)
                kb4[j] = *(const float4*)&Ks[(tx + 16 * j) * FA_QS_STRIDE + d4 * 4];
#pragma unroll
            for (int i = 0; i < 4; ++i)
#pragma unroll
                for (int j = 0; j < 4; ++j) {
                    s[i][j] += qa[i].x * kb4[j].x;
                    s[i][j] += qa[i].y * kb4[j].y;
                    s[i][j] += qa[i].z * kb4[j].z;
                    s[i][j] += qa[i].w * kb4[j].w;
                }
        }

        // Causal mask (only the diagonal tile needs it) + store S
        bool diag = (kt == qt);
#pragma unroll
        for (int i = 0; i < 4; ++i) {
            int r = ty * 4 + i;
#pragma unroll
            for (int j = 0; j < 4; ++j) {
                int c = tx + 16 * j;
                float sv = s[i][j];
                if (diag && c > r) sv = -1e30f;
                Sb[r * FA_S_STRIDE + c] = sv;
            }
        }
        __syncthreads();

        // Online softmax: one thread per row
        if (tid < 64) {
            float m_old = mrow[tid];
            float mx = m_old;
            float* row = &Sb[tid * FA_S_STRIDE];
#pragma unroll 8
            for (int c = 0; c < 64; ++c) mx = fmaxf(mx, row[c]);
            float a = __expf(m_old - mx);
            float sum = 0.0f;
#pragma unroll 8
            for (int c = 0; c < 64; ++c) {
                float p = __expf(row[c] - mx);
                row[c] = p;
                sum += p;
            }
            lrow[tid] = lrow[tid] * a + sum;
            mrow[tid] = mx;
            arow[tid] = a;
        }
        __syncthreads();

        // Rescale O and accumulate P @ V. Thread owns rows ty*4+i, cols tx+16*c
        float av[4];
#pragma unroll
        for (int i = 0; i < 4; ++i) av[i] = arow[ty * 4 + i];
#pragma unroll
        for (int i = 0; i < 4; ++i)
#pragma unroll
            for (int c = 0; c < 8; ++c) o[i][c] *= av[i];

        for (int kk4 = 0; kk4 < 16; ++kk4) {
            float4 p[4];
#pragma unroll
            for (int i = 0; i < 4; ++i)
                p[i] = *(const float4*)&Sb[(ty * 4 + i) * FA_S_STRIDE + kk4 * 4];
#pragma unroll
            for (int kk = 0; kk < 4; ++kk) {
#pragma unroll
                for (int c = 0; c < 8; ++c) {
                    float vv = Vs[(kk4 * 4 + kk) * 128 + tx + 16 * c];
                    float pv0 = (kk == 0) ? p[0].x : (kk == 1) ? p[0].y : (kk == 2) ? p[0].z : p[0].w;
                    float pv1 = (kk == 0) ? p[1].x : (kk == 1) ? p[1].y : (kk == 2) ? p[1].z : p[1].w;
                    float pv2 = (kk == 0) ? p[2].x : (kk == 1) ? p[2].y : (kk == 2) ? p[2].z : p[2].w;
                    float pv3 = (kk == 0) ? p[3].x : (kk == 1) ? p[3].y : (kk == 2) ? p[3].z : p[3].w;
                    o[0][c] += pv0 * vv;
                    o[1][c] += pv1 * vv;
                    o[2][c] += pv2 * vv;
                    o[3][c] += pv3 * vv;
                }
            }
        }
        __syncthreads();
    }

    // Epilogue: normalize and write (b,t,h,d)
    float linv[4];
#pragma unroll
    for (int i = 0; i < 4; ++i) linv[i] = 1.0f / lrow[ty * 4 + i];

#pragma unroll
    for (int i = 0; i < 4; ++i) {
        int t = qt * 64 + ty * 4 + i;
        float* obase = O + ((size_t)(b * TT + t)) * (HH * HD) + h * HD;
#pragma unroll
        for (int c = 0; c < 8; ++c)
            obase[tx + 16 * c] = o[i][c] * linv[i];
    }
}

// ---------------------------------------------------------------------------
extern "C" void kernel_launch(void* const* d_in, const int* in_sizes, int n_in,
                              void* d_out, int out_size) {
    const float* x    = (const float*)d_in[0];
    const float* Wq   = (const float*)d_in[1];
    const float* Wk   = (const float*)d_in[2];
    const float* Wv   = (const float*)d_in[3];
    const float* Wo   = (const float*)d_in[4];
    const float* qn   = (const float*)d_in[5];
    const float* kn   = (const float*)d_in[6];
    const float* sinp = (const float*)d_in[7];
    const float* cosp = (const float*)d_in[8];
    float* out = (float*)d_out;

    float *qr, *kr, *vr, *ob;
    cudaGetSymbolAddress((void**)&qr, g_q_raw);
    cudaGetSymbolAddress((void**)&kr, g_k_raw);
    cudaGetSymbolAddress((void**)&vr, g_v_raw);
    cudaGetSymbolAddress((void**)&ob, g_o);

    dim3 blk(256);

    // QKV projections
    sgemm128<<<dim3(16, 32), blk>>>(x, Wq, qr, MTOT, HH * HD, DD);
    sgemm128<<<dim3(8, 32),  blk>>>(x, Wk, kr, MTOT, KK * HD, DD);
    sgemm128<<<dim3(8, 32),  blk>>>(x, Wv, vr, MTOT, KK * HD, DD);

    // RMSNorm + RoPE (in place on q,k)
    normrope_kernel<<<12288, 256>>>(qr, kr, qn, kn, sinp, cosp);

    // Causal flash attention
    cudaFuncSetAttribute(flash_kernel, cudaFuncAttributeMaxDynamicSharedMemorySize,
                         FA_SMEM_BYTES);
    flash_kernel<<<dim3(TT / 64, BB * HH), blk, FA_SMEM_BYTES>>>(qr, kr, vr, ob);

    // Output projection
    sgemm128<<<dim3(16, 32), blk>>>(ob, Wo, out, MTOT, HH * HD, HH * HD);
}

// round 3
// speedup vs baseline: 1.6496x; 1.6496x over previous
#include <cuda_runtime.h>
#include <cuda_bf16.h>
#include <math.h>
#include <cstdint>

// Problem constants
#define BB 2
#define TT 2048
#define DD 2048
#define HH 16
#define KK 8
#define HD 128
#define MTOT (BB*TT)   // 4096

// ---------------------------------------------------------------------------
// Scratch (device globals; no allocation allowed)
// ---------------------------------------------------------------------------
__device__ __nv_bfloat16 g_xhi [(size_t)MTOT * DD];
__device__ __nv_bfloat16 g_xlo [(size_t)MTOT * DD];
__device__ __nv_bfloat16 g_wqt_hi[(size_t)(HH*HD) * DD];
__device__ __nv_bfloat16 g_wqt_lo[(size_t)(HH*HD) * DD];
__device__ __nv_bfloat16 g_wkt_hi[(size_t)(KK*HD) * DD];
__device__ __nv_bfloat16 g_wkt_lo[(size_t)(KK*HD) * DD];
__device__ __nv_bfloat16 g_wvt_hi[(size_t)(KK*HD) * DD];
__device__ __nv_bfloat16 g_wvt_lo[(size_t)(KK*HD) * DD];
__device__ __nv_bfloat16 g_wot_hi[(size_t)DD * (HH*HD)];
__device__ __nv_bfloat16 g_wot_lo[(size_t)DD * (HH*HD)];
__device__ float g_q_raw[(size_t)MTOT * (HH*HD)];
__device__ float g_k_raw[(size_t)MTOT * (KK*HD)];
__device__ float g_v_raw[(size_t)MTOT * (KK*HD)];
__device__ __nv_bfloat16 g_ohi [(size_t)MTOT * (HH*HD)];
__device__ __nv_bfloat16 g_olo [(size_t)MTOT * (HH*HD)];

// ---------------------------------------------------------------------------
// mma.sync helpers (sm_80+ PTX, valid on plain sm_103 target)
// ---------------------------------------------------------------------------
__device__ __forceinline__ uint32_t smem_to_u32(const void* p) {
    uint32_t a;
    asm("{ .reg .u64 t; cvta.to.shared.u64 t, %1; cvt.u32.u64 %0, t; }"
        : "=r"(a) : "l"(p));
    return a;
}

__device__ __forceinline__ void ldsm_x4(uint32_t& r0, uint32_t& r1,
                                        uint32_t& r2, uint32_t& r3, uint32_t addr) {
    asm volatile("ldmatrix.sync.aligned.m8n8.x4.shared.b16 {%0,%1,%2,%3}, [%4];"
                 : "=r"(r0), "=r"(r1), "=r"(r2), "=r"(r3) : "r"(addr));
}

__device__ __forceinline__ void mma_bf16(float* d, const uint32_t* a,
                                         uint32_t b0, uint32_t b1) {
    asm volatile(
        "mma.sync.aligned.m16n8k16.row.col.f32.bf16.bf16.f32 "
        "{%0,%1,%2,%3}, {%4,%5,%6,%7}, {%8,%9}, {%0,%1,%2,%3};"
        : "+f"(d[0]), "+f"(d[1]), "+f"(d[2]), "+f"(d[3])
        : "r"(a[0]), "r"(a[1]), "r"(a[2]), "r"(a[3]), "r"(b0), "r"(b1));
}

// ---------------------------------------------------------------------------
// Conversion: fp32 -> (bf16 hi, bf16 lo), same layout.
// ---------------------------------------------------------------------------
__global__ __launch_bounds__(256)
void convert_split_kernel(const float* __restrict__ X,
                          __nv_bfloat16* __restrict__ Hi,
                          __nv_bfloat16* __restrict__ Lo, int n4) {
    int i = blockIdx.x * 256 + threadIdx.x;
    if (i >= n4) return;
    float4 v = ((const float4*)X)[i];
    __nv_bfloat16 h0 = __float2bfloat16(v.x), h1 = __float2bfloat16(v.y);
    __nv_bfloat16 h2 = __float2bfloat16(v.z), h3 = __float2bfloat16(v.w);
    __nv_bfloat16 l0 = __float2bfloat16(v.x - __bfloat162float(h0));
    __nv_bfloat16 l1 = __float2bfloat16(v.y - __bfloat162float(h1));
    __nv_bfloat16 l2 = __float2bfloat16(v.z - __bfloat162float(h2));
    __nv_bfloat16 l3 = __float2bfloat16(v.w - __bfloat162float(h3));
    __nv_bfloat162* hp = (__nv_bfloat162*)(Hi + 4 * (size_t)i);
    __nv_bfloat162* lp = (__nv_bfloat162*)(Lo + 4 * (size_t)i);
    hp[0] = __nv_bfloat162(h0, h1); hp[1] = __nv_bfloat162(h2, h3);
    lp[0] = __nv_bfloat162(l0, l1); lp[1] = __nv_bfloat162(l2, l3);
}

// ---------------------------------------------------------------------------
// Transpose + split: W[Kd, N] fp32 -> T_hi/T_lo [N, Kd] bf16
// ---------------------------------------------------------------------------
__global__ __launch_bounds__(256)
void transpose_split_kernel(const float* __restrict__ W,
                            __nv_bfloat16* __restrict__ Thi,
                            __nv_bfloat16* __restrict__ Tlo, int Kd, int N) {
    __shared__ float tile[32][33];
    int n0 = blockIdx.x * 32, k0 = blockIdx.y * 32;
    int tx = threadIdx.x & 31, ty = threadIdx.x >> 5;  // 32 x 8
#pragma unroll
    for (int r = ty; r < 32; r += 8)
        tile[r][tx] = W[(size_t)(k0 + r) * N + n0 + tx];
    __syncthreads();
#pragma unroll
    for (int r = ty; r < 32; r += 8) {
        float v = tile[tx][r];   // = W[k0+tx][n0+r]
        __nv_bfloat16 h = __float2bfloat16(v);
        size_t o = (size_t)(n0 + r) * Kd + k0 + tx;
        Thi[o] = h;
        Tlo[o] = __float2bfloat16(v - __bfloat162float(h));
    }
}

// ---------------------------------------------------------------------------
// bf16-split tensor-core GEMM via mma.sync:
//   C[M,N] = (Ahi+Alo)[M,K] @ (Bhi+Blo)[N,K]^T   (fp32 out)
// 128x128 CTA tile, 8 warps (4 row x 2 col), warp tile 32x64, K-chunk 32.
// SMEM rows padded to 40 bf16 (80B) -> ldmatrix conflict-free.
// ---------------------------------------------------------------------------
#define GPAD 40
#define GTILE_BYTES (128 * GPAD * 2)      // 10240 per array
#define GSTAGE_BYTES (4 * GTILE_BYTES)    // 40960 per stage (Ahi,Alo,Bhi,Blo)
#define GSMEM_DYN (2 * GSTAGE_BYTES)      // 81920

__global__ __launch_bounds__(256, 1)
void gemm_mma(const __nv_bfloat16* __restrict__ Ahi,
              const __nv_bfloat16* __restrict__ Alo,
              const __nv_bfloat16* __restrict__ Bhi,
              const __nv_bfloat16* __restrict__ Blo,
              float* __restrict__ C, int N, int Kd) {
    extern __shared__ char smg[];
    const uint32_t sbase0 = smem_to_u32(smg);

    const int tid = threadIdx.x;
    const int lane = tid & 31;
    const int wid = tid >> 5;
    const int wr = wid & 3;          // warp row block (32 rows)
    const int wc = wid >> 2;         // warp col block (64 cols)
    const int row0 = blockIdx.y * 128;
    const int col0 = blockIdx.x * 128;

    float d[2][8][4];
#pragma unroll
    for (int m = 0; m < 2; ++m)
#pragma unroll
        for (int n = 0; n < 8; ++n)
#pragma unroll
            for (int j = 0; j < 4; ++j) d[m][n][j] = 0.0f;

    // per-thread global-load plan: for each of 4 arrays, 2 segments
    const __nv_bfloat16* gb[4] = {Ahi, Alo, Bhi, Blo};
    int grow[8], gseg[8];
#pragma unroll
    for (int a = 0; a < 4; ++a) {
        int r0 = (a < 2) ? row0 : col0;
        int s0 = tid, s1 = tid + 256;
        grow[2*a]   = r0 + (s0 >> 2); gseg[2*a]   = s0 & 3;
        grow[2*a+1] = r0 + (s1 >> 2); gseg[2*a+1] = s1 & 3;
    }

    uint4 pf[8];
    auto ldg_chunk = [&](int k0) {
#pragma unroll
        for (int a = 0; a < 4; ++a) {
#pragma unroll
            for (int j = 0; j < 2; ++j) {
                int e = 2 * a + j;
                pf[e] = *(const uint4*)(gb[a] + (size_t)grow[e] * Kd + k0 + gseg[e] * 8);
            }
        }
    };
    auto sts_chunk = [&](int buf) {
        char* st = smg + buf * GSTAGE_BYTES;
#pragma unroll
        for (int a = 0; a < 4; ++a) {
#pragma unroll
            for (int j = 0; j < 2; ++j) {
                int e = 2 * a + j;
                int s = tid + j * 256;
                *(uint4*)(st + a * GTILE_BYTES + (s >> 2) * (GPAD*2) + (s & 3) * 16) = pf[e];
            }
        }
    };

    const int NC = Kd / 32;

    ldg_chunk(0);
    sts_chunk(0);
    __syncthreads();

    for (int c = 0; c < NC; ++c) {
        const int cur = c & 1;
        const uint32_t sb = sbase0 + cur * GSTAGE_BYTES;

        if (c + 1 < NC) ldg_chunk((c + 1) * 32);   // prefetch into regs

#pragma unroll
        for (int ks = 0; ks < 2; ++ks) {
            // ldmatrix address pattern: rows via (lane&15), col16B via (lane>>4)
            const uint32_t coff = ks * 32 + (lane >> 4) * 16;
            uint32_t ah[2][4], al[2][4];
#pragma unroll
            for (int mb = 0; mb < 2; ++mb) {
                uint32_t addr = sb + (wr * 32 + mb * 16 + (lane & 15)) * (GPAD*2) + coff;
                ldsm_x4(ah[mb][0], ah[mb][1], ah[mb][2], ah[mb][3], addr);
                ldsm_x4(al[mb][0], al[mb][1], al[mb][2], al[mb][3], addr + GTILE_BYTES);
            }
            uint32_t bh[4][4], bl[4][4];
#pragma unroll
            for (int nb = 0; nb < 4; ++nb) {
                uint32_t addr = sb + 2 * GTILE_BYTES +
                                (wc * 64 + nb * 16 + (lane & 15)) * (GPAD*2) + coff;
                ldsm_x4(bh[nb][0], bh[nb][1], bh[nb][2], bh[nb][3], addr);
                ldsm_x4(bl[nb][0], bl[nb][1], bl[nb][2], bl[nb][3], addr + GTILE_BYTES);
            }
            // x4 register meaning for B loads: r0 = (n0-7,k0-7) -> b0 of ntile0,
            // r1 = (n8-15,k0-7) -> b0 of ntile1, r2/r3 = k8-15 halves (b1).
#pragma unroll
            for (int mb = 0; mb < 2; ++mb) {
#pragma unroll
                for (int nb = 0; nb < 4; ++nb) {
                    float* d0 = d[mb][2*nb];
                    float* d1 = d[mb][2*nb+1];
                    // hi*hi
                    mma_bf16(d0, ah[mb], bh[nb][0], bh[nb][2]);
                    mma_bf16(d1, ah[mb], bh[nb][1], bh[nb][3]);
                    // hi*lo
                    mma_bf16(d0, ah[mb], bl[nb][0], bl[nb][2]);
                    mma_bf16(d1, ah[mb], bl[nb][1], bl[nb][3]);
                    // lo*hi
                    mma_bf16(d0, al[mb], bh[nb][0], bh[nb][2]);
                    mma_bf16(d1, al[mb], bh[nb][1], bh[nb][3]);
                }
            }
        }

        if (c + 1 < NC) sts_chunk(cur ^ 1);
        __syncthreads();
    }

    // Epilogue: fragment layout m16n8 -> rows t/4 (+8), cols 2*(t%4)
    const int frow = lane >> 2;
    const int fcol = 2 * (lane & 3);
#pragma unroll
    for (int mb = 0; mb < 2; ++mb) {
#pragma unroll
        for (int nt = 0; nt < 8; ++nt) {
            int r = row0 + wr * 32 + mb * 16 + frow;
            int cc = col0 + wc * 64 + nt * 8 + fcol;
            *(float2*)&C[(size_t)r * N + cc]       = make_float2(d[mb][nt][0], d[mb][nt][1]);
            *(float2*)&C[(size_t)(r + 8) * N + cc] = make_float2(d[mb][nt][2], d[mb][nt][3]);
        }
    }
}

// ---------------------------------------------------------------------------
// Fused RMSNorm + RoPE, in-place. One warp per (b,t,head) 128-dim vector.
// ---------------------------------------------------------------------------
__global__ __launch_bounds__(256)
void normrope_kernel(float* __restrict__ q, float* __restrict__ k,
                     const float* __restrict__ qn, const float* __restrict__ kn,
                     const float* __restrict__ sinp, const float* __restrict__ cosp) {
    int warp = (blockIdx.x * blockDim.x + threadIdx.x) >> 5;
    int lane = threadIdx.x & 31;
    const int NQ = MTOT * HH;
    const int NTOT = NQ + MTOT * KK;
    if (warp >= NTOT) return;

    float* ptr;
    const float* w;
    int t;
    if (warp < NQ) {
        int bt = warp >> 4;
        int h = warp & 15;
        ptr = q + (size_t)bt * (HH * HD) + h * HD;
        w = qn;
        t = bt & (TT - 1);
    } else {
        int v2 = warp - NQ;
        int bt = v2 >> 3;
        int kh = v2 & 7;
        ptr = k + (size_t)bt * (KK * HD) + kh * HD;
        w = kn;
        t = bt & (TT - 1);
    }

    float2 a  = *(const float2*)(ptr + 2 * lane);
    float2 b2 = *(const float2*)(ptr + 64 + 2 * lane);

    float ss = a.x * a.x + a.y * a.y + b2.x * b2.x + b2.y * b2.y;
#pragma unroll
    for (int off = 16; off; off >>= 1) ss += __shfl_xor_sync(0xFFFFFFFFu, ss, off);
    float rinv = rsqrtf(ss * (1.0f / 128.0f) + 1e-6f);

    float w0 = w[2 * lane], w1 = w[2 * lane + 1];
    float w2 = w[64 + 2 * lane], w3 = w[65 + 2 * lane];
    float n0 = a.x * rinv * w0, n1 = a.y * rinv * w1;
    float n2 = b2.x * rinv * w2, n3 = b2.y * rinv * w3;

    float s0 = sinp[t * 64 + lane],      c0 = cosp[t * 64 + lane];
    float s1 = sinp[t * 64 + lane + 32], c1 = cosp[t * 64 + lane + 32];
    float o0 = n0 * c0 - n1 * s0;
    float o1 = n2 * c1 - n3 * s1;
    float o2 = n0 * s0 + n1 * c0;
    float o3 = n2 * s1 + n3 * c1;

    __syncwarp();
    ptr[lane]      = o0;
    ptr[lane + 32] = o1;
    ptr[lane + 64] = o2;
    ptr[lane + 96] = o3;
}

// ---------------------------------------------------------------------------
// Flash attention (fp32, causal). Epilogue writes bf16 hi/lo split for Wo GEMM.
// ---------------------------------------------------------------------------
#define FA_QS_STRIDE 132
#define FA_S_STRIDE  68
#define FA_SMEM_FLOATS (64*FA_QS_STRIDE + 64*FA_QS_STRIDE + 64*128 + 64*FA_S_STRIDE + 3*64)
#define FA_SMEM_BYTES (FA_SMEM_FLOATS * 4)

__global__ __launch_bounds__(256)
void flash_kernel(const float* __restrict__ Q, const float* __restrict__ K,
                  const float* __restrict__ V,
                  __nv_bfloat16* __restrict__ Ohi, __nv_bfloat16* __restrict__ Olo) {
    extern __shared__ float sm[];
    float* Qs   = sm;
    float* Ks   = Qs + 64 * FA_QS_STRIDE;
    float* Vs   = Ks + 64 * FA_QS_STRIDE;
    float* Sb   = Vs + 64 * 128;
    float* mrow = Sb + 64 * FA_S_STRIDE;
    float* lrow = mrow + 64;
    float* arow = lrow + 64;

    const int qt = blockIdx.x;
    const int bh = blockIdx.y;
    const int b = bh >> 4;
    const int h = bh & 15;
    const int kh = h >> 1;

    const int tid = threadIdx.x;
    const int tx = tid & 15;
    const int ty = tid >> 4;
    const float scale = 0.08838834764831845f;

    {
        const float* qbase = Q + ((size_t)(b * TT + qt * 64)) * (HH * HD) + h * HD;
        for (int i = tid; i < 64 * 32; i += 256) {
            int r = i >> 5, c4 = (i & 31) * 4;
            float4 v4 = *(const float4*)(qbase + (size_t)r * (HH * HD) + c4);
            v4.x *= scale; v4.y *= scale; v4.z *= scale; v4.w *= scale;
            *(float4*)&Qs[r * FA_QS_STRIDE + c4] = v4;
        }
    }
    if (tid < 64) { mrow[tid] = -INFINITY; lrow[tid] = 0.0f; }

    float o[4][8];
#pragma unroll
    for (int i = 0; i < 4; ++i)
#pragma unroll
        for (int c = 0; c < 8; ++c) o[i][c] = 0.0f;

    __syncthreads();

    for (int kt = 0; kt <= qt; ++kt) {
        {
            const float* kb = K + ((size_t)(b * TT + kt * 64)) * (KK * HD) + kh * HD;
            const float* vb = V + ((size_t)(b * TT + kt * 64)) * (KK * HD) + kh * HD;
            for (int i = tid; i < 64 * 32; i += 256) {
                int r = i >> 5, c4 = (i & 31) * 4;
                *(float4*)&Ks[r * FA_QS_STRIDE + c4] = *(const float4*)(kb + (size_t)r * (KK * HD) + c4);
                *(float4*)&Vs[r * 128 + c4]          = *(const float4*)(vb + (size_t)r * (KK * HD) + c4);
            }
        }
        __syncthreads();

        float s[4][4];
#pragma unroll
        for (int i = 0; i < 4; ++i)
#pragma unroll
            for (int j = 0; j < 4; ++j) s[i][j] = 0.0f;

        for (int d4 = 0; d4 < 32; ++d4) {
            float4 qa[4], kb4[4];
#pragma unroll
            for (int i = 0; i < 4; ++i)
                qa[i] = *(const float4*)&Qs[(ty * 4 + i) * FA_QS_STRIDE + d4 * 4];
#pragma unroll
            for (int j = 0; j < 4; ++j)
                kb4[j] = *(const float4*)&Ks[(tx + 16 * j) * FA_QS_STRIDE + d4 * 4];
#pragma unroll
            for (int i = 0; i < 4; ++i)
#pragma unroll
                for (int j = 0; j < 4; ++j) {
                    s[i][j] += qa[i].x * kb4[j].x;
                    s[i][j] += qa[i].y * kb4[j].y;
                    s[i][j] += qa[i].z * kb4[j].z;
                    s[i][j] += qa[i].w * kb4[j].w;
                }
        }

        bool diag = (kt == qt);
#pragma unroll
        for (int i = 0; i < 4; ++i) {
            int r = ty * 4 + i;
#pragma unroll
            for (int j = 0; j < 4; ++j) {
                int c = tx + 16 * j;
                float sv = s[i][j];
                if (diag && c > r) sv = -1e30f;
                Sb[r * FA_S_STRIDE + c] = sv;
            }
        }
        __syncthreads();

        if (tid < 64) {
            float m_old = mrow[tid];
            float mx = m_old;
            float* row = &Sb[tid * FA_S_STRIDE];
#pragma unroll 8
            for (int c = 0; c < 64; ++c) mx = fmaxf(mx, row[c]);
            float a = __expf(m_old - mx);
            float sum = 0.0f;
#pragma unroll 8
            for (int c = 0; c < 64; ++c) {
                float p = __expf(row[c] - mx);
                row[c] = p;
                sum += p;
            }
            lrow[tid] = lrow[tid] * a + sum;
            mrow[tid] = mx;
            arow[tid] = a;
        }
        __syncthreads();

        float av[4];
#pragma unroll
        for (int i = 0; i < 4; ++i) av[i] = arow[ty * 4 + i];
#pragma unroll
        for (int i = 0; i < 4; ++i)
#pragma unroll
            for (int c = 0; c < 8; ++c) o[i][c] *= av[i];

        for (int kk4 = 0; kk4 < 16; ++kk4) {
            float4 p[4];
#pragma unroll
            for (int i = 0; i < 4; ++i)
                p[i] = *(const float4*)&Sb[(ty * 4 + i) * FA_S_STRIDE + kk4 * 4];
#pragma unroll
            for (int kk = 0; kk < 4; ++kk) {
#pragma unroll
                for (int c = 0; c < 8; ++c) {
                    float vv = Vs[(kk4 * 4 + kk) * 128 + tx + 16 * c];
                    float pv0 = (kk == 0) ? p[0].x : (kk == 1) ? p[0].y : (kk == 2) ? p[0].z : p[0].w;
                    float pv1 = (kk == 0) ? p[1].x : (kk == 1) ? p[1].y : (kk == 2) ? p[1].z : p[1].w;
                    float pv2 = (kk == 0) ? p[2].x : (kk == 1) ? p[2].y : (kk == 2) ? p[2].z : p[2].w;
                    float pv3 = (kk == 0) ? p[3].x : (kk == 1) ? p[3].y : (kk == 2) ? p[3].z : p[3].w;
                    o[0][c] += pv0 * vv;
                    o[1][c] += pv1 * vv;
                    o[2][c] += pv2 * vv;
                    o[3][c] += pv3 * vv;
                }
            }
        }
        __syncthreads();
    }

    float linv[4];
#pragma unroll
    for (int i = 0; i < 4; ++i) linv[i] = 1.0f / lrow[ty * 4 + i];

#pragma unroll
    for (int i = 0; i < 4; ++i) {
        int t = qt * 64 + ty * 4 + i;
        size_t base = ((size_t)(b * TT + t)) * (HH * HD) + h * HD;
#pragma unroll
        for (int c = 0; c < 8; ++c) {
            float val = o[i][c] * linv[i];
            __nv_bfloat16 hi = __float2bfloat16(val);
            Ohi[base + tx + 16 * c] = hi;
            Olo[base + tx + 16 * c] = __float2bfloat16(val - __bfloat162float(hi));
        }
    }
}

// ---------------------------------------------------------------------------
extern "C" void kernel_launch(void* const* d_in, const int* in_sizes, int n_in,
                              void* d_out, int out_size) {
    const float* x    = (const float*)d_in[0];
    const float* Wq   = (const float*)d_in[1];
    const float* Wk   = (const float*)d_in[2];
    const float* Wv   = (const float*)d_in[3];
    const float* Wo   = (const float*)d_in[4];
    const float* qn   = (const float*)d_in[5];
    const float* kn   = (const float*)d_in[6];
    const float* sinp = (const float*)d_in[7];
    const float* cosp = (const float*)d_in[8];
    float* out = (float*)d_out;

    __nv_bfloat16 *xhi, *xlo, *wqh, *wql, *wkh, *wkl, *wvh, *wvl, *woh, *wol, *ohi, *olo;
    float *qr, *kr, *vr;
    cudaGetSymbolAddress((void**)&xhi, g_xhi);
    cudaGetSymbolAddress((void**)&xlo, g_xlo);
    cudaGetSymbolAddress((void**)&wqh, g_wqt_hi);
    cudaGetSymbolAddress((void**)&wql, g_wqt_lo);
    cudaGetSymbolAddress((void**)&wkh, g_wkt_hi);
    cudaGetSymbolAddress((void**)&wkl, g_wkt_lo);
    cudaGetSymbolAddress((void**)&wvh, g_wvt_hi);
    cudaGetSymbolAddress((void**)&wvl, g_wvt_lo);
    cudaGetSymbolAddress((void**)&woh, g_wot_hi);
    cudaGetSymbolAddress((void**)&wol, g_wot_lo);
    cudaGetSymbolAddress((void**)&qr, g_q_raw);
    cudaGetSymbolAddress((void**)&kr, g_k_raw);
    cudaGetSymbolAddress((void**)&vr, g_v_raw);
    cudaGetSymbolAddress((void**)&ohi, g_ohi);
    cudaGetSymbolAddress((void**)&olo, g_olo);

    // 1. split-convert x
    convert_split_kernel<<<(MTOT * DD / 4 + 255) / 256, 256>>>(x, xhi, xlo, MTOT * DD / 4);

    // 2. transpose + split weights  (W[K,N] -> T[N,K])
    transpose_split_kernel<<<dim3((HH*HD)/32, DD/32), 256>>>(Wq, wqh, wql, DD, HH*HD);
    transpose_split_kernel<<<dim3((KK*HD)/32, DD/32), 256>>>(Wk, wkh, wkl, DD, KK*HD);
    transpose_split_kernel<<<dim3((KK*HD)/32, DD/32), 256>>>(Wv, wvh, wvl, DD, KK*HD);
    transpose_split_kernel<<<dim3((HH*HD)/32, (HH*HD)/32), 256>>>(Wo, woh, wol, HH*HD, HH*HD);

    // 3. QKV projections on tensor cores (mma.sync)
    cudaFuncSetAttribute(gemm_mma, cudaFuncAttributeMaxDynamicSharedMemorySize, GSMEM_DYN);
    gemm_mma<<<dim3((HH*HD)/128, MTOT/128), 256, GSMEM_DYN>>>(xhi, xlo, wqh, wql, qr, HH*HD, DD);
    gemm_mma<<<dim3((KK*HD)/128, MTOT/128), 256, GSMEM_DYN>>>(xhi, xlo, wkh, wkl, kr, KK*HD, DD);
    gemm_mma<<<dim3((KK*HD)/128, MTOT/128), 256, GSMEM_DYN>>>(xhi, xlo, wvh, wvl, vr, KK*HD, DD);

    // 4. RMSNorm + RoPE
    normrope_kernel<<<12288, 256>>>(qr, kr, qn, kn, sinp, cosp);

    // 5. causal flash attention (fp32), writes bf16 hi/lo output
    cudaFuncSetAttribute(flash_kernel, cudaFuncAttributeMaxDynamicSharedMemorySize, FA_SMEM_BYTES);
    flash_kernel<<<dim3(TT / 64, BB * HH), 256, FA_SMEM_BYTES>>>(qr, kr, vr, ohi, olo);

    // 6. output projection on tensor cores
    gemm_mma<<<dim3((HH*HD)/128, MTOT/128), 256, GSMEM_DYN>>>(ohi, olo, woh, wol, out, HH*HD, HH*HD);
}

// round 4
// speedup vs baseline: 2.2611x; 1.3707x over previous
#include <cuda_runtime.h>
#include <cuda_bf16.h>
#include <math.h>
#include <cstdint>

// Problem constants
#define BB 2
#define TT 2048
#define DD 2048
#define HH 16
#define KK 8
#define HD 128
#define MTOT (BB*TT)   // 4096

// ---------------------------------------------------------------------------
// Scratch (device globals; no allocation allowed)
// ---------------------------------------------------------------------------
__device__ __nv_bfloat16 g_xhi [(size_t)MTOT * DD];
__device__ __nv_bfloat16 g_xlo [(size_t)MTOT * DD];
__device__ __nv_bfloat16 g_wqt_hi[(size_t)(HH*HD) * DD];
__device__ __nv_bfloat16 g_wqt_lo[(size_t)(HH*HD) * DD];
__device__ __nv_bfloat16 g_wkt_hi[(size_t)(KK*HD) * DD];
__device__ __nv_bfloat16 g_wkt_lo[(size_t)(KK*HD) * DD];
__device__ __nv_bfloat16 g_wvt_hi[(size_t)(KK*HD) * DD];
__device__ __nv_bfloat16 g_wvt_lo[(size_t)(KK*HD) * DD];
__device__ __nv_bfloat16 g_wot_hi[(size_t)DD * (HH*HD)];
__device__ __nv_bfloat16 g_wot_lo[(size_t)DD * (HH*HD)];
__device__ float g_q_raw[(size_t)MTOT * (HH*HD)];
__device__ float g_k_raw[(size_t)MTOT * (KK*HD)];
__device__ float g_v_raw[(size_t)MTOT * (KK*HD)];
__device__ __nv_bfloat16 g_qhi [(size_t)MTOT * (HH*HD)];
__device__ __nv_bfloat16 g_qlo [(size_t)MTOT * (HH*HD)];
__device__ __nv_bfloat16 g_khi [(size_t)MTOT * (KK*HD)];
__device__ __nv_bfloat16 g_klo [(size_t)MTOT * (KK*HD)];
__device__ __nv_bfloat16 g_vhi [(size_t)MTOT * (KK*HD)];
__device__ __nv_bfloat16 g_vlo [(size_t)MTOT * (KK*HD)];
__device__ __nv_bfloat16 g_ohi [(size_t)MTOT * (HH*HD)];
__device__ __nv_bfloat16 g_olo [(size_t)MTOT * (HH*HD)];

// ---------------------------------------------------------------------------
// mma.sync helpers
// ---------------------------------------------------------------------------
__device__ __forceinline__ uint32_t smem_to_u32(const void* p) {
    uint32_t a;
    asm("{ .reg .u64 t; cvta.to.shared.u64 t, %1; cvt.u32.u64 %0, t; }"
        : "=r"(a) : "l"(p));
    return a;
}

__device__ __forceinline__ void ldsm_x4(uint32_t& r0, uint32_t& r1,
                                        uint32_t& r2, uint32_t& r3, uint32_t addr) {
    asm volatile("ldmatrix.sync.aligned.m8n8.x4.shared.b16 {%0,%1,%2,%3}, [%4];"
                 : "=r"(r0), "=r"(r1), "=r"(r2), "=r"(r3) : "r"(addr));
}

__device__ __forceinline__ void ldsm_x4_trans(uint32_t& r0, uint32_t& r1,
                                              uint32_t& r2, uint32_t& r3, uint32_t addr) {
    asm volatile("ldmatrix.sync.aligned.m8n8.x4.trans.shared.b16 {%0,%1,%2,%3}, [%4];"
                 : "=r"(r0), "=r"(r1), "=r"(r2), "=r"(r3) : "r"(addr));
}

__device__ __forceinline__ void mma_bf16(float* d, const uint32_t* a,
                                         uint32_t b0, uint32_t b1) {
    asm volatile(
        "mma.sync.aligned.m16n8k16.row.col.f32.bf16.bf16.f32 "
        "{%0,%1,%2,%3}, {%4,%5,%6,%7}, {%8,%9}, {%0,%1,%2,%3};"
        : "+f"(d[0]), "+f"(d[1]), "+f"(d[2]), "+f"(d[3])
        : "r"(a[0]), "r"(a[1]), "r"(a[2]), "r"(a[3]), "r"(b0), "r"(b1));
}

// ---------------------------------------------------------------------------
// Conversion: fp32 -> (bf16 hi, bf16 lo), same layout.
// ---------------------------------------------------------------------------
__global__ __launch_bounds__(256)
void convert_split_kernel(const float* __restrict__ X,
                          __nv_bfloat16* __restrict__ Hi,
                          __nv_bfloat16* __restrict__ Lo, int n4) {
    int i = blockIdx.x * 256 + threadIdx.x;
    if (i >= n4) return;
    float4 v = ((const float4*)X)[i];
    __nv_bfloat16 h0 = __float2bfloat16(v.x), h1 = __float2bfloat16(v.y);
    __nv_bfloat16 h2 = __float2bfloat16(v.z), h3 = __float2bfloat16(v.w);
    __nv_bfloat16 l0 = __float2bfloat16(v.x - __bfloat162float(h0));
    __nv_bfloat16 l1 = __float2bfloat16(v.y - __bfloat162float(h1));
    __nv_bfloat16 l2 = __float2bfloat16(v.z - __bfloat162float(h2));
    __nv_bfloat16 l3 = __float2bfloat16(v.w - __bfloat162float(h3));
    __nv_bfloat162* hp = (__nv_bfloat162*)(Hi + 4 * (size_t)i);
    __nv_bfloat162* lp = (__nv_bfloat162*)(Lo + 4 * (size_t)i);
    hp[0] = __nv_bfloat162(h0, h1); hp[1] = __nv_bfloat162(h2, h3);
    lp[0] = __nv_bfloat162(l0, l1); lp[1] = __nv_bfloat162(l2, l3);
}

// ---------------------------------------------------------------------------
// Transpose + split: W[Kd, N] fp32 -> T_hi/T_lo [N, Kd] bf16
// ---------------------------------------------------------------------------
__global__ __launch_bounds__(256)
void transpose_split_kernel(const float* __restrict__ W,
                            __nv_bfloat16* __restrict__ Thi,
                            __nv_bfloat16* __restrict__ Tlo, int Kd, int N) {
    __shared__ float tile[32][33];
    int n0 = blockIdx.x * 32, k0 = blockIdx.y * 32;
    int tx = threadIdx.x & 31, ty = threadIdx.x >> 5;  // 32 x 8
#pragma unroll
    for (int r = ty; r < 32; r += 8)
        tile[r][tx] = W[(size_t)(k0 + r) * N + n0 + tx];
    __syncthreads();
#pragma unroll
    for (int r = ty; r < 32; r += 8) {
        float v = tile[tx][r];
        __nv_bfloat16 h = __float2bfloat16(v);
        size_t o = (size_t)(n0 + r) * Kd + k0 + tx;
        Thi[o] = h;
        Tlo[o] = __float2bfloat16(v - __bfloat162float(h));
    }
}

// ---------------------------------------------------------------------------
// bf16-split tensor-core GEMM via mma.sync (unchanged from R3, validated)
// ---------------------------------------------------------------------------
#define GPAD 40
#define GTILE_BYTES (128 * GPAD * 2)
#define GSTAGE_BYTES (4 * GTILE_BYTES)
#define GSMEM_DYN (2 * GSTAGE_BYTES)

__global__ __launch_bounds__(256, 1)
void gemm_mma(const __nv_bfloat16* __restrict__ Ahi,
              const __nv_bfloat16* __restrict__ Alo,
              const __nv_bfloat16* __restrict__ Bhi,
              const __nv_bfloat16* __restrict__ Blo,
              float* __restrict__ C, int N, int Kd) {
    extern __shared__ char smg[];
    const uint32_t sbase0 = smem_to_u32(smg);

    const int tid = threadIdx.x;
    const int lane = tid & 31;
    const int wid = tid >> 5;
    const int wr = wid & 3;
    const int wc = wid >> 2;
    const int row0 = blockIdx.y * 128;
    const int col0 = blockIdx.x * 128;

    float d[2][8][4];
#pragma unroll
    for (int m = 0; m < 2; ++m)
#pragma unroll
        for (int n = 0; n < 8; ++n)
#pragma unroll
            for (int j = 0; j < 4; ++j) d[m][n][j] = 0.0f;

    const __nv_bfloat16* gb[4] = {Ahi, Alo, Bhi, Blo};
    int grow[8], gseg[8];
#pragma unroll
    for (int a = 0; a < 4; ++a) {
        int r0 = (a < 2) ? row0 : col0;
        int s0 = tid, s1 = tid + 256;
        grow[2*a]   = r0 + (s0 >> 2); gseg[2*a]   = s0 & 3;
        grow[2*a+1] = r0 + (s1 >> 2); gseg[2*a+1] = s1 & 3;
    }

    uint4 pf[8];
    auto ldg_chunk = [&](int k0) {
#pragma unroll
        for (int a = 0; a < 4; ++a) {
#pragma unroll
            for (int j = 0; j < 2; ++j) {
                int e = 2 * a + j;
                pf[e] = *(const uint4*)(gb[a] + (size_t)grow[e] * Kd + k0 + gseg[e] * 8);
            }
        }
    };
    auto sts_chunk = [&](int buf) {
        char* st = smg + buf * GSTAGE_BYTES;
#pragma unroll
        for (int a = 0; a < 4; ++a) {
#pragma unroll
            for (int j = 0; j < 2; ++j) {
                int e = 2 * a + j;
                int s = tid + j * 256;
                *(uint4*)(st + a * GTILE_BYTES + (s >> 2) * (GPAD*2) + (s & 3) * 16) = pf[e];
            }
        }
    };

    const int NC = Kd / 32;

    ldg_chunk(0);
    sts_chunk(0);
    __syncthreads();

    for (int c = 0; c < NC; ++c) {
        const int cur = c & 1;
        const uint32_t sb = sbase0 + cur * GSTAGE_BYTES;

        if (c + 1 < NC) ldg_chunk((c + 1) * 32);

#pragma unroll
        for (int ks = 0; ks < 2; ++ks) {
            const uint32_t coff = ks * 32 + (lane >> 4) * 16;
            uint32_t ah[2][4], al[2][4];
#pragma unroll
            for (int mb = 0; mb < 2; ++mb) {
                uint32_t addr = sb + (wr * 32 + mb * 16 + (lane & 15)) * (GPAD*2) + coff;
                ldsm_x4(ah[mb][0], ah[mb][1], ah[mb][2], ah[mb][3], addr);
                ldsm_x4(al[mb][0], al[mb][1], al[mb][2], al[mb][3], addr + GTILE_BYTES);
            }
            uint32_t bh[4][4], bl[4][4];
#pragma unroll
            for (int nb = 0; nb < 4; ++nb) {
                uint32_t addr = sb + 2 * GTILE_BYTES +
                                (wc * 64 + nb * 16 + (lane & 15)) * (GPAD*2) + coff;
                ldsm_x4(bh[nb][0], bh[nb][1], bh[nb][2], bh[nb][3], addr);
                ldsm_x4(bl[nb][0], bl[nb][1], bl[nb][2], bl[nb][3], addr + GTILE_BYTES);
            }
#pragma unroll
            for (int mb = 0; mb < 2; ++mb) {
#pragma unroll
                for (int nb = 0; nb < 4; ++nb) {
                    float* d0 = d[mb][2*nb];
                    float* d1 = d[mb][2*nb+1];
                    mma_bf16(d0, ah[mb], bh[nb][0], bh[nb][2]);
                    mma_bf16(d1, ah[mb], bh[nb][1], bh[nb][3]);
                    mma_bf16(d0, ah[mb], bl[nb][0], bl[nb][2]);
                    mma_bf16(d1, ah[mb], bl[nb][1], bl[nb][3]);
                    mma_bf16(d0, al[mb], bh[nb][0], bh[nb][2]);
                    mma_bf16(d1, al[mb], bh[nb][1], bh[nb][3]);
                }
            }
        }

        if (c + 1 < NC) sts_chunk(cur ^ 1);
        __syncthreads();
    }

    const int frow = lane >> 2;
    const int fcol = 2 * (lane & 3);
#pragma unroll
    for (int mb = 0; mb < 2; ++mb) {
#pragma unroll
        for (int nt = 0; nt < 8; ++nt) {
            int r = row0 + wr * 32 + mb * 16 + frow;
            int cc = col0 + wc * 64 + nt * 8 + fcol;
            *(float2*)&C[(size_t)r * N + cc]       = make_float2(d[mb][nt][0], d[mb][nt][1]);
            *(float2*)&C[(size_t)(r + 8) * N + cc] = make_float2(d[mb][nt][2], d[mb][nt][3]);
        }
    }
}

// ---------------------------------------------------------------------------
// Fused RMSNorm + RoPE. Reads fp32 q/k, writes bf16 hi/lo (q pre-scaled).
// ---------------------------------------------------------------------------
__global__ __launch_bounds__(256)
void normrope_kernel(const float* __restrict__ q, const float* __restrict__ k,
                     __nv_bfloat16* __restrict__ Qhi, __nv_bfloat16* __restrict__ Qlo,
                     __nv_bfloat16* __restrict__ Khi, __nv_bfloat16* __restrict__ Klo,
                     const float* __restrict__ qn, const float* __restrict__ kn,
                     const float* __restrict__ sinp, const float* __restrict__ cosp) {
    int warp = (blockIdx.x * blockDim.x + threadIdx.x) >> 5;
    int lane = threadIdx.x & 31;
    const int NQ = MTOT * HH;
    const int NTOT = NQ + MTOT * KK;
    if (warp >= NTOT) return;

    const float* ptr;
    __nv_bfloat16 *dhi, *dlo;
    const float* w;
    int t;
    float oscale;
    if (warp < NQ) {
        int bt = warp >> 4;
        int h = warp & 15;
        size_t off = (size_t)bt * (HH * HD) + h * HD;
        ptr = q + off; dhi = Qhi + off; dlo = Qlo + off;
        w = qn;
        t = bt & (TT - 1);
        oscale = 0.08838834764831845f;   // 1/sqrt(128)
    } else {
        int v2 = warp - NQ;
        int bt = v2 >> 3;
        int kh = v2 & 7;
        size_t off = (size_t)bt * (KK * HD) + kh * HD;
        ptr = k + off; dhi = Khi + off; dlo = Klo + off;
        w = kn;
        t = bt & (TT - 1);
        oscale = 1.0f;
    }

    float2 a  = *(const float2*)(ptr + 2 * lane);
    float2 b2 = *(const float2*)(ptr + 64 + 2 * lane);

    float ss = a.x * a.x + a.y * a.y + b2.x * b2.x + b2.y * b2.y;
#pragma unroll
    for (int off = 16; off; off >>= 1) ss += __shfl_xor_sync(0xFFFFFFFFu, ss, off);
    float rinv = rsqrtf(ss * (1.0f / 128.0f) + 1e-6f);

    float w0 = w[2 * lane], w1 = w[2 * lane + 1];
    float w2 = w[64 + 2 * lane], w3 = w[65 + 2 * lane];
    float n0 = a.x * rinv * w0, n1 = a.y * rinv * w1;
    float n2 = b2.x * rinv * w2, n3 = b2.y * rinv * w3;

    float s0 = sinp[t * 64 + lane],      c0 = cosp[t * 64 + lane];
    float s1 = sinp[t * 64 + lane + 32], c1 = cosp[t * 64 + lane + 32];
    float o0 = (n0 * c0 - n1 * s0) * oscale;
    float o1 = (n2 * c1 - n3 * s1) * oscale;
    float o2 = (n0 * s0 + n1 * c0) * oscale;
    float o3 = (n2 * s1 + n3 * c1) * oscale;

    __nv_bfloat16 h0 = __float2bfloat16(o0);
    __nv_bfloat16 h1 = __float2bfloat16(o1);
    __nv_bfloat16 h2 = __float2bfloat16(o2);
    __nv_bfloat16 h3 = __float2bfloat16(o3);
    dhi[lane]      = h0;  dlo[lane]      = __float2bfloat16(o0 - __bfloat162float(h0));
    dhi[lane + 32] = h1;  dlo[lane + 32] = __float2bfloat16(o1 - __bfloat162float(h1));
    dhi[lane + 64] = h2;  dlo[lane + 64] = __float2bfloat16(o2 - __bfloat162float(h2));
    dhi[lane + 96] = h3;  dlo[lane + 96] = __float2bfloat16(o3 - __bfloat162float(h3));
}

// ---------------------------------------------------------------------------
// Flash attention on tensor cores (bf16 hi/lo split, 3 passes each GEMM).
// 64 q-rows per CTA, K/V tiles of 64. 8 warps: S = 4x2 over 64x64,
// PV = 4x2 over 64x128.
// ---------------------------------------------------------------------------
#define FK_STRB 272          // bytes per row of 128-wide bf16 tile (136 bf16)
#define FP_STRB 144          // bytes per row of P tile (72 bf16)
#define FTILE (64 * FK_STRB) // 17408

#define FOFF_QH 0
#define FOFF_QL (FOFF_QH + FTILE)
#define FOFF_KH (FOFF_QL + FTILE)
#define FOFF_KL (FOFF_KH + FTILE)
#define FOFF_VH (FOFF_KL + FTILE)
#define FOFF_VL (FOFF_VH + FTILE)
#define FOFF_PH (FOFF_VL + FTILE)
#define FOFF_PL (FOFF_PH + 64 * FP_STRB)
#define FOFF_S  (FOFF_PL + 64 * FP_STRB)
#define FOFF_ST (FOFF_S + 64 * 68 * 4)
#define FA2_SMEM (FOFF_ST + 3 * 64 * 4)

__global__ __launch_bounds__(256, 1)
void flash_mma(const __nv_bfloat16* __restrict__ Qhi, const __nv_bfloat16* __restrict__ Qlo,
               const __nv_bfloat16* __restrict__ Khi, const __nv_bfloat16* __restrict__ Klo,
               const __nv_bfloat16* __restrict__ Vhi, const __nv_bfloat16* __restrict__ Vlo,
               __nv_bfloat16* __restrict__ Ohi, __nv_bfloat16* __restrict__ Olo) {
    extern __shared__ char sm[];
    const uint32_t sb = smem_to_u32(sm);

    float* Sb   = (float*)(sm + FOFF_S);
    float* mrow = (float*)(sm + FOFF_ST);
    float* lrow = mrow + 64;
    float* arow = lrow + 64;

    const int qt = blockIdx.x;
    const int bh = blockIdx.y;
    const int b = bh >> 4;
    const int h = bh & 15;
    const int kh = h >> 1;

    const int tid = threadIdx.x;
    const int lane = tid & 31;
    const int wid = tid >> 5;
    const int wr = wid & 3;
    const int wc = wid >> 2;
    const int frow = lane >> 2;
    const int fcol = 2 * (lane & 3);

    // Load Q tile (hi/lo): 64 rows x 128 bf16 = 64x16 uint4 per array
    {
        const __nv_bfloat16* qh = Qhi + ((size_t)(b * TT + qt * 64)) * (HH*HD) + h * HD;
        const __nv_bfloat16* ql = Qlo + ((size_t)(b * TT + qt * 64)) * (HH*HD) + h * HD;
        for (int i = tid; i < 64 * 16; i += 256) {
            int r = i >> 4, s = i & 15;
            *(uint4*)(sm + FOFF_QH + r * FK_STRB + s * 16) = *(const uint4*)(qh + (size_t)r * (HH*HD) + s * 8);
            *(uint4*)(sm + FOFF_QL + r * FK_STRB + s * 16) = *(const uint4*)(ql + (size_t)r * (HH*HD) + s * 8);
        }
    }
    if (tid < 64) { mrow[tid] = -INFINITY; lrow[tid] = 0.0f; }

    float o[8][4];
#pragma unroll
    for (int n = 0; n < 8; ++n)
#pragma unroll
        for (int j = 0; j < 4; ++j) o[n][j] = 0.0f;

    __syncthreads();

    for (int kt = 0; kt <= qt; ++kt) {
        // Load K/V tiles (hi/lo)
        {
            size_t base = ((size_t)(b * TT + kt * 64)) * (KK*HD) + kh * HD;
            for (int i = tid; i < 64 * 16; i += 256) {
                int r = i >> 4, s = i & 15;
                size_t g = base + (size_t)r * (KK*HD) + s * 8;
                *(uint4*)(sm + FOFF_KH + r * FK_STRB + s * 16) = *(const uint4*)(Khi + g);
                *(uint4*)(sm + FOFF_KL + r * FK_STRB + s * 16) = *(const uint4*)(Klo + g);
                *(uint4*)(sm + FOFF_VH + r * FK_STRB + s * 16) = *(const uint4*)(Vhi + g);
                *(uint4*)(sm + FOFF_VL + r * FK_STRB + s * 16) = *(const uint4*)(Vlo + g);
            }
        }
        __syncthreads();

        // ---- S = Q @ K^T (3-pass hi/lo) ----
        float s[4][4];
#pragma unroll
        for (int i = 0; i < 4; ++i)
#pragma unroll
            for (int j = 0; j < 4; ++j) s[i][j] = 0.0f;

#pragma unroll
        for (int ks = 0; ks < 8; ++ks) {
            const uint32_t coff = ks * 32 + (lane >> 4) * 16;
            uint32_t aq[4], al4[4];
            {
                uint32_t addr = sb + FOFF_QH + (wr * 16 + (lane & 15)) * FK_STRB + coff;
                ldsm_x4(aq[0], aq[1], aq[2], aq[3], addr);
                ldsm_x4(al4[0], al4[1], al4[2], al4[3], addr + FTILE);
            }
#pragma unroll
            for (int nb = 0; nb < 2; ++nb) {
                uint32_t addr = sb + FOFF_KH + (wc * 32 + nb * 16 + (lane & 15)) * FK_STRB + coff;
                uint32_t kb[4], klb[4];
                ldsm_x4(kb[0], kb[1], kb[2], kb[3], addr);
                ldsm_x4(klb[0], klb[1], klb[2], klb[3], addr + FTILE);
                float* d0 = s[2*nb];
                float* d1 = s[2*nb+1];
                mma_bf16(d0, aq, kb[0], kb[2]);
                mma_bf16(d1, aq, kb[1], kb[3]);
                mma_bf16(d0, aq, klb[0], klb[2]);
                mma_bf16(d1, aq, klb[1], klb[3]);
                mma_bf16(d0, al4, kb[0], kb[2]);
                mma_bf16(d1, al4, kb[1], kb[3]);
            }
        }

        // Store S with causal mask (diag tile only)
        bool diag = (kt == qt);
#pragma unroll
        for (int nt = 0; nt < 4; ++nt) {
            int r = wr * 16 + frow;
            int c = wc * 32 + nt * 8 + fcol;
            float v0 = s[nt][0], v1 = s[nt][1], v2 = s[nt][2], v3 = s[nt][3];
            if (diag) {
                if (c     > r)     v0 = -1e30f;
                if (c + 1 > r)     v1 = -1e30f;
                if (c     > r + 8) v2 = -1e30f;
                if (c + 1 > r + 8) v3 = -1e30f;
            }
            Sb[r * 68 + c] = v0;       Sb[r * 68 + c + 1] = v1;
            Sb[(r+8) * 68 + c] = v2;   Sb[(r+8) * 68 + c + 1] = v3;
        }
        __syncthreads();

        // ---- online softmax (64 threads, one per row) ----
        if (tid < 64) {
            float m_old = mrow[tid];
            float mx = m_old;
            float* row = &Sb[tid * 68];
#pragma unroll 8
            for (int c = 0; c < 64; ++c) mx = fmaxf(mx, row[c]);
            float a = __expf(m_old - mx);
            float sum = 0.0f;
#pragma unroll 8
            for (int c = 0; c < 64; ++c) {
                float p = __expf(row[c] - mx);
                row[c] = p;
                sum += p;
            }
            lrow[tid] = lrow[tid] * a + sum;
            mrow[tid] = mx;
            arow[tid] = a;
        }
        __syncthreads();

        // ---- convert P -> bf16 hi/lo (256 threads, 16 cols each) ----
        {
            int r = tid >> 2;
            int c0 = (tid & 3) * 16;
            const float* row = &Sb[r * 68 + c0];
            __nv_bfloat16* ph = (__nv_bfloat16*)(sm + FOFF_PH + r * FP_STRB) + c0;
            __nv_bfloat16* pl = (__nv_bfloat16*)(sm + FOFF_PL + r * FP_STRB) + c0;
#pragma unroll
            for (int j = 0; j < 16; ++j) {
                float p = row[j];
                __nv_bfloat16 hi = __float2bfloat16(p);
                ph[j] = hi;
                pl[j] = __float2bfloat16(p - __bfloat162float(hi));
            }
        }
        __syncthreads();

        // ---- rescale O, then O += P @ V (3-pass hi/lo) ----
        {
            float a0 = arow[wr * 16 + frow];
            float a1 = arow[wr * 16 + frow + 8];
#pragma unroll
            for (int nt = 0; nt < 8; ++nt) {
                o[nt][0] *= a0; o[nt][1] *= a0;
                o[nt][2] *= a1; o[nt][3] *= a1;
            }
        }

#pragma unroll
        for (int ks = 0; ks < 4; ++ks) {
            uint32_t ap[4], apl[4];
            {
                uint32_t addr = sb + FOFF_PH + (wr * 16 + (lane & 15)) * FP_STRB
                                + ks * 32 + (lane >> 4) * 16;
                ldsm_x4(ap[0], ap[1], ap[2], ap[3], addr);
                ldsm_x4(apl[0], apl[1], apl[2], apl[3], addr + 64 * FP_STRB);
            }
#pragma unroll
            for (int nb = 0; nb < 4; ++nb) {
                uint32_t addr = sb + FOFF_VH + (ks * 16 + (lane & 15)) * FK_STRB
                                + (wc * 64 + nb * 16 + (lane >> 4) * 8) * 2;
                uint32_t vh4[4], vl4[4];
                ldsm_x4_trans(vh4[0], vh4[1], vh4[2], vh4[3], addr);
                ldsm_x4_trans(vl4[0], vl4[1], vl4[2], vl4[3], addr + FTILE);
                float* d0 = o[2*nb];
                float* d1 = o[2*nb+1];
                mma_bf16(d0, ap, vh4[0], vh4[1]);
                mma_bf16(d1, ap, vh4[2], vh4[3]);
                mma_bf16(d0, ap, vl4[0], vl4[1]);
                mma_bf16(d1, ap, vl4[2], vl4[3]);
                mma_bf16(d0, apl, vh4[0], vh4[1]);
                mma_bf16(d1, apl, vh4[2], vh4[3]);
            }
        }
        __syncthreads();   // protect K/V/P tiles before next iteration
    }

    // Epilogue: normalize by 1/l, write bf16 hi/lo (b,t,h,d)
    {
        float li0 = 1.0f / lrow[wr * 16 + frow];
        float li1 = 1.0f / lrow[wr * 16 + frow + 8];
        int r0g = b * TT + qt * 64 + wr * 16 + frow;
#pragma unroll
        for (int nt = 0; nt < 8; ++nt) {
            int c = wc * 64 + nt * 8 + fcol;
            size_t o0 = (size_t)r0g * (HH*HD) + h * HD + c;
            size_t o1 = (size_t)(r0g + 8) * (HH*HD) + h * HD + c;
            float v00 = o[nt][0] * li0, v01 = o[nt][1] * li0;
            float v10 = o[nt][2] * li1, v11 = o[nt][3] * li1;
            __nv_bfloat16 h00 = __float2bfloat16(v00);
            __nv_bfloat16 h01 = __float2bfloat16(v01);
            __nv_bfloat16 h10 = __float2bfloat16(v10);
            __nv_bfloat16 h11 = __float2bfloat16(v11);
            Ohi[o0] = h00; Ohi[o0 + 1] = h01;
            Ohi[o1] = h10; Ohi[o1 + 1] = h11;
            Olo[o0]     = __float2bfloat16(v00 - __bfloat162float(h00));
            Olo[o0 + 1] = __float2bfloat16(v01 - __bfloat162float(h01));
            Olo[o1]     = __float2bfloat16(v10 - __bfloat162float(h10));
            Olo[o1 + 1] = __float2bfloat16(v11 - __bfloat162float(h11));
        }
    }
}

// ---------------------------------------------------------------------------
extern "C" void kernel_launch(void* const* d_in, const int* in_sizes, int n_in,
                              void* d_out, int out_size) {
    const float* x    = (const float*)d_in[0];
    const float* Wq   = (const float*)d_in[1];
    const float* Wk   = (const float*)d_in[2];
    const float* Wv   = (const float*)d_in[3];
    const float* Wo   = (const float*)d_in[4];
    const float* qn   = (const float*)d_in[5];
    const float* kn   = (const float*)d_in[6];
    const float* sinp = (const float*)d_in[7];
    const float* cosp = (const float*)d_in[8];
    float* out = (float*)d_out;

    __nv_bfloat16 *xhi, *xlo, *wqh, *wql, *wkh, *wkl, *wvh, *wvl, *woh, *wol;
    __nv_bfloat16 *qhi, *qlo, *khi, *klo, *vhi, *vlo, *ohi, *olo;
    float *qr, *kr, *vr;
    cudaGetSymbolAddress((void**)&xhi, g_xhi);
    cudaGetSymbolAddress((void**)&xlo, g_xlo);
    cudaGetSymbolAddress((void**)&wqh, g_wqt_hi);
    cudaGetSymbolAddress((void**)&wql, g_wqt_lo);
    cudaGetSymbolAddress((void**)&wkh, g_wkt_hi);
    cudaGetSymbolAddress((void**)&wkl, g_wkt_lo);
    cudaGetSymbolAddress((void**)&wvh, g_wvt_hi);
    cudaGetSymbolAddress((void**)&wvl, g_wvt_lo);
    cudaGetSymbolAddress((void**)&woh, g_wot_hi);
    cudaGetSymbolAddress((void**)&wol, g_wot_lo);
    cudaGetSymbolAddress((void**)&qr, g_q_raw);
    cudaGetSymbolAddress((void**)&kr, g_k_raw);
    cudaGetSymbolAddress((void**)&vr, g_v_raw);
    cudaGetSymbolAddress((void**)&qhi, g_qhi);
    cudaGetSymbolAddress((void**)&qlo, g_qlo);
    cudaGetSymbolAddress((void**)&khi, g_khi);
    cudaGetSymbolAddress((void**)&klo, g_klo);
    cudaGetSymbolAddress((void**)&vhi, g_vhi);
    cudaGetSymbolAddress((void**)&vlo, g_vlo);
    cudaGetSymbolAddress((void**)&ohi, g_ohi);
    cudaGetSymbolAddress((void**)&olo, g_olo);

    // 1. split-convert x
    convert_split_kernel<<<(MTOT * DD / 4 + 255) / 256, 256>>>(x, xhi, xlo, MTOT * DD / 4);

    // 2. transpose + split weights
    transpose_split_kernel<<<dim3((HH*HD)/32, DD/32), 256>>>(Wq, wqh, wql, DD, HH*HD);
    transpose_split_kernel<<<dim3((KK*HD)/32, DD/32), 256>>>(Wk, wkh, wkl, DD, KK*HD);
    transpose_split_kernel<<<dim3((KK*HD)/32, DD/32), 256>>>(Wv, wvh, wvl, DD, KK*HD);
    transpose_split_kernel<<<dim3((HH*HD)/32, (HH*HD)/32), 256>>>(Wo, woh, wol, HH*HD, HH*HD);

    // 3. QKV projections on tensor cores
    cudaFuncSetAttribute(gemm_mma, cudaFuncAttributeMaxDynamicSharedMemorySize, GSMEM_DYN);
    gemm_mma<<<dim3((HH*HD)/128, MTOT/128), 256, GSMEM_DYN>>>(xhi, xlo, wqh, wql, qr, HH*HD, DD);
    gemm_mma<<<dim3((KK*HD)/128, MTOT/128), 256, GSMEM_DYN>>>(xhi, xlo, wkh, wkl, kr, KK*HD, DD);
    gemm_mma<<<dim3((KK*HD)/128, MTOT/128), 256, GSMEM_DYN>>>(xhi, xlo, wvh, wvl, vr, KK*HD, DD);

    // 4. RMSNorm + RoPE -> bf16 hi/lo q,k ; split-convert v
    normrope_kernel<<<12288, 256>>>(qr, kr, qhi, qlo, khi, klo, qn, kn, sinp, cosp);
    convert_split_kernel<<<(MTOT * KK * HD / 4 + 255) / 256, 256>>>(vr, vhi, vlo, MTOT * KK * HD / 4);

    // 5. causal flash attention on tensor cores
    cudaFuncSetAttribute(flash_mma, cudaFuncAttributeMaxDynamicSharedMemorySize, FA2_SMEM);
    flash_mma<<<dim3(TT / 64, BB * HH), 256, FA2_SMEM>>>(qhi, qlo, khi, klo, vhi, vlo, ohi, olo);

    // 6. output projection on tensor cores
    gemm_mma<<<dim3((HH*HD)/128, MTOT/128), 256, GSMEM_DYN>>>(ohi, olo, woh, wol, out, HH*HD, HH*HD);
}

// round 5
// speedup vs baseline: 2.5116x; 1.1108x over previous
#include <cuda_runtime.h>
#include <cuda_bf16.h>
#include <math.h>
#include <cstdint>

// Problem constants
#define BB 2
#define TT 2048
#define DD 2048
#define HH 16
#define KK 8
#define HD 128
#define MTOT (BB*TT)   // 4096

// ---------------------------------------------------------------------------
// Scratch (device globals; no allocation allowed)
// ---------------------------------------------------------------------------
__device__ __nv_bfloat16 g_xhi [(size_t)MTOT * DD];
__device__ __nv_bfloat16 g_xlo [(size_t)MTOT * DD];
__device__ __nv_bfloat16 g_wqt_hi[(size_t)(HH*HD) * DD];
__device__ __nv_bfloat16 g_wqt_lo[(size_t)(HH*HD) * DD];
__device__ __nv_bfloat16 g_wkt_hi[(size_t)(KK*HD) * DD];
__device__ __nv_bfloat16 g_wkt_lo[(size_t)(KK*HD) * DD];
__device__ __nv_bfloat16 g_wvt_hi[(size_t)(KK*HD) * DD];
__device__ __nv_bfloat16 g_wvt_lo[(size_t)(KK*HD) * DD];
__device__ __nv_bfloat16 g_wot_hi[(size_t)DD * (HH*HD)];
__device__ __nv_bfloat16 g_wot_lo[(size_t)DD * (HH*HD)];
__device__ float g_q_raw[(size_t)MTOT * (HH*HD)];
__device__ float g_k_raw[(size_t)MTOT * (KK*HD)];
__device__ float g_v_raw[(size_t)MTOT * (KK*HD)];
__device__ __nv_bfloat16 g_qhi [(size_t)MTOT * (HH*HD)];
__device__ __nv_bfloat16 g_qlo [(size_t)MTOT * (HH*HD)];
__device__ __nv_bfloat16 g_khi [(size_t)MTOT * (KK*HD)];
__device__ __nv_bfloat16 g_klo [(size_t)MTOT * (KK*HD)];
__device__ __nv_bfloat16 g_vhi [(size_t)MTOT * (KK*HD)];
__device__ __nv_bfloat16 g_vlo [(size_t)MTOT * (KK*HD)];
__device__ __nv_bfloat16 g_ohi [(size_t)MTOT * (HH*HD)];
__device__ __nv_bfloat16 g_olo [(size_t)MTOT * (HH*HD)];

// ---------------------------------------------------------------------------
// mma.sync helpers
// ---------------------------------------------------------------------------
__device__ __forceinline__ uint32_t smem_to_u32(const void* p) {
    uint32_t a;
    asm("{ .reg .u64 t; cvta.to.shared.u64 t, %1; cvt.u32.u64 %0, t; }"
        : "=r"(a) : "l"(p));
    return a;
}

__device__ __forceinline__ void ldsm_x4(uint32_t& r0, uint32_t& r1,
                                        uint32_t& r2, uint32_t& r3, uint32_t addr) {
    asm volatile("ldmatrix.sync.aligned.m8n8.x4.shared.b16 {%0,%1,%2,%3}, [%4];"
                 : "=r"(r0), "=r"(r1), "=r"(r2), "=r"(r3) : "r"(addr));
}

__device__ __forceinline__ void ldsm_x4_trans(uint32_t& r0, uint32_t& r1,
                                              uint32_t& r2, uint32_t& r3, uint32_t addr) {
    asm volatile("ldmatrix.sync.aligned.m8n8.x4.trans.shared.b16 {%0,%1,%2,%3}, [%4];"
                 : "=r"(r0), "=r"(r1), "=r"(r2), "=r"(r3) : "r"(addr));
}

__device__ __forceinline__ void mma_bf16(float* d, const uint32_t* a,
                                         uint32_t b0, uint32_t b1) {
    asm volatile(
        "mma.sync.aligned.m16n8k16.row.col.f32.bf16.bf16.f32 "
        "{%0,%1,%2,%3}, {%4,%5,%6,%7}, {%8,%9}, {%0,%1,%2,%3};"
        : "+f"(d[0]), "+f"(d[1]), "+f"(d[2]), "+f"(d[3])
        : "r"(a[0]), "r"(a[1]), "r"(a[2]), "r"(a[3]), "r"(b0), "r"(b1));
}

// ---------------------------------------------------------------------------
// Conversion: fp32 -> (bf16 hi, bf16 lo), same layout.
// ---------------------------------------------------------------------------
__global__ __launch_bounds__(256)
void convert_split_kernel(const float* __restrict__ X,
                          __nv_bfloat16* __restrict__ Hi,
                          __nv_bfloat16* __restrict__ Lo, int n4) {
    int i = blockIdx.x * 256 + threadIdx.x;
    if (i >= n4) return;
    float4 v = ((const float4*)X)[i];
    __nv_bfloat16 h0 = __float2bfloat16(v.x), h1 = __float2bfloat16(v.y);
    __nv_bfloat16 h2 = __float2bfloat16(v.z), h3 = __float2bfloat16(v.w);
    __nv_bfloat16 l0 = __float2bfloat16(v.x - __bfloat162float(h0));
    __nv_bfloat16 l1 = __float2bfloat16(v.y - __bfloat162float(h1));
    __nv_bfloat16 l2 = __float2bfloat16(v.z - __bfloat162float(h2));
    __nv_bfloat16 l3 = __float2bfloat16(v.w - __bfloat162float(h3));
    __nv_bfloat162* hp = (__nv_bfloat162*)(Hi + 4 * (size_t)i);
    __nv_bfloat162* lp = (__nv_bfloat162*)(Lo + 4 * (size_t)i);
    hp[0] = __nv_bfloat162(h0, h1); hp[1] = __nv_bfloat162(h2, h3);
    lp[0] = __nv_bfloat162(l0, l1); lp[1] = __nv_bfloat162(l2, l3);
}

// ---------------------------------------------------------------------------
// Transpose + split: W[Kd, N] fp32 -> T_hi/T_lo [N, Kd] bf16
// ---------------------------------------------------------------------------
__global__ __launch_bounds__(256)
void transpose_split_kernel(const float* __restrict__ W,
                            __nv_bfloat16* __restrict__ Thi,
                            __nv_bfloat16* __restrict__ Tlo, int Kd, int N) {
    __shared__ float tile[32][33];
    int n0 = blockIdx.x * 32, k0 = blockIdx.y * 32;
    int tx = threadIdx.x & 31, ty = threadIdx.x >> 5;  // 32 x 8
#pragma unroll
    for (int r = ty; r < 32; r += 8)
        tile[r][tx] = W[(size_t)(k0 + r) * N + n0 + tx];
    __syncthreads();
#pragma unroll
    for (int r = ty; r < 32; r += 8) {
        float v = tile[tx][r];
        __nv_bfloat16 h = __float2bfloat16(v);
        size_t o = (size_t)(n0 + r) * Kd + k0 + tx;
        Thi[o] = h;
        Tlo[o] = __float2bfloat16(v - __bfloat162float(h));
    }
}

// ---------------------------------------------------------------------------
// bf16-split tensor-core GEMM core (pass-major mma ordering).
// 128x128 CTA tile, 8 warps, K-chunk 32, double-buffered SMEM.
// ---------------------------------------------------------------------------
#define GPAD 40
#define GTILE_BYTES (128 * GPAD * 2)
#define GSTAGE_BYTES (4 * GTILE_BYTES)
#define GSMEM_DYN (2 * GSTAGE_BYTES)

__device__ __forceinline__ void gemm_core(
    const __nv_bfloat16* __restrict__ Ahi, const __nv_bfloat16* __restrict__ Alo,
    const __nv_bfloat16* __restrict__ Bhi, const __nv_bfloat16* __restrict__ Blo,
    float* __restrict__ C, int N, int Kd, int row0, int col0, char* smg) {
    const uint32_t sbase0 = smem_to_u32(smg);

    const int tid = threadIdx.x;
    const int lane = tid & 31;
    const int wid = tid >> 5;
    const int wr = wid & 3;
    const int wc = wid >> 2;

    float d[2][8][4];
#pragma unroll
    for (int m = 0; m < 2; ++m)
#pragma unroll
        for (int n = 0; n < 8; ++n)
#pragma unroll
            for (int j = 0; j < 4; ++j) d[m][n][j] = 0.0f;

    const __nv_bfloat16* gb[4] = {Ahi, Alo, Bhi, Blo};
    int grow[8], gseg[8];
#pragma unroll
    for (int a = 0; a < 4; ++a) {
        int r0 = (a < 2) ? row0 : col0;
        int s0 = tid, s1 = tid + 256;
        grow[2*a]   = r0 + (s0 >> 2); gseg[2*a]   = s0 & 3;
        grow[2*a+1] = r0 + (s1 >> 2); gseg[2*a+1] = s1 & 3;
    }

    uint4 pf[8];
    auto ldg_chunk = [&](int k0) {
#pragma unroll
        for (int a = 0; a < 4; ++a) {
#pragma unroll
            for (int j = 0; j < 2; ++j) {
                int e = 2 * a + j;
                pf[e] = *(const uint4*)(gb[a] + (size_t)grow[e] * Kd + k0 + gseg[e] * 8);
            }
        }
    };
    auto sts_chunk = [&](int buf) {
        char* st = smg + buf * GSTAGE_BYTES;
#pragma unroll
        for (int a = 0; a < 4; ++a) {
#pragma unroll
            for (int j = 0; j < 2; ++j) {
                int e = 2 * a + j;
                int s = tid + j * 256;
                *(uint4*)(st + a * GTILE_BYTES + (s >> 2) * (GPAD*2) + (s & 3) * 16) = pf[e];
            }
        }
    };

    const int NC = Kd / 32;

    ldg_chunk(0);
    sts_chunk(0);
    __syncthreads();

    for (int c = 0; c < NC; ++c) {
        const int cur = c & 1;
        const uint32_t sb = sbase0 + cur * GSTAGE_BYTES;

        if (c + 1 < NC) ldg_chunk((c + 1) * 32);

#pragma unroll
        for (int ks = 0; ks < 2; ++ks) {
            const uint32_t coff = ks * 32 + (lane >> 4) * 16;
            uint32_t ah[2][4], al[2][4];
#pragma unroll
            for (int mb = 0; mb < 2; ++mb) {
                uint32_t addr = sb + (wr * 32 + mb * 16 + (lane & 15)) * (GPAD*2) + coff;
                ldsm_x4(ah[mb][0], ah[mb][1], ah[mb][2], ah[mb][3], addr);
                ldsm_x4(al[mb][0], al[mb][1], al[mb][2], al[mb][3], addr + GTILE_BYTES);
            }
            uint32_t bh[4][4], bl[4][4];
#pragma unroll
            for (int nb = 0; nb < 4; ++nb) {
                uint32_t addr = sb + 2 * GTILE_BYTES +
                                (wc * 64 + nb * 16 + (lane & 15)) * (GPAD*2) + coff;
                ldsm_x4(bh[nb][0], bh[nb][1], bh[nb][2], bh[nb][3], addr);
                ldsm_x4(bl[nb][0], bl[nb][1], bl[nb][2], bl[nb][3], addr + GTILE_BYTES);
            }
            // pass-major ordering: 16 independent mma between accumulator reuse
#pragma unroll
            for (int pass = 0; pass < 3; ++pass) {
#pragma unroll
                for (int mb = 0; mb < 2; ++mb) {
#pragma unroll
                    for (int nb = 0; nb < 4; ++nb) {
                        const uint32_t* a = (pass == 2) ? al[mb] : ah[mb];
                        const uint32_t* b = (pass == 1) ? bl[nb] : bh[nb];
                        mma_bf16(d[mb][2*nb],   a, b[0], b[2]);
                        mma_bf16(d[mb][2*nb+1], a, b[1], b[3]);
                    }
                }
            }
        }

        if (c + 1 < NC) sts_chunk(cur ^ 1);
        __syncthreads();
    }

    const int frow = lane >> 2;
    const int fcol = 2 * (lane & 3);
#pragma unroll
    for (int mb = 0; mb < 2; ++mb) {
#pragma unroll
        for (int nt = 0; nt < 8; ++nt) {
            int r = row0 + wr * 32 + mb * 16 + frow;
            int cc = col0 + wc * 64 + nt * 8 + fcol;
            *(float2*)&C[(size_t)r * N + cc]       = make_float2(d[mb][nt][0], d[mb][nt][1]);
            *(float2*)&C[(size_t)(r + 8) * N + cc] = make_float2(d[mb][nt][2], d[mb][nt][3]);
        }
    }
}

// Single GEMM (used for Wo projection)
__global__ __launch_bounds__(256, 1)
void gemm_mma(const __nv_bfloat16* __restrict__ Ahi, const __nv_bfloat16* __restrict__ Alo,
              const __nv_bfloat16* __restrict__ Bhi, const __nv_bfloat16* __restrict__ Blo,
              float* __restrict__ C, int N, int Kd) {
    extern __shared__ char smg[];
    gemm_core(Ahi, Alo, Bhi, Blo, C, N, Kd, blockIdx.y * 128, blockIdx.x * 128, smg);
}

// Fused QKV GEMM: col-tiles 0-15 -> Wq/qr, 16-23 -> Wk/kr, 24-31 -> Wv/vr
__global__ __launch_bounds__(256, 1)
void gemm_qkv(const __nv_bfloat16* __restrict__ Xhi, const __nv_bfloat16* __restrict__ Xlo,
              const __nv_bfloat16* __restrict__ Wqh, const __nv_bfloat16* __restrict__ Wql,
              const __nv_bfloat16* __restrict__ Wkh, const __nv_bfloat16* __restrict__ Wkl,
              const __nv_bfloat16* __restrict__ Wvh, const __nv_bfloat16* __restrict__ Wvl,
              float* __restrict__ Q, float* __restrict__ Kc, float* __restrict__ V) {
    extern __shared__ char smg[];
    int ct = blockIdx.x;
    const __nv_bfloat16 *bh, *bl;
    float* C;
    int N, col0;
    if (ct < 16)      { bh = Wqh; bl = Wql; C = Q;  N = HH*HD; col0 = ct * 128; }
    else if (ct < 24) { bh = Wkh; bl = Wkl; C = Kc; N = KK*HD; col0 = (ct - 16) * 128; }
    else              { bh = Wvh; bl = Wvl; C = V;  N = KK*HD; col0 = (ct - 24) * 128; }
    gemm_core(Xhi, Xlo, bh, bl, C, N, DD, blockIdx.y * 128, col0, smg);
}

// ---------------------------------------------------------------------------
// Fused RMSNorm + RoPE. Reads fp32 q/k, writes bf16 hi/lo (q pre-scaled).
// ---------------------------------------------------------------------------
__global__ __launch_bounds__(256)
void normrope_kernel(const float* __restrict__ q, const float* __restrict__ k,
                     __nv_bfloat16* __restrict__ Qhi, __nv_bfloat16* __restrict__ Qlo,
                     __nv_bfloat16* __restrict__ Khi, __nv_bfloat16* __restrict__ Klo,
                     const float* __restrict__ qn, const float* __restrict__ kn,
                     const float* __restrict__ sinp, const float* __restrict__ cosp) {
    int warp = (blockIdx.x * blockDim.x + threadIdx.x) >> 5;
    int lane = threadIdx.x & 31;
    const int NQ = MTOT * HH;
    const int NTOT = NQ + MTOT * KK;
    if (warp >= NTOT) return;

    const float* ptr;
    __nv_bfloat16 *dhi, *dlo;
    const float* w;
    int t;
    float oscale;
    if (warp < NQ) {
        int bt = warp >> 4;
        int h = warp & 15;
        size_t off = (size_t)bt * (HH * HD) + h * HD;
        ptr = q + off; dhi = Qhi + off; dlo = Qlo + off;
        w = qn;
        t = bt & (TT - 1);
        oscale = 0.08838834764831845f;   // 1/sqrt(128)
    } else {
        int v2 = warp - NQ;
        int bt = v2 >> 3;
        int kh = v2 & 7;
        size_t off = (size_t)bt * (KK * HD) + kh * HD;
        ptr = k + off; dhi = Khi + off; dlo = Klo + off;
        w = kn;
        t = bt & (TT - 1);
        oscale = 1.0f;
    }

    float2 a  = *(const float2*)(ptr + 2 * lane);
    float2 b2 = *(const float2*)(ptr + 64 + 2 * lane);

    float ss = a.x * a.x + a.y * a.y + b2.x * b2.x + b2.y * b2.y;
#pragma unroll
    for (int off = 16; off; off >>= 1) ss += __shfl_xor_sync(0xFFFFFFFFu, ss, off);
    float rinv = rsqrtf(ss * (1.0f / 128.0f) + 1e-6f);

    float w0 = w[2 * lane], w1 = w[2 * lane + 1];
    float w2 = w[64 + 2 * lane], w3 = w[65 + 2 * lane];
    float n0 = a.x * rinv * w0, n1 = a.y * rinv * w1;
    float n2 = b2.x * rinv * w2, n3 = b2.y * rinv * w3;

    float s0 = sinp[t * 64 + lane],      c0 = cosp[t * 64 + lane];
    float s1 = sinp[t * 64 + lane + 32], c1 = cosp[t * 64 + lane + 32];
    float o0 = (n0 * c0 - n1 * s0) * oscale;
    float o1 = (n2 * c1 - n3 * s1) * oscale;
    float o2 = (n0 * s0 + n1 * c0) * oscale;
    float o3 = (n2 * s1 + n3 * c1) * oscale;

    __nv_bfloat16 h0 = __float2bfloat16(o0);
    __nv_bfloat16 h1 = __float2bfloat16(o1);
    __nv_bfloat16 h2 = __float2bfloat16(o2);
    __nv_bfloat16 h3 = __float2bfloat16(o3);
    dhi[lane]      = h0;  dlo[lane]      = __float2bfloat16(o0 - __bfloat162float(h0));
    dhi[lane + 32] = h1;  dlo[lane + 32] = __float2bfloat16(o1 - __bfloat162float(h1));
    dhi[lane + 64] = h2;  dlo[lane + 64] = __float2bfloat16(o2 - __bfloat162float(h2));
    dhi[lane + 96] = h3;  dlo[lane + 96] = __float2bfloat16(o3 - __bfloat162float(h3));
}

// ---------------------------------------------------------------------------
// Flash attention on tensor cores (bf16 hi/lo split, pass-major ordering,
// fused parallel softmax + P split).
// ---------------------------------------------------------------------------
#define FK_STRB 272          // bytes per row of 128-wide bf16 tile (136 bf16)
#define FP_STRB 144          // bytes per row of P tile (72 bf16)
#define FTILE (64 * FK_STRB) // 17408

#define FOFF_QH 0
#define FOFF_QL (FOFF_QH + FTILE)
#define FOFF_KH (FOFF_QL + FTILE)
#define FOFF_KL (FOFF_KH + FTILE)
#define FOFF_VH (FOFF_KL + FTILE)
#define FOFF_VL (FOFF_VH + FTILE)
#define FOFF_PH (FOFF_VL + FTILE)
#define FOFF_PL (FOFF_PH + 64 * FP_STRB)
#define FOFF_S  (FOFF_PL + 64 * FP_STRB)
#define FOFF_ST (FOFF_S + 64 * 68 * 4)
#define FA2_SMEM (FOFF_ST + 3 * 64 * 4)

__global__ __launch_bounds__(256, 1)
void flash_mma(const __nv_bfloat16* __restrict__ Qhi, const __nv_bfloat16* __restrict__ Qlo,
               const __nv_bfloat16* __restrict__ Khi, const __nv_bfloat16* __restrict__ Klo,
               const __nv_bfloat16* __restrict__ Vhi, const __nv_bfloat16* __restrict__ Vlo,
               __nv_bfloat16* __restrict__ Ohi, __nv_bfloat16* __restrict__ Olo) {
    extern __shared__ char sm[];
    const uint32_t sb = smem_to_u32(sm);

    float* Sb   = (float*)(sm + FOFF_S);
    float* mrow = (float*)(sm + FOFF_ST);
    float* lrow = mrow + 64;
    float* arow = lrow + 64;

    const int qt = blockIdx.x;
    const int bh = blockIdx.y;
    const int b = bh >> 4;
    const int h = bh & 15;
    const int kh = h >> 1;

    const int tid = threadIdx.x;
    const int lane = tid & 31;
    const int wid = tid >> 5;
    const int wr = wid & 3;
    const int wc = wid >> 2;
    const int frow = lane >> 2;
    const int fcol = 2 * (lane & 3);

    // Load Q tile (hi/lo)
    {
        const __nv_bfloat16* qh = Qhi + ((size_t)(b * TT + qt * 64)) * (HH*HD) + h * HD;
        const __nv_bfloat16* ql = Qlo + ((size_t)(b * TT + qt * 64)) * (HH*HD) + h * HD;
        for (int i = tid; i < 64 * 16; i += 256) {
            int r = i >> 4, s = i & 15;
            *(uint4*)(sm + FOFF_QH + r * FK_STRB + s * 16) = *(const uint4*)(qh + (size_t)r * (HH*HD) + s * 8);
            *(uint4*)(sm + FOFF_QL + r * FK_STRB + s * 16) = *(const uint4*)(ql + (size_t)r * (HH*HD) + s * 8);
        }
    }
    if (tid < 64) { mrow[tid] = -INFINITY; lrow[tid] = 0.0f; }

    float o[8][4];
#pragma unroll
    for (int n = 0; n < 8; ++n)
#pragma unroll
        for (int j = 0; j < 4; ++j) o[n][j] = 0.0f;

    __syncthreads();

    for (int kt = 0; kt <= qt; ++kt) {
        // Load K/V tiles (hi/lo)
        {
            size_t base = ((size_t)(b * TT + kt * 64)) * (KK*HD) + kh * HD;
            for (int i = tid; i < 64 * 16; i += 256) {
                int r = i >> 4, s = i & 15;
                size_t g = base + (size_t)r * (KK*HD) + s * 8;
                *(uint4*)(sm + FOFF_KH + r * FK_STRB + s * 16) = *(const uint4*)(Khi + g);
                *(uint4*)(sm + FOFF_KL + r * FK_STRB + s * 16) = *(const uint4*)(Klo + g);
                *(uint4*)(sm + FOFF_VH + r * FK_STRB + s * 16) = *(const uint4*)(Vhi + g);
                *(uint4*)(sm + FOFF_VL + r * FK_STRB + s * 16) = *(const uint4*)(Vlo + g);
            }
        }
        __syncthreads();

        // ---- S = Q @ K^T (3-pass hi/lo, pass-major) ----
        float s[4][4];
#pragma unroll
        for (int i = 0; i < 4; ++i)
#pragma unroll
            for (int j = 0; j < 4; ++j) s[i][j] = 0.0f;

#pragma unroll
        for (int ks = 0; ks < 8; ++ks) {
            const uint32_t coff = ks * 32 + (lane >> 4) * 16;
            uint32_t aq[4], al4[4];
            {
                uint32_t addr = sb + FOFF_QH + (wr * 16 + (lane & 15)) * FK_STRB + coff;
                ldsm_x4(aq[0], aq[1], aq[2], aq[3], addr);
                ldsm_x4(al4[0], al4[1], al4[2], al4[3], addr + FTILE);
            }
            uint32_t kb[2][4], klb[2][4];
#pragma unroll
            for (int nb = 0; nb < 2; ++nb) {
                uint32_t addr = sb + FOFF_KH + (wc * 32 + nb * 16 + (lane & 15)) * FK_STRB + coff;
                ldsm_x4(kb[nb][0], kb[nb][1], kb[nb][2], kb[nb][3], addr);
                ldsm_x4(klb[nb][0], klb[nb][1], klb[nb][2], klb[nb][3], addr + FTILE);
            }
#pragma unroll
            for (int pass = 0; pass < 3; ++pass) {
#pragma unroll
                for (int nb = 0; nb < 2; ++nb) {
                    const uint32_t* a = (pass == 2) ? al4 : aq;
                    const uint32_t* bV = (pass == 1) ? klb[nb] : kb[nb];
                    mma_bf16(s[2*nb],   a, bV[0], bV[2]);
                    mma_bf16(s[2*nb+1], a, bV[1], bV[3]);
                }
            }
        }

        // Store S with causal mask (diag tile only)
        bool diag = (kt == qt);
#pragma unroll
        for (int nt = 0; nt < 4; ++nt) {
            int r = wr * 16 + frow;
            int c = wc * 32 + nt * 8 + fcol;
            float v0 = s[nt][0], v1 = s[nt][1], v2 = s[nt][2], v3 = s[nt][3];
            if (diag) {
                if (c     > r)     v0 = -1e30f;
                if (c + 1 > r)     v1 = -1e30f;
                if (c     > r + 8) v2 = -1e30f;
                if (c + 1 > r + 8) v3 = -1e30f;
            }
            Sb[r * 68 + c] = v0;       Sb[r * 68 + c + 1] = v1;
            Sb[(r+8) * 68 + c] = v2;   Sb[(r+8) * 68 + c + 1] = v3;
        }
        __syncthreads();

        // ---- fused online softmax + P hi/lo split (4 threads per row) ----
        {
            int r = tid >> 2;
            int quarter = tid & 3;
            int c0 = quarter * 16;
            const float* row = &Sb[r * 68 + c0];
            float mx = -INFINITY;
#pragma unroll
            for (int j = 0; j < 16; ++j) mx = fmaxf(mx, row[j]);
            mx = fmaxf(mx, __shfl_xor_sync(0xFFFFFFFFu, mx, 1));
            mx = fmaxf(mx, __shfl_xor_sync(0xFFFFFFFFu, mx, 2));
            float m_old = mrow[r];
            mx = fmaxf(mx, m_old);
            float a = __expf(m_old - mx);
            float sum = 0.0f;
            __nv_bfloat16* ph = (__nv_bfloat16*)(sm + FOFF_PH + r * FP_STRB) + c0;
            __nv_bfloat16* pl = (__nv_bfloat16*)(sm + FOFF_PL + r * FP_STRB) + c0;
#pragma unroll
            for (int j = 0; j < 16; ++j) {
                float p = __expf(row[j] - mx);
                sum += p;
                __nv_bfloat16 hi = __float2bfloat16(p);
                ph[j] = hi;
                pl[j] = __float2bfloat16(p - __bfloat162float(hi));
            }
            sum += __shfl_xor_sync(0xFFFFFFFFu, sum, 1);
            sum += __shfl_xor_sync(0xFFFFFFFFu, sum, 2);
            if (quarter == 0) {
                lrow[r] = lrow[r] * a + sum;
                mrow[r] = mx;
                arow[r] = a;
            }
        }
        __syncthreads();

        // ---- rescale O, then O += P @ V (3-pass hi/lo, pass-major) ----
        {
            float a0 = arow[wr * 16 + frow];
            float a1 = arow[wr * 16 + frow + 8];
#pragma unroll
            for (int nt = 0; nt < 8; ++nt) {
                o[nt][0] *= a0; o[nt][1] *= a0;
                o[nt][2] *= a1; o[nt][3] *= a1;
            }
        }

#pragma unroll
        for (int ks = 0; ks < 4; ++ks) {
            uint32_t ap[4], apl[4];
            {
                uint32_t addr = sb + FOFF_PH + (wr * 16 + (lane & 15)) * FP_STRB
                                + ks * 32 + (lane >> 4) * 16;
                ldsm_x4(ap[0], ap[1], ap[2], ap[3], addr);
                ldsm_x4(apl[0], apl[1], apl[2], apl[3], addr + 64 * FP_STRB);
            }
            // load V-hi fragments for all 4 n-blocks up front
            uint32_t vh4[4][4];
#pragma unroll
            for (int nb = 0; nb < 4; ++nb) {
                uint32_t addr = sb + FOFF_VH + (ks * 16 + (lane & 15)) * FK_STRB
                                + (wc * 64 + nb * 16 + (lane >> 4) * 8) * 2;
                ldsm_x4_trans(vh4[nb][0], vh4[nb][1], vh4[nb][2], vh4[nb][3], addr);
            }
            // pass 0: P_hi x V_hi
#pragma unroll
            for (int nb = 0; nb < 4; ++nb) {
                mma_bf16(o[2*nb],   ap, vh4[nb][0], vh4[nb][1]);
                mma_bf16(o[2*nb+1], ap, vh4[nb][2], vh4[nb][3]);
            }
            // pass 1: P_hi x V_lo (load V_lo inline)
#pragma unroll
            for (int nb = 0; nb < 4; ++nb) {
                uint32_t addr = sb + FOFF_VL + (ks * 16 + (lane & 15)) * FK_STRB
                                + (wc * 64 + nb * 16 + (lane >> 4) * 8) * 2;
                uint32_t vl0, vl1, vl2, vl3;
                ldsm_x4_trans(vl0, vl1, vl2, vl3, addr);
                mma_bf16(o[2*nb],   ap, vl0, vl1);
                mma_bf16(o[2*nb+1], ap, vl2, vl3);
            }
            // pass 2: P_lo x V_hi
#pragma unroll
            for (int nb = 0; nb < 4; ++nb) {
                mma_bf16(o[2*nb],   apl, vh4[nb][0], vh4[nb][1]);
                mma_bf16(o[2*nb+1], apl, vh4[nb][2], vh4[nb][3]);
            }
        }
        __syncthreads();   // protect K/V/P tiles before next iteration
    }

    // Epilogue: normalize by 1/l, write bf16 hi/lo (b,t,h,d)
    {
        float li0 = 1.0f / lrow[wr * 16 + frow];
        float li1 = 1.0f / lrow[wr * 16 + frow + 8];
        int r0g = b * TT + qt * 64 + wr * 16 + frow;
#pragma unroll
        for (int nt = 0; nt < 8; ++nt) {
            int c = wc * 64 + nt * 8 + fcol;
            size_t o0 = (size_t)r0g * (HH*HD) + h * HD + c;
            size_t o1 = (size_t)(r0g + 8) * (HH*HD) + h * HD + c;
            float v00 = o[nt][0] * li0, v01 = o[nt][1] * li0;
            float v10 = o[nt][2] * li1, v11 = o[nt][3] * li1;
            __nv_bfloat16 h00 = __float2bfloat16(v00);
            __nv_bfloat16 h01 = __float2bfloat16(v01);
            __nv_bfloat16 h10 = __float2bfloat16(v10);
            __nv_bfloat16 h11 = __float2bfloat16(v11);
            Ohi[o0] = h00; Ohi[o0 + 1] = h01;
            Ohi[o1] = h10; Ohi[o1 + 1] = h11;
            Olo[o0]     = __float2bfloat16(v00 - __bfloat162float(h00));
            Olo[o0 + 1] = __float2bfloat16(v01 - __bfloat162float(h01));
            Olo[o1]     = __float2bfloat16(v10 - __bfloat162float(h10));
            Olo[o1 + 1] = __float2bfloat16(v11 - __bfloat162float(h11));
        }
    }
}

// ---------------------------------------------------------------------------
extern "C" void kernel_launch(void* const* d_in, const int* in_sizes, int n_in,
                              void* d_out, int out_size) {
    const float* x    = (const float*)d_in[0];
    const float* Wq   = (const float*)d_in[1];
    const float* Wk   = (const float*)d_in[2];
    const float* Wv   = (const float*)d_in[3];
    const float* Wo   = (const float*)d_in[4];
    const float* qn   = (const float*)d_in[5];
    const float* kn   = (const float*)d_in[6];
    const float* sinp = (const float*)d_in[7];
    const float* cosp = (const float*)d_in[8];
    float* out = (float*)d_out;

    __nv_bfloat16 *xhi, *xlo, *wqh, *wql, *wkh, *wkl, *wvh, *wvl, *woh, *wol;
    __nv_bfloat16 *qhi, *qlo, *khi, *klo, *vhi, *vlo, *ohi, *olo;
    float *qr, *kr, *vr;
    cudaGetSymbolAddress((void**)&xhi, g_xhi);
    cudaGetSymbolAddress((void**)&xlo, g_xlo);
    cudaGetSymbolAddress((void**)&wqh, g_wqt_hi);
    cudaGetSymbolAddress((void**)&wql, g_wqt_lo);
    cudaGetSymbolAddress((void**)&wkh, g_wkt_hi);
    cudaGetSymbolAddress((void**)&wkl, g_wkt_lo);
    cudaGetSymbolAddress((void**)&wvh, g_wvt_hi);
    cudaGetSymbolAddress((void**)&wvl, g_wvt_lo);
    cudaGetSymbolAddress((void**)&woh, g_wot_hi);
    cudaGetSymbolAddress((void**)&wol, g_wot_lo);
    cudaGetSymbolAddress((void**)&qr, g_q_raw);
    cudaGetSymbolAddress((void**)&kr, g_k_raw);
    cudaGetSymbolAddress((void**)&vr, g_v_raw);
    cudaGetSymbolAddress((void**)&qhi, g_qhi);
    cudaGetSymbolAddress((void**)&qlo, g_qlo);
    cudaGetSymbolAddress((void**)&khi, g_khi);
    cudaGetSymbolAddress((void**)&klo, g_klo);
    cudaGetSymbolAddress((void**)&vhi, g_vhi);
    cudaGetSymbolAddress((void**)&vlo, g_vlo);
    cudaGetSymbolAddress((void**)&ohi, g_ohi);
    cudaGetSymbolAddress((void**)&olo, g_olo);

    // 1. split-convert x
    convert_split_kernel<<<(MTOT * DD / 4 + 255) / 256, 256>>>(x, xhi, xlo, MTOT * DD / 4);

    // 2. transpose + split weights
    transpose_split_kernel<<<dim3((HH*HD)/32, DD/32), 256>>>(Wq, wqh, wql, DD, HH*HD);
    transpose_split_kernel<<<dim3((KK*HD)/32, DD/32), 256>>>(Wk, wkh, wkl, DD, KK*HD);
    transpose_split_kernel<<<dim3((KK*HD)/32, DD/32), 256>>>(Wv, wvh, wvl, DD, KK*HD);
    transpose_split_kernel<<<dim3((HH*HD)/32, (HH*HD)/32), 256>>>(Wo, woh, wol, HH*HD, HH*HD);

    // 3. fused QKV projection on tensor cores (one launch, 1024 CTAs)
    cudaFuncSetAttribute(gemm_qkv, cudaFuncAttributeMaxDynamicSharedMemorySize, GSMEM_DYN);
    gemm_qkv<<<dim3(32, MTOT/128), 256, GSMEM_DYN>>>(xhi, xlo, wqh, wql, wkh, wkl,
                                                     wvh, wvl, qr, kr, vr);

    // 4. RMSNorm + RoPE -> bf16 hi/lo q,k ; split-convert v
    normrope_kernel<<<12288, 256>>>(qr, kr, qhi, qlo, khi, klo, qn, kn, sinp, cosp);
    convert_split_kernel<<<(MTOT * KK * HD / 4 + 255) / 256, 256>>>(vr, vhi, vlo, MTOT * KK * HD / 4);

    // 5. causal flash attention on tensor cores
    cudaFuncSetAttribute(flash_mma, cudaFuncAttributeMaxDynamicSharedMemorySize, FA2_SMEM);
    flash_mma<<<dim3(TT / 64, BB * HH), 256, FA2_SMEM>>>(qhi, qlo, khi, klo, vhi, vlo, ohi, olo);

    // 6. output projection on tensor cores
    cudaFuncSetAttribute(gemm_mma, cudaFuncAttributeMaxDynamicSharedMemorySize, GSMEM_DYN);
    gemm_mma<<<dim3((HH*HD)/128, MTOT/128), 256, GSMEM_DYN>>>(ohi, olo, woh, wol, out, HH*HD, HH*HD);
}

// round 6
// speedup vs baseline: 3.6282x; 1.4446x over previous
#include <cuda_runtime.h>
#include <cuda_fp16.h>
#include <math.h>
#include <cstdint>

// Problem constants
#define BB 2
#define TT 2048
#define DD 2048
#define HH 16
#define KK 8
#define HD 128
#define MTOT (BB*TT)   // 4096

// ---------------------------------------------------------------------------
// Scratch (device globals; no allocation allowed)
// ---------------------------------------------------------------------------
__device__ __half g_xhi [(size_t)MTOT * DD];
__device__ __half g_xlo [(size_t)MTOT * DD];
__device__ __half g_wqt [(size_t)(HH*HD) * DD];
__device__ __half g_wkt [(size_t)(KK*HD) * DD];
__device__ __half g_wvt [(size_t)(KK*HD) * DD];
__device__ __half g_wot [(size_t)DD * (HH*HD)];
__device__ float g_q_raw[(size_t)MTOT * (HH*HD)];
__device__ float g_k_raw[(size_t)MTOT * (KK*HD)];
__device__ float g_v_raw[(size_t)MTOT * (KK*HD)];
__device__ __half g_qhi [(size_t)MTOT * (HH*HD)];
__device__ __half g_qlo [(size_t)MTOT * (HH*HD)];
__device__ __half g_khi [(size_t)MTOT * (KK*HD)];
__device__ __half g_vhi [(size_t)MTOT * (KK*HD)];
__device__ __half g_ohi [(size_t)MTOT * (HH*HD)];
__device__ __half g_olo [(size_t)MTOT * (HH*HD)];

// ---------------------------------------------------------------------------
// mma.sync helpers
// ---------------------------------------------------------------------------
__device__ __forceinline__ uint32_t smem_to_u32(const void* p) {
    uint32_t a;
    asm("{ .reg .u64 t; cvta.to.shared.u64 t, %1; cvt.u32.u64 %0, t; }"
        : "=r"(a) : "l"(p));
    return a;
}

__device__ __forceinline__ void ldsm_x4(uint32_t& r0, uint32_t& r1,
                                        uint32_t& r2, uint32_t& r3, uint32_t addr) {
    asm volatile("ldmatrix.sync.aligned.m8n8.x4.shared.b16 {%0,%1,%2,%3}, [%4];"
                 : "=r"(r0), "=r"(r1), "=r"(r2), "=r"(r3) : "r"(addr));
}

__device__ __forceinline__ void ldsm_x4_trans(uint32_t& r0, uint32_t& r1,
                                              uint32_t& r2, uint32_t& r3, uint32_t addr) {
    asm volatile("ldmatrix.sync.aligned.m8n8.x4.trans.shared.b16 {%0,%1,%2,%3}, [%4];"
                 : "=r"(r0), "=r"(r1), "=r"(r2), "=r"(r3) : "r"(addr));
}

__device__ __forceinline__ void mma_f16(float* d, const uint32_t* a,
                                        uint32_t b0, uint32_t b1) {
    asm volatile(
        "mma.sync.aligned.m16n8k16.row.col.f32.f16.f16.f32 "
        "{%0,%1,%2,%3}, {%4,%5,%6,%7}, {%8,%9}, {%0,%1,%2,%3};"
        : "+f"(d[0]), "+f"(d[1]), "+f"(d[2]), "+f"(d[3])
        : "r"(a[0]), "r"(a[1]), "r"(a[2]), "r"(a[3]), "r"(b0), "r"(b1));
}

// ---------------------------------------------------------------------------
// Conversion: fp32 -> (fp16 hi, fp16 lo)
// ---------------------------------------------------------------------------
__global__ __launch_bounds__(256)
void convert_split_kernel(const float* __restrict__ X,
                          __half* __restrict__ Hi,
                          __half* __restrict__ Lo, int n4) {
    int i = blockIdx.x * 256 + threadIdx.x;
    if (i >= n4) return;
    float4 v = ((const float4*)X)[i];
    __half h0 = __float2half_rn(v.x), h1 = __float2half_rn(v.y);
    __half h2 = __float2half_rn(v.z), h3 = __float2half_rn(v.w);
    __half l0 = __float2half_rn(v.x - __half2float(h0));
    __half l1 = __float2half_rn(v.y - __half2float(h1));
    __half l2 = __float2half_rn(v.z - __half2float(h2));
    __half l3 = __float2half_rn(v.w - __half2float(h3));
    __half2* hp = (__half2*)(Hi + 4 * (size_t)i);
    __half2* lp = (__half2*)(Lo + 4 * (size_t)i);
    hp[0] = __halves2half2(h0, h1); hp[1] = __halves2half2(h2, h3);
    lp[0] = __halves2half2(l0, l1); lp[1] = __halves2half2(l2, l3);
}

// fp32 -> fp16 (hi only)
__global__ __launch_bounds__(256)
void convert_half_kernel(const float* __restrict__ X, __half* __restrict__ Hi, int n4) {
    int i = blockIdx.x * 256 + threadIdx.x;
    if (i >= n4) return;
    float4 v = ((const float4*)X)[i];
    __half2* hp = (__half2*)(Hi + 4 * (size_t)i);
    hp[0] = __halves2half2(__float2half_rn(v.x), __float2half_rn(v.y));
    hp[1] = __halves2half2(__float2half_rn(v.z), __float2half_rn(v.w));
}

// ---------------------------------------------------------------------------
// Transpose: W[Kd, N] fp32 -> T [N, Kd] fp16 (hi only)
// ---------------------------------------------------------------------------
__global__ __launch_bounds__(256)
void transpose_half_kernel(const float* __restrict__ W,
                           __half* __restrict__ Thi, int Kd, int N) {
    __shared__ float tile[32][33];
    int n0 = blockIdx.x * 32, k0 = blockIdx.y * 32;
    int tx = threadIdx.x & 31, ty = threadIdx.x >> 5;
#pragma unroll
    for (int r = ty; r < 32; r += 8)
        tile[r][tx] = W[(size_t)(k0 + r) * N + n0 + tx];
    __syncthreads();
#pragma unroll
    for (int r = ty; r < 32; r += 8)
        Thi[(size_t)(n0 + r) * Kd + k0 + tx] = __float2half_rn(tile[tx][r]);
}

// ---------------------------------------------------------------------------
// fp16 2-pass compensated GEMM: C[M,N] = (Ahi+Alo)[M,K] @ Bhi[N,K]^T
// 128x128 CTA tile, 8 warps, K-chunk 32, double-buffered SMEM.
// ---------------------------------------------------------------------------
#define GPAD 40
#define GTILE_BYTES (128 * GPAD * 2)      // 10240
#define GSTAGE_BYTES (3 * GTILE_BYTES)    // 30720 (Ahi, Alo, Bhi)
#define GSMEM_DYN (2 * GSTAGE_BYTES)      // 61440

__device__ __forceinline__ void gemm_core(
    const __half* __restrict__ Ahi, const __half* __restrict__ Alo,
    const __half* __restrict__ Bhi,
    float* __restrict__ C, int N, int Kd, int row0, int col0, char* smg) {
    const uint32_t sbase0 = smem_to_u32(smg);

    const int tid = threadIdx.x;
    const int lane = tid & 31;
    const int wid = tid >> 5;
    const int wr = wid & 3;
    const int wc = wid >> 2;

    float d[2][8][4];
#pragma unroll
    for (int m = 0; m < 2; ++m)
#pragma unroll
        for (int n = 0; n < 8; ++n)
#pragma unroll
            for (int j = 0; j < 4; ++j) d[m][n][j] = 0.0f;

    const __half* gb[3] = {Ahi, Alo, Bhi};
    int grow[6], gseg[6];
#pragma unroll
    for (int a = 0; a < 3; ++a) {
        int r0 = (a < 2) ? row0 : col0;
        int s0 = tid, s1 = tid + 256;
        grow[2*a]   = r0 + (s0 >> 2); gseg[2*a]   = s0 & 3;
        grow[2*a+1] = r0 + (s1 >> 2); gseg[2*a+1] = s1 & 3;
    }

    uint4 pf[6];
    auto ldg_chunk = [&](int k0) {
#pragma unroll
        for (int a = 0; a < 3; ++a) {
#pragma unroll
            for (int j = 0; j < 2; ++j) {
                int e = 2 * a + j;
                pf[e] = *(const uint4*)(gb[a] + (size_t)grow[e] * Kd + k0 + gseg[e] * 8);
            }
        }
    };
    auto sts_chunk = [&](int buf) {
        char* st = smg + buf * GSTAGE_BYTES;
#pragma unroll
        for (int a = 0; a < 3; ++a) {
#pragma unroll
            for (int j = 0; j < 2; ++j) {
                int e = 2 * a + j;
                int s = tid + j * 256;
                *(uint4*)(st + a * GTILE_BYTES + (s >> 2) * (GPAD*2) + (s & 3) * 16) = pf[e];
            }
        }
    };

    const int NC = Kd / 32;

    ldg_chunk(0);
    sts_chunk(0);
    __syncthreads();

    for (int c = 0; c < NC; ++c) {
        const int cur = c & 1;
        const uint32_t sb = sbase0 + cur * GSTAGE_BYTES;

        if (c + 1 < NC) ldg_chunk((c + 1) * 32);

#pragma unroll
        for (int ks = 0; ks < 2; ++ks) {
            const uint32_t coff = ks * 32 + (lane >> 4) * 16;
            uint32_t ah[2][4], al[2][4];
#pragma unroll
            for (int mb = 0; mb < 2; ++mb) {
                uint32_t addr = sb + (wr * 32 + mb * 16 + (lane & 15)) * (GPAD*2) + coff;
                ldsm_x4(ah[mb][0], ah[mb][1], ah[mb][2], ah[mb][3], addr);
                ldsm_x4(al[mb][0], al[mb][1], al[mb][2], al[mb][3], addr + GTILE_BYTES);
            }
            uint32_t bh[4][4];
#pragma unroll
            for (int nb = 0; nb < 4; ++nb) {
                uint32_t addr = sb + 2 * GTILE_BYTES +
                                (wc * 64 + nb * 16 + (lane & 15)) * (GPAD*2) + coff;
                ldsm_x4(bh[nb][0], bh[nb][1], bh[nb][2], bh[nb][3], addr);
            }
            // pass-major: hh then lh
#pragma unroll
            for (int pass = 0; pass < 2; ++pass) {
#pragma unroll
                for (int mb = 0; mb < 2; ++mb) {
#pragma unroll
                    for (int nb = 0; nb < 4; ++nb) {
                        const uint32_t* a = pass ? al[mb] : ah[mb];
                        mma_f16(d[mb][2*nb],   a, bh[nb][0], bh[nb][2]);
                        mma_f16(d[mb][2*nb+1], a, bh[nb][1], bh[nb][3]);
                    }
                }
            }
        }

        if (c + 1 < NC) sts_chunk(cur ^ 1);
        __syncthreads();
    }

    const int frow = lane >> 2;
    const int fcol = 2 * (lane & 3);
#pragma unroll
    for (int mb = 0; mb < 2; ++mb) {
#pragma unroll
        for (int nt = 0; nt < 8; ++nt) {
            int r = row0 + wr * 32 + mb * 16 + frow;
            int cc = col0 + wc * 64 + nt * 8 + fcol;
            *(float2*)&C[(size_t)r * N + cc]       = make_float2(d[mb][nt][0], d[mb][nt][1]);
            *(float2*)&C[(size_t)(r + 8) * N + cc] = make_float2(d[mb][nt][2], d[mb][nt][3]);
        }
    }
}

__global__ __launch_bounds__(256, 1)
void gemm_mma(const __half* __restrict__ Ahi, const __half* __restrict__ Alo,
              const __half* __restrict__ Bhi,
              float* __restrict__ C, int N, int Kd) {
    extern __shared__ char smg[];
    gemm_core(Ahi, Alo, Bhi, C, N, Kd, blockIdx.y * 128, blockIdx.x * 128, smg);
}

// Fused QKV GEMM: col-tiles 0-15 -> Wq/qr, 16-23 -> Wk/kr, 24-31 -> Wv/vr
__global__ __launch_bounds__(256, 1)
void gemm_qkv(const __half* __restrict__ Xhi, const __half* __restrict__ Xlo,
              const __half* __restrict__ Wq, const __half* __restrict__ Wk,
              const __half* __restrict__ Wv,
              float* __restrict__ Q, float* __restrict__ Kc, float* __restrict__ V) {
    extern __shared__ char smg[];
    int ct = blockIdx.x;
    const __half* bh;
    float* C;
    int N, col0;
    if (ct < 16)      { bh = Wq; C = Q;  N = HH*HD; col0 = ct * 128; }
    else if (ct < 24) { bh = Wk; C = Kc; N = KK*HD; col0 = (ct - 16) * 128; }
    else              { bh = Wv; C = V;  N = KK*HD; col0 = (ct - 24) * 128; }
    gemm_core(Xhi, Xlo, bh, C, N, DD, blockIdx.y * 128, col0, smg);
}

// ---------------------------------------------------------------------------
// Fused RMSNorm + RoPE. q -> fp16 hi/lo (unscaled); k -> fp16 hi only.
// ---------------------------------------------------------------------------
__global__ __launch_bounds__(256)
void normrope_kernel(const float* __restrict__ q, const float* __restrict__ k,
                     __half* __restrict__ Qhi, __half* __restrict__ Qlo,
                     __half* __restrict__ Khi,
                     const float* __restrict__ qn, const float* __restrict__ kn,
                     const float* __restrict__ sinp, const float* __restrict__ cosp) {
    int warp = (blockIdx.x * blockDim.x + threadIdx.x) >> 5;
    int lane = threadIdx.x & 31;
    const int NQ = MTOT * HH;
    const int NTOT = NQ + MTOT * KK;
    if (warp >= NTOT) return;

    const float* ptr;
    const float* w;
    int t;
    bool isq = warp < NQ;
    size_t off;
    if (isq) {
        int bt = warp >> 4;
        int h = warp & 15;
        off = (size_t)bt * (HH * HD) + h * HD;
        ptr = q + off;
        w = qn;
        t = bt & (TT - 1);
    } else {
        int v2 = warp - NQ;
        int bt = v2 >> 3;
        int kh = v2 & 7;
        off = (size_t)bt * (KK * HD) + kh * HD;
        ptr = k + off;
        w = kn;
        t = bt & (TT - 1);
    }

    float2 a  = *(const float2*)(ptr + 2 * lane);
    float2 b2 = *(const float2*)(ptr + 64 + 2 * lane);

    float ss = a.x * a.x + a.y * a.y + b2.x * b2.x + b2.y * b2.y;
#pragma unroll
    for (int o = 16; o; o >>= 1) ss += __shfl_xor_sync(0xFFFFFFFFu, ss, o);
    float rinv = rsqrtf(ss * (1.0f / 128.0f) + 1e-6f);

    float w0 = w[2 * lane], w1 = w[2 * lane + 1];
    float w2 = w[64 + 2 * lane], w3 = w[65 + 2 * lane];
    float n0 = a.x * rinv * w0, n1 = a.y * rinv * w1;
    float n2 = b2.x * rinv * w2, n3 = b2.y * rinv * w3;

    float s0 = sinp[t * 64 + lane],      c0 = cosp[t * 64 + lane];
    float s1 = sinp[t * 64 + lane + 32], c1 = cosp[t * 64 + lane + 32];
    float o0 = n0 * c0 - n1 * s0;
    float o1 = n2 * c1 - n3 * s1;
    float o2 = n0 * s0 + n1 * c0;
    float o3 = n2 * s1 + n3 * c1;

    if (isq) {
        __half h0 = __float2half_rn(o0);
        __half h1 = __float2half_rn(o1);
        __half h2 = __float2half_rn(o2);
        __half h3 = __float2half_rn(o3);
        __half* dhi = Qhi + off;
        __half* dlo = Qlo + off;
        dhi[lane]      = h0;  dlo[lane]      = __float2half_rn(o0 - __half2float(h0));
        dhi[lane + 32] = h1;  dlo[lane + 32] = __float2half_rn(o1 - __half2float(h1));
        dhi[lane + 64] = h2;  dlo[lane + 64] = __float2half_rn(o2 - __half2float(h2));
        dhi[lane + 96] = h3;  dlo[lane + 96] = __float2half_rn(o3 - __half2float(h3));
    } else {
        __half* dhi = Khi + off;
        dhi[lane]      = __float2half_rn(o0);
        dhi[lane + 32] = __float2half_rn(o1);
        dhi[lane + 64] = __float2half_rn(o2);
        dhi[lane + 96] = __float2half_rn(o3);
    }
}

// ---------------------------------------------------------------------------
// Flash attention on tensor cores, fp16 2-pass compensated.
// S: (Qhi+Qlo)@Khi^T, scale folded at store. PV: (Phi+Plo)@Vhi.
// ---------------------------------------------------------------------------
#define FK_STRB 272          // bytes per row of 128-wide fp16 tile (136 halves)
#define FP_STRB 144          // bytes per row of P tile
#define FTILE (64 * FK_STRB) // 17408

#define FOFF_QH 0
#define FOFF_QL (FOFF_QH + FTILE)
#define FOFF_KH (FOFF_QL + FTILE)
#define FOFF_VH (FOFF_KH + FTILE)
#define FOFF_PH (FOFF_VH + FTILE)
#define FOFF_PL (FOFF_PH + 64 * FP_STRB)
#define FOFF_S  (FOFF_PL + 64 * FP_STRB)
#define FOFF_ST (FOFF_S + 64 * 68 * 4)
#define FA2_SMEM (FOFF_ST + 3 * 64 * 4)   // ~105 KB -> 2 CTAs/SM

__global__ __launch_bounds__(256, 2)
void flash_mma(const __half* __restrict__ Qhi, const __half* __restrict__ Qlo,
               const __half* __restrict__ Khi, const __half* __restrict__ Vhi,
               __half* __restrict__ Ohi, __half* __restrict__ Olo) {
    extern __shared__ char sm[];
    const uint32_t sb = smem_to_u32(sm);

    float* Sb   = (float*)(sm + FOFF_S);
    float* mrow = (float*)(sm + FOFF_ST);
    float* lrow = mrow + 64;
    float* arow = lrow + 64;

    const int qt = blockIdx.x;
    const int bh = blockIdx.y;
    const int b = bh >> 4;
    const int h = bh & 15;
    const int kh = h >> 1;

    const int tid = threadIdx.x;
    const int lane = tid & 31;
    const int wid = tid >> 5;
    const int wr = wid & 3;
    const int wc = wid >> 2;
    const int frow = lane >> 2;
    const int fcol = 2 * (lane & 3);
    const float scale = 0.08838834764831845f;  // 1/sqrt(128)

    // Load Q tile (hi/lo)
    {
        const __half* qh = Qhi + ((size_t)(b * TT + qt * 64)) * (HH*HD) + h * HD;
        const __half* ql = Qlo + ((size_t)(b * TT + qt * 64)) * (HH*HD) + h * HD;
        for (int i = tid; i < 64 * 16; i += 256) {
            int r = i >> 4, s = i & 15;
            *(uint4*)(sm + FOFF_QH + r * FK_STRB + s * 16) = *(const uint4*)(qh + (size_t)r * (HH*HD) + s * 8);
            *(uint4*)(sm + FOFF_QL + r * FK_STRB + s * 16) = *(const uint4*)(ql + (size_t)r * (HH*HD) + s * 8);
        }
    }
    if (tid < 64) { mrow[tid] = -INFINITY; lrow[tid] = 0.0f; }

    float o[8][4];
#pragma unroll
    for (int n = 0; n < 8; ++n)
#pragma unroll
        for (int j = 0; j < 4; ++j) o[n][j] = 0.0f;

    __syncthreads();

    for (int kt = 0; kt <= qt; ++kt) {
        // Load K/V tiles (hi only)
        {
            size_t base = ((size_t)(b * TT + kt * 64)) * (KK*HD) + kh * HD;
            for (int i = tid; i < 64 * 16; i += 256) {
                int r = i >> 4, s = i & 15;
                size_t g = base + (size_t)r * (KK*HD) + s * 8;
                *(uint4*)(sm + FOFF_KH + r * FK_STRB + s * 16) = *(const uint4*)(Khi + g);
                *(uint4*)(sm + FOFF_VH + r * FK_STRB + s * 16) = *(const uint4*)(Vhi + g);
            }
        }
        __syncthreads();

        // ---- S = Q @ K^T (2-pass: Qhi + Qlo vs Khi) ----
        float s[4][4];
#pragma unroll
        for (int i = 0; i < 4; ++i)
#pragma unroll
            for (int j = 0; j < 4; ++j) s[i][j] = 0.0f;

#pragma unroll
        for (int ks = 0; ks < 8; ++ks) {
            const uint32_t coff = ks * 32 + (lane >> 4) * 16;
            uint32_t aq[4], aql[4];
            {
                uint32_t addr = sb + FOFF_QH + (wr * 16 + (lane & 15)) * FK_STRB + coff;
                ldsm_x4(aq[0], aq[1], aq[2], aq[3], addr);
                ldsm_x4(aql[0], aql[1], aql[2], aql[3], addr + FTILE);
            }
            uint32_t kb[2][4];
#pragma unroll
            for (int nb = 0; nb < 2; ++nb) {
                uint32_t addr = sb + FOFF_KH + (wc * 32 + nb * 16 + (lane & 15)) * FK_STRB + coff;
                ldsm_x4(kb[nb][0], kb[nb][1], kb[nb][2], kb[nb][3], addr);
            }
#pragma unroll
            for (int pass = 0; pass < 2; ++pass) {
#pragma unroll
                for (int nb = 0; nb < 2; ++nb) {
                    const uint32_t* a = pass ? aql : aq;
                    mma_f16(s[2*nb],   a, kb[nb][0], kb[nb][2]);
                    mma_f16(s[2*nb+1], a, kb[nb][1], kb[nb][3]);
                }
            }
        }

        // Store S (scaled) with causal mask (diag tile only)
        bool diag = (kt == qt);
#pragma unroll
        for (int nt = 0; nt < 4; ++nt) {
            int r = wr * 16 + frow;
            int c = wc * 32 + nt * 8 + fcol;
            float v0 = s[nt][0] * scale, v1 = s[nt][1] * scale;
            float v2 = s[nt][2] * scale, v3 = s[nt][3] * scale;
            if (diag) {
                if (c     > r)     v0 = -1e30f;
                if (c + 1 > r)     v1 = -1e30f;
                if (c     > r + 8) v2 = -1e30f;
                if (c + 1 > r + 8) v3 = -1e30f;
            }
            Sb[r * 68 + c] = v0;       Sb[r * 68 + c + 1] = v1;
            Sb[(r+8) * 68 + c] = v2;   Sb[(r+8) * 68 + c + 1] = v3;
        }
        __syncthreads();

        // ---- fused online softmax + P hi/lo split (4 threads per row) ----
        {
            int r = tid >> 2;
            int quarter = tid & 3;
            int c0 = quarter * 16;
            const float* row = &Sb[r * 68 + c0];
            float mx = -INFINITY;
#pragma unroll
            for (int j = 0; j < 16; ++j) mx = fmaxf(mx, row[j]);
            mx = fmaxf(mx, __shfl_xor_sync(0xFFFFFFFFu, mx, 1));
            mx = fmaxf(mx, __shfl_xor_sync(0xFFFFFFFFu, mx, 2));
            float m_old = mrow[r];
            mx = fmaxf(mx, m_old);
            float a = __expf(m_old - mx);
            float sum = 0.0f;
            __half* ph = (__half*)(sm + FOFF_PH + r * FP_STRB) + c0;
            __half* pl = (__half*)(sm + FOFF_PL + r * FP_STRB) + c0;
#pragma unroll
            for (int j = 0; j < 16; ++j) {
                float p = __expf(row[j] - mx);
                sum += p;
                __half hi = __float2half_rn(p);
                ph[j] = hi;
                pl[j] = __float2half_rn(p - __half2float(hi));
            }
            sum += __shfl_xor_sync(0xFFFFFFFFu, sum, 1);
            sum += __shfl_xor_sync(0xFFFFFFFFu, sum, 2);
            if (quarter == 0) {
                lrow[r] = lrow[r] * a + sum;
                mrow[r] = mx;
                arow[r] = a;
            }
        }
        __syncthreads();

        // ---- rescale O, then O += (Phi+Plo) @ Vhi ----
        {
            float a0 = arow[wr * 16 + frow];
            float a1 = arow[wr * 16 + frow + 8];
#pragma unroll
            for (int nt = 0; nt < 8; ++nt) {
                o[nt][0] *= a0; o[nt][1] *= a0;
                o[nt][2] *= a1; o[nt][3] *= a1;
            }
        }

#pragma unroll
        for (int ks = 0; ks < 4; ++ks) {
            uint32_t ap[4], apl[4];
            {
                uint32_t addr = sb + FOFF_PH + (wr * 16 + (lane & 15)) * FP_STRB
                                + ks * 32 + (lane >> 4) * 16;
                ldsm_x4(ap[0], ap[1], ap[2], ap[3], addr);
                ldsm_x4(apl[0], apl[1], apl[2], apl[3], addr + 64 * FP_STRB);
            }
            uint32_t vh4[4][4];
#pragma unroll
            for (int nb = 0; nb < 4; ++nb) {
                uint32_t addr = sb + FOFF_VH + (ks * 16 + (lane & 15)) * FK_STRB
                                + (wc * 64 + nb * 16 + (lane >> 4) * 8) * 2;
                ldsm_x4_trans(vh4[nb][0], vh4[nb][1], vh4[nb][2], vh4[nb][3], addr);
            }
            // pass 0: P_hi x V_hi
#pragma unroll
            for (int nb = 0; nb < 4; ++nb) {
                mma_f16(o[2*nb],   ap, vh4[nb][0], vh4[nb][1]);
                mma_f16(o[2*nb+1], ap, vh4[nb][2], vh4[nb][3]);
            }
            // pass 1: P_lo x V_hi
#pragma unroll
            for (int nb = 0; nb < 4; ++nb) {
                mma_f16(o[2*nb],   apl, vh4[nb][0], vh4[nb][1]);
                mma_f16(o[2*nb+1], apl, vh4[nb][2], vh4[nb][3]);
            }
        }
        __syncthreads();   // protect K/V/P tiles before next iteration
    }

    // Epilogue: normalize by 1/l, write fp16 hi/lo (b,t,h,d)
    {
        float li0 = 1.0f / lrow[wr * 16 + frow];
        float li1 = 1.0f / lrow[wr * 16 + frow + 8];
        int r0g = b * TT + qt * 64 + wr * 16 + frow;
#pragma unroll
        for (int nt = 0; nt < 8; ++nt) {
            int c = wc * 64 + nt * 8 + fcol;
            size_t o0 = (size_t)r0g * (HH*HD) + h * HD + c;
            size_t o1 = (size_t)(r0g + 8) * (HH*HD) + h * HD + c;
            float v00 = o[nt][0] * li0, v01 = o[nt][1] * li0;
            float v10 = o[nt][2] * li1, v11 = o[nt][3] * li1;
            __half h00 = __float2half_rn(v00);
            __half h01 = __float2half_rn(v01);
            __half h10 = __float2half_rn(v10);
            __half h11 = __float2half_rn(v11);
            Ohi[o0] = h00; Ohi[o0 + 1] = h01;
            Ohi[o1] = h10; Ohi[o1 + 1] = h11;
            Olo[o0]     = __float2half_rn(v00 - __half2float(h00));
            Olo[o0 + 1] = __float2half_rn(v01 - __half2float(h01));
            Olo[o1]     = __float2half_rn(v10 - __half2float(h10));
            Olo[o1 + 1] = __float2half_rn(v11 - __half2float(h11));
        }
    }
}

// ---------------------------------------------------------------------------
extern "C" void kernel_launch(void* const* d_in, const int* in_sizes, int n_in,
                              void* d_out, int out_size) {
    const float* x    = (const float*)d_in[0];
    const float* Wq   = (const float*)d_in[1];
    const float* Wk   = (const float*)d_in[2];
    const float* Wv   = (const float*)d_in[3];
    const float* Wo   = (const float*)d_in[4];
    const float* qn   = (const float*)d_in[5];
    const float* kn   = (const float*)d_in[6];
    const float* sinp = (const float*)d_in[7];
    const float* cosp = (const float*)d_in[8];
    float* out = (float*)d_out;

    __half *xhi, *xlo, *wqt, *wkt, *wvt, *wot;
    __half *qhi, *qlo, *khi, *vhi, *ohi, *olo;
    float *qr, *kr, *vr;
    cudaGetSymbolAddress((void**)&xhi, g_xhi);
    cudaGetSymbolAddress((void**)&xlo, g_xlo);
    cudaGetSymbolAddress((void**)&wqt, g_wqt);
    cudaGetSymbolAddress((void**)&wkt, g_wkt);
    cudaGetSymbolAddress((void**)&wvt, g_wvt);
    cudaGetSymbolAddress((void**)&wot, g_wot);
    cudaGetSymbolAddress((void**)&qr, g_q_raw);
    cudaGetSymbolAddress((void**)&kr, g_k_raw);
    cudaGetSymbolAddress((void**)&vr, g_v_raw);
    cudaGetSymbolAddress((void**)&qhi, g_qhi);
    cudaGetSymbolAddress((void**)&qlo, g_qlo);
    cudaGetSymbolAddress((void**)&khi, g_khi);
    cudaGetSymbolAddress((void**)&vhi, g_vhi);
    cudaGetSymbolAddress((void**)&ohi, g_ohi);
    cudaGetSymbolAddress((void**)&olo, g_olo);

    // 1. split-convert x
    convert_split_kernel<<<(MTOT * DD / 4 + 255) / 256, 256>>>(x, xhi, xlo, MTOT * DD / 4);

    // 2. transpose weights to fp16 (hi only)
    transpose_half_kernel<<<dim3((HH*HD)/32, DD/32), 256>>>(Wq, wqt, DD, HH*HD);
    transpose_half_kernel<<<dim3((KK*HD)/32, DD/32), 256>>>(Wk, wkt, DD, KK*HD);
    transpose_half_kernel<<<dim3((KK*HD)/32, DD/32), 256>>>(Wv, wvt, DD, KK*HD);
    transpose_half_kernel<<<dim3((HH*HD)/32, (HH*HD)/32), 256>>>(Wo, wot, HH*HD, HH*HD);

    // 3. fused QKV projection (fp16 2-pass)
    cudaFuncSetAttribute(gemm_qkv, cudaFuncAttributeMaxDynamicSharedMemorySize, GSMEM_DYN);
    gemm_qkv<<<dim3(32, MTOT/128), 256, GSMEM_DYN>>>(xhi, xlo, wqt, wkt, wvt, qr, kr, vr);

    // 4. RMSNorm + RoPE -> q hi/lo, k hi ; convert v -> hi
    normrope_kernel<<<12288, 256>>>(qr, kr, qhi, qlo, khi, qn, kn, sinp, cosp);
    convert_half_kernel<<<(MTOT * KK * HD / 4 + 255) / 256, 256>>>(vr, vhi, MTOT * KK * HD / 4);

    // 5. causal flash attention (fp16 2-pass)
    cudaFuncSetAttribute(flash_mma, cudaFuncAttributeMaxDynamicSharedMemorySize, FA2_SMEM);
    flash_mma<<<dim3(TT / 64, BB * HH), 256, FA2_SMEM>>>(qhi, qlo, khi, vhi, ohi, olo);

    // 6. output projection (fp16 2-pass)
    cudaFuncSetAttribute(gemm_mma, cudaFuncAttributeMaxDynamicSharedMemorySize, GSMEM_DYN);
    gemm_mma<<<dim3((HH*HD)/128, MTOT/128), 256, GSMEM_DYN>>>(ohi, olo, wot, out, HH*HD, HH*HD);
}

// round 7
// speedup vs baseline: 3.8373x; 1.0576x over previous
#include <cuda_runtime.h>
#include <cuda_fp16.h>
#include <math.h>
#include <cstdint>

// Problem constants
#define BB 2
#define TT 2048
#define DD 2048
#define HH 16
#define KK 8
#define HD 128
#define MTOT (BB*TT)   // 4096

// ---------------------------------------------------------------------------
// Scratch (device globals; no allocation allowed)
// ---------------------------------------------------------------------------
__device__ __half g_xhi [(size_t)MTOT * DD];
__device__ __half g_xlo [(size_t)MTOT * DD];
__device__ __half g_wqt [(size_t)(HH*HD) * DD];
__device__ __half g_wkt [(size_t)(KK*HD) * DD];
__device__ __half g_wvt [(size_t)(KK*HD) * DD];
__device__ __half g_wot [(size_t)DD * (HH*HD)];
__device__ float g_q_raw[(size_t)MTOT * (HH*HD)];
__device__ float g_k_raw[(size_t)MTOT * (KK*HD)];
__device__ __half g_qhi [(size_t)MTOT * (HH*HD)];
__device__ __half g_qlo [(size_t)MTOT * (HH*HD)];
__device__ __half g_khi [(size_t)MTOT * (KK*HD)];
__device__ __half g_vhi [(size_t)MTOT * (KK*HD)];
__device__ __half g_ohi [(size_t)MTOT * (HH*HD)];
__device__ __half g_olo [(size_t)MTOT * (HH*HD)];

// ---------------------------------------------------------------------------
// mma.sync / cp.async helpers
// ---------------------------------------------------------------------------
__device__ __forceinline__ uint32_t smem_to_u32(const void* p) {
    uint32_t a;
    asm("{ .reg .u64 t; cvta.to.shared.u64 t, %1; cvt.u32.u64 %0, t; }"
        : "=r"(a) : "l"(p));
    return a;
}

__device__ __forceinline__ void ldsm_x4(uint32_t& r0, uint32_t& r1,
                                        uint32_t& r2, uint32_t& r3, uint32_t addr) {
    asm volatile("ldmatrix.sync.aligned.m8n8.x4.shared.b16 {%0,%1,%2,%3}, [%4];"
                 : "=r"(r0), "=r"(r1), "=r"(r2), "=r"(r3) : "r"(addr));
}

__device__ __forceinline__ void ldsm_x4_trans(uint32_t& r0, uint32_t& r1,
                                              uint32_t& r2, uint32_t& r3, uint32_t addr) {
    asm volatile("ldmatrix.sync.aligned.m8n8.x4.trans.shared.b16 {%0,%1,%2,%3}, [%4];"
                 : "=r"(r0), "=r"(r1), "=r"(r2), "=r"(r3) : "r"(addr));
}

__device__ __forceinline__ void mma_f16(float* d, const uint32_t* a,
                                        uint32_t b0, uint32_t b1) {
    asm volatile(
        "mma.sync.aligned.m16n8k16.row.col.f32.f16.f16.f32 "
        "{%0,%1,%2,%3}, {%4,%5,%6,%7}, {%8,%9}, {%0,%1,%2,%3};"
        : "+f"(d[0]), "+f"(d[1]), "+f"(d[2]), "+f"(d[3])
        : "r"(a[0]), "r"(a[1]), "r"(a[2]), "r"(a[3]), "r"(b0), "r"(b1));
}

__device__ __forceinline__ void cp_async16(uint32_t saddr, const void* gaddr) {
    asm volatile("cp.async.cg.shared.global [%0], [%1], 16;"
                 :: "r"(saddr), "l"(gaddr) : "memory");
}
__device__ __forceinline__ void cp_commit() {
    asm volatile("cp.async.commit_group;" ::: "memory");
}

// ---------------------------------------------------------------------------
// Conversion: fp32 -> (fp16 hi, fp16 lo)
// ---------------------------------------------------------------------------
__global__ __launch_bounds__(256)
void convert_split_kernel(const float* __restrict__ X,
                          __half* __restrict__ Hi,
                          __half* __restrict__ Lo, int n4) {
    int i = blockIdx.x * 256 + threadIdx.x;
    if (i >= n4) return;
    float4 v = ((const float4*)X)[i];
    __half h0 = __float2half_rn(v.x), h1 = __float2half_rn(v.y);
    __half h2 = __float2half_rn(v.z), h3 = __float2half_rn(v.w);
    __half l0 = __float2half_rn(v.x - __half2float(h0));
    __half l1 = __float2half_rn(v.y - __half2float(h1));
    __half l2 = __float2half_rn(v.z - __half2float(h2));
    __half l3 = __float2half_rn(v.w - __half2float(h3));
    __half2* hp = (__half2*)(Hi + 4 * (size_t)i);
    __half2* lp = (__half2*)(Lo + 4 * (size_t)i);
    hp[0] = __halves2half2(h0, h1); hp[1] = __halves2half2(h2, h3);
    lp[0] = __halves2half2(l0, l1); lp[1] = __halves2half2(l2, l3);
}

// ---------------------------------------------------------------------------
// Transpose: W[Kd, N] fp32 -> T [N, Kd] fp16 (hi only)
// ---------------------------------------------------------------------------
__global__ __launch_bounds__(256)
void transpose_half_kernel(const float* __restrict__ W,
                           __half* __restrict__ Thi, int Kd, int N) {
    __shared__ float tile[32][33];
    int n0 = blockIdx.x * 32, k0 = blockIdx.y * 32;
    int tx = threadIdx.x & 31, ty = threadIdx.x >> 5;
#pragma unroll
    for (int r = ty; r < 32; r += 8)
        tile[r][tx] = W[(size_t)(k0 + r) * N + n0 + tx];
    __syncthreads();
#pragma unroll
    for (int r = ty; r < 32; r += 8)
        Thi[(size_t)(n0 + r) * Kd + k0 + tx] = __float2half_rn(tile[tx][r]);
}

// ---------------------------------------------------------------------------
// fp16 2-pass compensated GEMM with cp.async 3-stage pipeline.
// C[M,N] = (Ahi+Alo)[M,K] @ Bhi[N,K]^T ; output fp32 (C) or fp16 (Ch).
// 128x128 CTA tile, 8 warps, K-chunk 32, one barrier per chunk, 2 CTAs/SM.
// ---------------------------------------------------------------------------
#define GPAD 40
#define GTILE_BYTES (128 * GPAD * 2)      // 10240
#define GSTAGE_BYTES (3 * GTILE_BYTES)    // 30720 (Ahi, Alo, Bhi)
#define GSMEM_DYN (3 * GSTAGE_BYTES)      // 92160 (3 stages)

__device__ __forceinline__ void gemm_core(
    const __half* __restrict__ Ahi, const __half* __restrict__ Alo,
    const __half* __restrict__ Bhi,
    float* __restrict__ C, __half* __restrict__ Ch,
    int N, int Kd, int row0, int col0, char* smg) {
    const uint32_t sbase0 = smem_to_u32(smg);

    const int tid = threadIdx.x;
    const int lane = tid & 31;
    const int wid = tid >> 5;
    const int wr = wid & 3;
    const int wc = wid >> 2;

    float d[2][8][4];
#pragma unroll
    for (int m = 0; m < 2; ++m)
#pragma unroll
        for (int n = 0; n < 8; ++n)
#pragma unroll
            for (int j = 0; j < 4; ++j) d[m][n][j] = 0.0f;

    const __half* gb[3] = {Ahi, Alo, Bhi};
    int grow[6], gseg[6];
#pragma unroll
    for (int a = 0; a < 3; ++a) {
        int r0 = (a < 2) ? row0 : col0;
        int s0 = tid, s1 = tid + 256;
        grow[2*a]   = r0 + (s0 >> 2); gseg[2*a]   = s0 & 3;
        grow[2*a+1] = r0 + (s1 >> 2); gseg[2*a+1] = s1 & 3;
    }

    // cp.async one 32-wide K-chunk into stage
    auto cp_chunk = [&](int k0, int stage) {
        uint32_t st = sbase0 + stage * GSTAGE_BYTES;
#pragma unroll
        for (int a = 0; a < 3; ++a) {
#pragma unroll
            for (int j = 0; j < 2; ++j) {
                int e = 2 * a + j;
                int s = tid + j * 256;
                uint32_t sa = st + a * GTILE_BYTES + (s >> 2) * (GPAD*2) + (s & 3) * 16;
                cp_async16(sa, gb[a] + (size_t)grow[e] * Kd + k0 + gseg[e] * 8);
            }
        }
        cp_commit();
    };

    const int NC = Kd / 32;   // >= 2 always here

    cp_chunk(0, 0);
    cp_chunk(32, 1);

    for (int c = 0; c < NC; ++c) {
        // wait for chunk c (allow 1 newer group in flight if it exists)
        if (c + 1 < NC) asm volatile("cp.async.wait_group 1;" ::: "memory");
        else            asm volatile("cp.async.wait_group 0;" ::: "memory");
        __syncthreads();

        if (c + 2 < NC) cp_chunk((c + 2) * 32, (c + 2) % 3);

        const uint32_t sb = sbase0 + (c % 3) * GSTAGE_BYTES;
#pragma unroll
        for (int ks = 0; ks < 2; ++ks) {
            const uint32_t coff = ks * 32 + (lane >> 4) * 16;
            uint32_t ah[2][4], al[2][4];
#pragma unroll
            for (int mb = 0; mb < 2; ++mb) {
                uint32_t addr = sb + (wr * 32 + mb * 16 + (lane & 15)) * (GPAD*2) + coff;
                ldsm_x4(ah[mb][0], ah[mb][1], ah[mb][2], ah[mb][3], addr);
                ldsm_x4(al[mb][0], al[mb][1], al[mb][2], al[mb][3], addr + GTILE_BYTES);
            }
            uint32_t bh[4][4];
#pragma unroll
            for (int nb = 0; nb < 4; ++nb) {
                uint32_t addr = sb + 2 * GTILE_BYTES +
                                (wc * 64 + nb * 16 + (lane & 15)) * (GPAD*2) + coff;
                ldsm_x4(bh[nb][0], bh[nb][1], bh[nb][2], bh[nb][3], addr);
            }
#pragma unroll
            for (int pass = 0; pass < 2; ++pass) {
#pragma unroll
                for (int mb = 0; mb < 2; ++mb) {
#pragma unroll
                    for (int nb = 0; nb < 4; ++nb) {
                        const uint32_t* a = pass ? al[mb] : ah[mb];
                        mma_f16(d[mb][2*nb],   a, bh[nb][0], bh[nb][2]);
                        mma_f16(d[mb][2*nb+1], a, bh[nb][1], bh[nb][3]);
                    }
                }
            }
        }
    }

    const int frow = lane >> 2;
    const int fcol = 2 * (lane & 3);
#pragma unroll
    for (int mb = 0; mb < 2; ++mb) {
#pragma unroll
        for (int nt = 0; nt < 8; ++nt) {
            int r = row0 + wr * 32 + mb * 16 + frow;
            int cc = col0 + wc * 64 + nt * 8 + fcol;
            if (Ch) {
                *(__half2*)&Ch[(size_t)r * N + cc] =
                    __halves2half2(__float2half_rn(d[mb][nt][0]), __float2half_rn(d[mb][nt][1]));
                *(__half2*)&Ch[(size_t)(r + 8) * N + cc] =
                    __halves2half2(__float2half_rn(d[mb][nt][2]), __float2half_rn(d[mb][nt][3]));
            } else {
                *(float2*)&C[(size_t)r * N + cc]       = make_float2(d[mb][nt][0], d[mb][nt][1]);
                *(float2*)&C[(size_t)(r + 8) * N + cc] = make_float2(d[mb][nt][2], d[mb][nt][3]);
            }
        }
    }
}

__global__ __launch_bounds__(256, 2)
void gemm_mma(const __half* __restrict__ Ahi, const __half* __restrict__ Alo,
              const __half* __restrict__ Bhi,
              float* __restrict__ C, int N, int Kd) {
    extern __shared__ char smg[];
    gemm_core(Ahi, Alo, Bhi, C, nullptr, N, Kd, blockIdx.y * 128, blockIdx.x * 128, smg);
}

// Fused QKV GEMM: col-tiles 0-15 -> Wq/qr(f32), 16-23 -> Wk/kr(f32),
// 24-31 -> Wv -> vhi (fp16 direct, no norm/rope needed on V)
__global__ __launch_bounds__(256, 2)
void gemm_qkv(const __half* __restrict__ Xhi, const __half* __restrict__ Xlo,
              const __half* __restrict__ Wq, const __half* __restrict__ Wk,
              const __half* __restrict__ Wv,
              float* __restrict__ Q, float* __restrict__ Kc, __half* __restrict__ Vh) {
    extern __shared__ char smg[];
    int ct = blockIdx.x;
    if (ct < 16) {
        gemm_core(Xhi, Xlo, Wq, Q, nullptr, HH*HD, DD, blockIdx.y * 128, ct * 128, smg);
    } else if (ct < 24) {
        gemm_core(Xhi, Xlo, Wk, Kc, nullptr, KK*HD, DD, blockIdx.y * 128, (ct - 16) * 128, smg);
    } else {
        gemm_core(Xhi, Xlo, Wv, nullptr, Vh, KK*HD, DD, blockIdx.y * 128, (ct - 24) * 128, smg);
    }
}

// ---------------------------------------------------------------------------
// Fused RMSNorm + RoPE. q -> fp16 hi/lo (unscaled); k -> fp16 hi only.
// ---------------------------------------------------------------------------
__global__ __launch_bounds__(256)
void normrope_kernel(const float* __restrict__ q, const float* __restrict__ k,
                     __half* __restrict__ Qhi, __half* __restrict__ Qlo,
                     __half* __restrict__ Khi,
                     const float* __restrict__ qn, const float* __restrict__ kn,
                     const float* __restrict__ sinp, const float* __restrict__ cosp) {
    int warp = (blockIdx.x * blockDim.x + threadIdx.x) >> 5;
    int lane = threadIdx.x & 31;
    const int NQ = MTOT * HH;
    const int NTOT = NQ + MTOT * KK;
    if (warp >= NTOT) return;

    const float* ptr;
    const float* w;
    int t;
    bool isq = warp < NQ;
    size_t off;
    if (isq) {
        int bt = warp >> 4;
        int h = warp & 15;
        off = (size_t)bt * (HH * HD) + h * HD;
        ptr = q + off;
        w = qn;
        t = bt & (TT - 1);
    } else {
        int v2 = warp - NQ;
        int bt = v2 >> 3;
        int kh = v2 & 7;
        off = (size_t)bt * (KK * HD) + kh * HD;
        ptr = k + off;
        w = kn;
        t = bt & (TT - 1);
    }

    float2 a  = *(const float2*)(ptr + 2 * lane);
    float2 b2 = *(const float2*)(ptr + 64 + 2 * lane);

    float ss = a.x * a.x + a.y * a.y + b2.x * b2.x + b2.y * b2.y;
#pragma unroll
    for (int o = 16; o; o >>= 1) ss += __shfl_xor_sync(0xFFFFFFFFu, ss, o);
    float rinv = rsqrtf(ss * (1.0f / 128.0f) + 1e-6f);

    float w0 = w[2 * lane], w1 = w[2 * lane + 1];
    float w2 = w[64 + 2 * lane], w3 = w[65 + 2 * lane];
    float n0 = a.x * rinv * w0, n1 = a.y * rinv * w1;
    float n2 = b2.x * rinv * w2, n3 = b2.y * rinv * w3;

    float s0 = sinp[t * 64 + lane],      c0 = cosp[t * 64 + lane];
    float s1 = sinp[t * 64 + lane + 32], c1 = cosp[t * 64 + lane + 32];
    float o0 = n0 * c0 - n1 * s0;
    float o1 = n2 * c1 - n3 * s1;
    float o2 = n0 * s0 + n1 * c0;
    float o3 = n2 * s1 + n3 * c1;

    if (isq) {
        __half h0 = __float2half_rn(o0);
        __half h1 = __float2half_rn(o1);
        __half h2 = __float2half_rn(o2);
        __half h3 = __float2half_rn(o3);
        __half* dhi = Qhi + off;
        __half* dlo = Qlo + off;
        dhi[lane]      = h0;  dlo[lane]      = __float2half_rn(o0 - __half2float(h0));
        dhi[lane + 32] = h1;  dlo[lane + 32] = __float2half_rn(o1 - __half2float(h1));
        dhi[lane + 64] = h2;  dlo[lane + 64] = __float2half_rn(o2 - __half2float(h2));
        dhi[lane + 96] = h3;  dlo[lane + 96] = __float2half_rn(o3 - __half2float(h3));
    } else {
        __half* dhi = Khi + off;
        dhi[lane]      = __float2half_rn(o0);
        dhi[lane + 32] = __float2half_rn(o1);
        dhi[lane + 64] = __float2half_rn(o2);
        dhi[lane + 96] = __float2half_rn(o3);
    }
}

// ---------------------------------------------------------------------------
// Flash attention on tensor cores, fp16 2-pass compensated.
// Descending-qt scheduling for tail balance.
// ---------------------------------------------------------------------------
#define FK_STRB 272          // bytes per row of 128-wide fp16 tile (136 halves)
#define FP_STRB 144          // bytes per row of P tile
#define FTILE (64 * FK_STRB) // 17408

#define FOFF_QH 0
#define FOFF_QL (FOFF_QH + FTILE)
#define FOFF_KH (FOFF_QL + FTILE)
#define FOFF_VH (FOFF_KH + FTILE)
#define FOFF_PH (FOFF_VH + FTILE)
#define FOFF_PL (FOFF_PH + 64 * FP_STRB)
#define FOFF_S  (FOFF_PL + 64 * FP_STRB)
#define FOFF_ST (FOFF_S + 64 * 68 * 4)
#define FA2_SMEM (FOFF_ST + 3 * 64 * 4)   // ~105 KB -> 2 CTAs/SM

__global__ __launch_bounds__(256, 2)
void flash_mma(const __half* __restrict__ Qhi, const __half* __restrict__ Qlo,
               const __half* __restrict__ Khi, const __half* __restrict__ Vhi,
               __half* __restrict__ Ohi, __half* __restrict__ Olo) {
    extern __shared__ char sm[];
    const uint32_t sb = smem_to_u32(sm);

    float* Sb   = (float*)(sm + FOFF_S);
    float* mrow = (float*)(sm + FOFF_ST);
    float* lrow = mrow + 64;
    float* arow = lrow + 64;

    const int qt = gridDim.x - 1 - blockIdx.x;   // descending work order
    const int bh = blockIdx.y;
    const int b = bh >> 4;
    const int h = bh & 15;
    const int kh = h >> 1;

    const int tid = threadIdx.x;
    const int lane = tid & 31;
    const int wid = tid >> 5;
    const int wr = wid & 3;
    const int wc = wid >> 2;
    const int frow = lane >> 2;
    const int fcol = 2 * (lane & 3);
    const float scale = 0.08838834764831845f;  // 1/sqrt(128)

    // Load Q tile (hi/lo)
    {
        const __half* qh = Qhi + ((size_t)(b * TT + qt * 64)) * (HH*HD) + h * HD;
        const __half* ql = Qlo + ((size_t)(b * TT + qt * 64)) * (HH*HD) + h * HD;
        for (int i = tid; i < 64 * 16; i += 256) {
            int r = i >> 4, s = i & 15;
            *(uint4*)(sm + FOFF_QH + r * FK_STRB + s * 16) = *(const uint4*)(qh + (size_t)r * (HH*HD) + s * 8);
            *(uint4*)(sm + FOFF_QL + r * FK_STRB + s * 16) = *(const uint4*)(ql + (size_t)r * (HH*HD) + s * 8);
        }
    }
    if (tid < 64) { mrow[tid] = -INFINITY; lrow[tid] = 0.0f; }

    float o[8][4];
#pragma unroll
    for (int n = 0; n < 8; ++n)
#pragma unroll
        for (int j = 0; j < 4; ++j) o[n][j] = 0.0f;

    __syncthreads();

    for (int kt = 0; kt <= qt; ++kt) {
        // Load K/V tiles (hi only)
        {
            size_t base = ((size_t)(b * TT + kt * 64)) * (KK*HD) + kh * HD;
            for (int i = tid; i < 64 * 16; i += 256) {
                int r = i >> 4, s = i & 15;
                size_t g = base + (size_t)r * (KK*HD) + s * 8;
                *(uint4*)(sm + FOFF_KH + r * FK_STRB + s * 16) = *(const uint4*)(Khi + g);
                *(uint4*)(sm + FOFF_VH + r * FK_STRB + s * 16) = *(const uint4*)(Vhi + g);
            }
        }
        __syncthreads();

        // ---- S = Q @ K^T (2-pass: Qhi + Qlo vs Khi) ----
        float s[4][4];
#pragma unroll
        for (int i = 0; i < 4; ++i)
#pragma unroll
            for (int j = 0; j < 4; ++j) s[i][j] = 0.0f;

#pragma unroll
        for (int ks = 0; ks < 8; ++ks) {
            const uint32_t coff = ks * 32 + (lane >> 4) * 16;
            uint32_t aq[4], aql[4];
            {
                uint32_t addr = sb + FOFF_QH + (wr * 16 + (lane & 15)) * FK_STRB + coff;
                ldsm_x4(aq[0], aq[1], aq[2], aq[3], addr);
                ldsm_x4(aql[0], aql[1], aql[2], aql[3], addr + FTILE);
            }
            uint32_t kb[2][4];
#pragma unroll
            for (int nb = 0; nb < 2; ++nb) {
                uint32_t addr = sb + FOFF_KH + (wc * 32 + nb * 16 + (lane & 15)) * FK_STRB + coff;
                ldsm_x4(kb[nb][0], kb[nb][1], kb[nb][2], kb[nb][3], addr);
            }
#pragma unroll
            for (int pass = 0; pass < 2; ++pass) {
#pragma unroll
                for (int nb = 0; nb < 2; ++nb) {
                    const uint32_t* a = pass ? aql : aq;
                    mma_f16(s[2*nb],   a, kb[nb][0], kb[nb][2]);
                    mma_f16(s[2*nb+1], a, kb[nb][1], kb[nb][3]);
                }
            }
        }

        // Store S (scaled) with causal mask (diag tile only)
        bool diag = (kt == qt);
#pragma unroll
        for (int nt = 0; nt < 4; ++nt) {
            int r = wr * 16 + frow;
            int c = wc * 32 + nt * 8 + fcol;
            float v0 = s[nt][0] * scale, v1 = s[nt][1] * scale;
            float v2 = s[nt][2] * scale, v3 = s[nt][3] * scale;
            if (diag) {
                if (c     > r)     v0 = -1e30f;
                if (c + 1 > r)     v1 = -1e30f;
                if (c     > r + 8) v2 = -1e30f;
                if (c + 1 > r + 8) v3 = -1e30f;
            }
            Sb[r * 68 + c] = v0;       Sb[r * 68 + c + 1] = v1;
            Sb[(r+8) * 68 + c] = v2;   Sb[(r+8) * 68 + c + 1] = v3;
        }
        __syncthreads();

        // ---- fused online softmax + P hi/lo split (4 threads per row) ----
        {
            int r = tid >> 2;
            int quarter = tid & 3;
            int c0 = quarter * 16;
            const float* row = &Sb[r * 68 + c0];
            float mx = -INFINITY;
#pragma unroll
            for (int j = 0; j < 16; ++j) mx = fmaxf(mx, row[j]);
            mx = fmaxf(mx, __shfl_xor_sync(0xFFFFFFFFu, mx, 1));
            mx = fmaxf(mx, __shfl_xor_sync(0xFFFFFFFFu, mx, 2));
            float m_old = mrow[r];
            mx = fmaxf(mx, m_old);
            float a = __expf(m_old - mx);
            float sum = 0.0f;
            __half* ph = (__half*)(sm + FOFF_PH + r * FP_STRB) + c0;
            __half* pl = (__half*)(sm + FOFF_PL + r * FP_STRB) + c0;
#pragma unroll
            for (int j = 0; j < 16; ++j) {
                float p = __expf(row[j] - mx);
                sum += p;
                __half hi = __float2half_rn(p);
                ph[j] = hi;
                pl[j] = __float2half_rn(p - __half2float(hi));
            }
            sum += __shfl_xor_sync(0xFFFFFFFFu, sum, 1);
            sum += __shfl_xor_sync(0xFFFFFFFFu, sum, 2);
            if (quarter == 0) {
                lrow[r] = lrow[r] * a + sum;
                mrow[r] = mx;
                arow[r] = a;
            }
        }
        __syncthreads();

        // ---- rescale O, then O += (Phi+Plo) @ Vhi ----
        {
            float a0 = arow[wr * 16 + frow];
            float a1 = arow[wr * 16 + frow + 8];
#pragma unroll
            for (int nt = 0; nt < 8; ++nt) {
                o[nt][0] *= a0; o[nt][1] *= a0;
                o[nt][2] *= a1; o[nt][3] *= a1;
            }
        }

#pragma unroll
        for (int ks = 0; ks < 4; ++ks) {
            uint32_t ap[4], apl[4];
            {
                uint32_t addr = sb + FOFF_PH + (wr * 16 + (lane & 15)) * FP_STRB
                                + ks * 32 + (lane >> 4) * 16;
                ldsm_x4(ap[0], ap[1], ap[2], ap[3], addr);
                ldsm_x4(apl[0], apl[1], apl[2], apl[3], addr + 64 * FP_STRB);
            }
            uint32_t vh4[4][4];
#pragma unroll
            for (int nb = 0; nb < 4; ++nb) {
                uint32_t addr = sb + FOFF_VH + (ks * 16 + (lane & 15)) * FK_STRB
                                + (wc * 64 + nb * 16 + (lane >> 4) * 8) * 2;
                ldsm_x4_trans(vh4[nb][0], vh4[nb][1], vh4[nb][2], vh4[nb][3], addr);
            }
#pragma unroll
            for (int nb = 0; nb < 4; ++nb) {
                mma_f16(o[2*nb],   ap, vh4[nb][0], vh4[nb][1]);
                mma_f16(o[2*nb+1], ap, vh4[nb][2], vh4[nb][3]);
            }
#pragma unroll
            for (int nb = 0; nb < 4; ++nb) {
                mma_f16(o[2*nb],   apl, vh4[nb][0], vh4[nb][1]);
                mma_f16(o[2*nb+1], apl, vh4[nb][2], vh4[nb][3]);
            }
        }
        __syncthreads();   // protect K/V/P tiles before next iteration
    }

    // Epilogue: normalize by 1/l, write fp16 hi/lo (b,t,h,d)
    {
        float li0 = 1.0f / lrow[wr * 16 + frow];
        float li1 = 1.0f / lrow[wr * 16 + frow + 8];
        int r0g = b * TT + qt * 64 + wr * 16 + frow;
#pragma unroll
        for (int nt = 0; nt < 8; ++nt) {
            int c = wc * 64 + nt * 8 + fcol;
            size_t o0 = (size_t)r0g * (HH*HD) + h * HD + c;
            size_t o1 = (size_t)(r0g + 8) * (HH*HD) + h * HD + c;
            float v00 = o[nt][0] * li0, v01 = o[nt][1] * li0;
            float v10 = o[nt][2] * li1, v11 = o[nt][3] * li1;
            __half h00 = __float2half_rn(v00);
            __half h01 = __float2half_rn(v01);
            __half h10 = __float2half_rn(v10);
            __half h11 = __float2half_rn(v11);
            Ohi[o0] = h00; Ohi[o0 + 1] = h01;
            Ohi[o1] = h10; Ohi[o1 + 1] = h11;
            Olo[o0]     = __float2half_rn(v00 - __half2float(h00));
            Olo[o0 + 1] = __float2half_rn(v01 - __half2float(h01));
            Olo[o1]     = __float2half_rn(v10 - __half2float(h10));
            Olo[o1 + 1] = __float2half_rn(v11 - __half2float(h11));
        }
    }
}

// ---------------------------------------------------------------------------
extern "C" void kernel_launch(void* const* d_in, const int* in_sizes, int n_in,
                              void* d_out, int out_size) {
    const float* x    = (const float*)d_in[0];
    const float* Wq   = (const float*)d_in[1];
    const float* Wk   = (const float*)d_in[2];
    const float* Wv   = (const float*)d_in[3];
    const float* Wo   = (const float*)d_in[4];
    const float* qn   = (const float*)d_in[5];
    const float* kn   = (const float*)d_in[6];
    const float* sinp = (const float*)d_in[7];
    const float* cosp = (const float*)d_in[8];
    float* out = (float*)d_out;

    __half *xhi, *xlo, *wqt, *wkt, *wvt, *wot;
    __half *qhi, *qlo, *khi, *vhi, *ohi, *olo;
    float *qr, *kr;
    cudaGetSymbolAddress((void**)&xhi, g_xhi);
    cudaGetSymbolAddress((void**)&xlo, g_xlo);
    cudaGetSymbolAddress((void**)&wqt, g_wqt);
    cudaGetSymbolAddress((void**)&wkt, g_wkt);
    cudaGetSymbolAddress((void**)&wvt, g_wvt);
    cudaGetSymbolAddress((void**)&wot, g_wot);
    cudaGetSymbolAddress((void**)&qr, g_q_raw);
    cudaGetSymbolAddress((void**)&kr, g_k_raw);
    cudaGetSymbolAddress((void**)&qhi, g_qhi);
    cudaGetSymbolAddress((void**)&qlo, g_qlo);
    cudaGetSymbolAddress((void**)&khi, g_khi);
    cudaGetSymbolAddress((void**)&vhi, g_vhi);
    cudaGetSymbolAddress((void**)&ohi, g_ohi);
    cudaGetSymbolAddress((void**)&olo, g_olo);

    // 1. split-convert x
    convert_split_kernel<<<(MTOT * DD / 4 + 255) / 256, 256>>>(x, xhi, xlo, MTOT * DD / 4);

    // 2. transpose weights to fp16 (hi only)
    transpose_half_kernel<<<dim3((HH*HD)/32, DD/32), 256>>>(Wq, wqt, DD, HH*HD);
    transpose_half_kernel<<<dim3((KK*HD)/32, DD/32), 256>>>(Wk, wkt, DD, KK*HD);
    transpose_half_kernel<<<dim3((KK*HD)/32, DD/32), 256>>>(Wv, wvt, DD, KK*HD);
    transpose_half_kernel<<<dim3((HH*HD)/32, (HH*HD)/32), 256>>>(Wo, wot, HH*HD, HH*HD);

    // 3. fused QKV projection (fp16 2-pass, cp.async pipeline; V -> fp16 direct)
    cudaFuncSetAttribute(gemm_qkv, cudaFuncAttributeMaxDynamicSharedMemorySize, GSMEM_DYN);
    gemm_qkv<<<dim3(32, MTOT/128), 256, GSMEM_DYN>>>(xhi, xlo, wqt, wkt, wvt, qr, kr, vhi);

    // 4. RMSNorm + RoPE -> q hi/lo, k hi
    normrope_kernel<<<12288, 256>>>(qr, kr, qhi, qlo, khi, qn, kn, sinp, cosp);

    // 5. causal flash attention (fp16 2-pass, descending-qt schedule)
    cudaFuncSetAttribute(flash_mma, cudaFuncAttributeMaxDynamicSharedMemorySize, FA2_SMEM);
    flash_mma<<<dim3(TT / 64, BB * HH), 256, FA2_SMEM>>>(qhi, qlo, khi, vhi, ohi, olo);

    // 6. output projection (fp16 2-pass, cp.async pipeline)
    cudaFuncSetAttribute(gemm_mma, cudaFuncAttributeMaxDynamicSharedMemorySize, GSMEM_DYN);
    gemm_mma<<<dim3((HH*HD)/128, MTOT/128), 256, GSMEM_DYN>>>(ohi, olo, wot, out, HH*HD, HH*HD);
}

// round 9
// speedup vs baseline: 3.9987x; 1.0421x over previous
#include <cuda_runtime.h>
#include <cuda_fp16.h>
#include <math.h>
#include <cstdint>

// Problem constants
#define BB 2
#define TT 2048
#define DD 2048
#define HH 16
#define KK 8
#define HD 128
#define MTOT (BB*TT)   // 4096

// ---------------------------------------------------------------------------
// Scratch (device globals; no allocation allowed)
// ---------------------------------------------------------------------------
__device__ __half g_xhi [(size_t)MTOT * DD];
__device__ __half g_xlo [(size_t)MTOT * DD];
__device__ __half g_wqt [(size_t)(HH*HD) * DD];
__device__ __half g_wkt [(size_t)(KK*HD) * DD];
__device__ __half g_wvt [(size_t)(KK*HD) * DD];
__device__ __half g_wot [(size_t)DD * (HH*HD)];
__device__ float g_q_raw[(size_t)MTOT * (HH*HD)];
__device__ float g_k_raw[(size_t)MTOT * (KK*HD)];
__device__ __half g_qhi [(size_t)MTOT * (HH*HD)];
__device__ __half g_qlo [(size_t)MTOT * (HH*HD)];
__device__ __half g_khi [(size_t)MTOT * (KK*HD)];
__device__ __half g_vhi [(size_t)MTOT * (KK*HD)];
__device__ __half g_ohi [(size_t)MTOT * (HH*HD)];
__device__ __half g_olo [(size_t)MTOT * (HH*HD)];

// ---------------------------------------------------------------------------
// mma.sync / cp.async helpers
// ---------------------------------------------------------------------------
__device__ __forceinline__ uint32_t smem_to_u32(const void* p) {
    uint32_t a;
    asm("{ .reg .u64 t; cvta.to.shared.u64 t, %1; cvt.u32.u64 %0, t; }"
        : "=r"(a) : "l"(p));
    return a;
}

__device__ __forceinline__ uint32_t pack_half2(__half lo, __half hi) {
    return (uint32_t)__half_as_ushort(lo) | ((uint32_t)__half_as_ushort(hi) << 16);
}

__device__ __forceinline__ void ldsm_x4(uint32_t& r0, uint32_t& r1,
                                        uint32_t& r2, uint32_t& r3, uint32_t addr) {
    asm volatile("ldmatrix.sync.aligned.m8n8.x4.shared.b16 {%0,%1,%2,%3}, [%4];"
                 : "=r"(r0), "=r"(r1), "=r"(r2), "=r"(r3) : "r"(addr));
}

__device__ __forceinline__ void ldsm_x4_trans(uint32_t& r0, uint32_t& r1,
                                              uint32_t& r2, uint32_t& r3, uint32_t addr) {
    asm volatile("ldmatrix.sync.aligned.m8n8.x4.trans.shared.b16 {%0,%1,%2,%3}, [%4];"
                 : "=r"(r0), "=r"(r1), "=r"(r2), "=r"(r3) : "r"(addr));
}

__device__ __forceinline__ void mma_f16(float* d, const uint32_t* a,
                                        uint32_t b0, uint32_t b1) {
    asm volatile(
        "mma.sync.aligned.m16n8k16.row.col.f32.f16.f16.f32 "
        "{%0,%1,%2,%3}, {%4,%5,%6,%7}, {%8,%9}, {%0,%1,%2,%3};"
        : "+f"(d[0]), "+f"(d[1]), "+f"(d[2]), "+f"(d[3])
        : "r"(a[0]), "r"(a[1]), "r"(a[2]), "r"(a[3]), "r"(b0), "r"(b1));
}

__device__ __forceinline__ void cp_async16(uint32_t saddr, const void* gaddr) {
    asm volatile("cp.async.cg.shared.global [%0], [%1], 16;"
                 :: "r"(saddr), "l"(gaddr) : "memory");
}
__device__ __forceinline__ void cp_commit() {
    asm volatile("cp.async.commit_group;" ::: "memory");
}

// ---------------------------------------------------------------------------
// Conversion: fp32 -> (fp16 hi, fp16 lo)
// ---------------------------------------------------------------------------
__global__ __launch_bounds__(256)
void convert_split_kernel(const float* __restrict__ X,
                          __half* __restrict__ Hi,
                          __half* __restrict__ Lo, int n4) {
    int i = blockIdx.x * 256 + threadIdx.x;
    if (i >= n4) return;
    float4 v = ((const float4*)X)[i];
    __half h0 = __float2half_rn(v.x), h1 = __float2half_rn(v.y);
    __half h2 = __float2half_rn(v.z), h3 = __float2half_rn(v.w);
    __half l0 = __float2half_rn(v.x - __half2float(h0));
    __half l1 = __float2half_rn(v.y - __half2float(h1));
    __half l2 = __float2half_rn(v.z - __half2float(h2));
    __half l3 = __float2half_rn(v.w - __half2float(h3));
    __half2* hp = (__half2*)(Hi + 4 * (size_t)i);
    __half2* lp = (__half2*)(Lo + 4 * (size_t)i);
    hp[0] = __halves2half2(h0, h1); hp[1] = __halves2half2(h2, h3);
    lp[0] = __halves2half2(l0, l1); lp[1] = __halves2half2(l2, l3);
}

// ---------------------------------------------------------------------------
// Transpose: W[Kd, N] fp32 -> T [N, Kd] fp16 (hi only)
// ---------------------------------------------------------------------------
__global__ __launch_bounds__(256)
void transpose_half_kernel(const float* __restrict__ W,
                           __half* __restrict__ Thi, int Kd, int N) {
    __shared__ float tile[32][33];
    int n0 = blockIdx.x * 32, k0 = blockIdx.y * 32;
    int tx = threadIdx.x & 31, ty = threadIdx.x >> 5;
#pragma unroll
    for (int r = ty; r < 32; r += 8)
        tile[r][tx] = W[(size_t)(k0 + r) * N + n0 + tx];
    __syncthreads();
#pragma unroll
    for (int r = ty; r < 32; r += 8)
        Thi[(size_t)(n0 + r) * Kd + k0 + tx] = __float2half_rn(tile[tx][r]);
}

// ---------------------------------------------------------------------------
// fp16 2-pass compensated GEMM with cp.async 3-stage pipeline (from R7).
// ---------------------------------------------------------------------------
#define GPAD 40
#define GTILE_BYTES (128 * GPAD * 2)      // 10240
#define GSTAGE_BYTES (3 * GTILE_BYTES)    // 30720 (Ahi, Alo, Bhi)
#define GSMEM_DYN (3 * GSTAGE_BYTES)      // 92160 (3 stages)

__device__ __forceinline__ void gemm_core(
    const __half* __restrict__ Ahi, const __half* __restrict__ Alo,
    const __half* __restrict__ Bhi,
    float* __restrict__ C, __half* __restrict__ Ch,
    int N, int Kd, int row0, int col0, char* smg) {
    const uint32_t sbase0 = smem_to_u32(smg);

    const int tid = threadIdx.x;
    const int lane = tid & 31;
    const int wid = tid >> 5;
    const int wr = wid & 3;
    const int wc = wid >> 2;

    float d[2][8][4];
#pragma unroll
    for (int m = 0; m < 2; ++m)
#pragma unroll
        for (int n = 0; n < 8; ++n)
#pragma unroll
            for (int j = 0; j < 4; ++j) d[m][n][j] = 0.0f;

    const __half* gb[3] = {Ahi, Alo, Bhi};
    int grow[6], gseg[6];
#pragma unroll
    for (int a = 0; a < 3; ++a) {
        int r0 = (a < 2) ? row0 : col0;
        int s0 = tid, s1 = tid + 256;
        grow[2*a]   = r0 + (s0 >> 2); gseg[2*a]   = s0 & 3;
        grow[2*a+1] = r0 + (s1 >> 2); gseg[2*a+1] = s1 & 3;
    }

    auto cp_chunk = [&](int k0, int stage) {
        uint32_t st = sbase0 + stage * GSTAGE_BYTES;
#pragma unroll
        for (int a = 0; a < 3; ++a) {
#pragma unroll
            for (int j = 0; j < 2; ++j) {
                int e = 2 * a + j;
                int s = tid + j * 256;
                uint32_t sa = st + a * GTILE_BYTES + (s >> 2) * (GPAD*2) + (s & 3) * 16;
                cp_async16(sa, gb[a] + (size_t)grow[e] * Kd + k0 + gseg[e] * 8);
            }
        }
        cp_commit();
    };

    const int NC = Kd / 32;

    cp_chunk(0, 0);
    cp_chunk(32, 1);

    for (int c = 0; c < NC; ++c) {
        if (c + 1 < NC) asm volatile("cp.async.wait_group 1;" ::: "memory");
        else            asm volatile("cp.async.wait_group 0;" ::: "memory");
        __syncthreads();

        if (c + 2 < NC) cp_chunk((c + 2) * 32, (c + 2) % 3);

        const uint32_t sb = sbase0 + (c % 3) * GSTAGE_BYTES;
#pragma unroll
        for (int ks = 0; ks < 2; ++ks) {
            const uint32_t coff = ks * 32 + (lane >> 4) * 16;
            uint32_t ah[2][4], al[2][4];
#pragma unroll
            for (int mb = 0; mb < 2; ++mb) {
                uint32_t addr = sb + (wr * 32 + mb * 16 + (lane & 15)) * (GPAD*2) + coff;
                ldsm_x4(ah[mb][0], ah[mb][1], ah[mb][2], ah[mb][3], addr);
                ldsm_x4(al[mb][0], al[mb][1], al[mb][2], al[mb][3], addr + GTILE_BYTES);
            }
            uint32_t bh[4][4];
#pragma unroll
            for (int nb = 0; nb < 4; ++nb) {
                uint32_t addr = sb + 2 * GTILE_BYTES +
                                (wc * 64 + nb * 16 + (lane & 15)) * (GPAD*2) + coff;
                ldsm_x4(bh[nb][0], bh[nb][1], bh[nb][2], bh[nb][3], addr);
            }
#pragma unroll
            for (int pass = 0; pass < 2; ++pass) {
#pragma unroll
                for (int mb = 0; mb < 2; ++mb) {
#pragma unroll
                    for (int nb = 0; nb < 4; ++nb) {
                        const uint32_t* a = pass ? al[mb] : ah[mb];
                        mma_f16(d[mb][2*nb],   a, bh[nb][0], bh[nb][2]);
                        mma_f16(d[mb][2*nb+1], a, bh[nb][1], bh[nb][3]);
                    }
                }
            }
        }
    }

    const int frow = lane >> 2;
    const int fcol = 2 * (lane & 3);
#pragma unroll
    for (int mb = 0; mb < 2; ++mb) {
#pragma unroll
        for (int nt = 0; nt < 8; ++nt) {
            int r = row0 + wr * 32 + mb * 16 + frow;
            int cc = col0 + wc * 64 + nt * 8 + fcol;
            if (Ch) {
                *(__half2*)&Ch[(size_t)r * N + cc] =
                    __halves2half2(__float2half_rn(d[mb][nt][0]), __float2half_rn(d[mb][nt][1]));
                *(__half2*)&Ch[(size_t)(r + 8) * N + cc] =
                    __halves2half2(__float2half_rn(d[mb][nt][2]), __float2half_rn(d[mb][nt][3]));
            } else {
                *(float2*)&C[(size_t)r * N + cc]       = make_float2(d[mb][nt][0], d[mb][nt][1]);
                *(float2*)&C[(size_t)(r + 8) * N + cc] = make_float2(d[mb][nt][2], d[mb][nt][3]);
            }
        }
    }
}

__global__ __launch_bounds__(256, 2)
void gemm_mma(const __half* __restrict__ Ahi, const __half* __restrict__ Alo,
              const __half* __restrict__ Bhi,
              float* __restrict__ C, int N, int Kd) {
    extern __shared__ char smg[];
    gemm_core(Ahi, Alo, Bhi, C, nullptr, N, Kd, blockIdx.y * 128, blockIdx.x * 128, smg);
}

__global__ __launch_bounds__(256, 2)
void gemm_qkv(const __half* __restrict__ Xhi, const __half* __restrict__ Xlo,
              const __half* __restrict__ Wq, const __half* __restrict__ Wk,
              const __half* __restrict__ Wv,
              float* __restrict__ Q, float* __restrict__ Kc, __half* __restrict__ Vh) {
    extern __shared__ char smg[];
    int ct = blockIdx.x;
    if (ct < 16) {
        gemm_core(Xhi, Xlo, Wq, Q, nullptr, HH*HD, DD, blockIdx.y * 128, ct * 128, smg);
    } else if (ct < 24) {
        gemm_core(Xhi, Xlo, Wk, Kc, nullptr, KK*HD, DD, blockIdx.y * 128, (ct - 16) * 128, smg);
    } else {
        gemm_core(Xhi, Xlo, Wv, nullptr, Vh, KK*HD, DD, blockIdx.y * 128, (ct - 24) * 128, smg);
    }
}

// ---------------------------------------------------------------------------
// Fused RMSNorm + RoPE. q -> fp16 hi/lo (unscaled); k -> fp16 hi only.
// ---------------------------------------------------------------------------
__global__ __launch_bounds__(256)
void normrope_kernel(const float* __restrict__ q, const float* __restrict__ k,
                     __half* __restrict__ Qhi, __half* __restrict__ Qlo,
                     __half* __restrict__ Khi,
                     const float* __restrict__ qn, const float* __restrict__ kn,
                     const float* __restrict__ sinp, const float* __restrict__ cosp) {
    int warp = (blockIdx.x * blockDim.x + threadIdx.x) >> 5;
    int lane = threadIdx.x & 31;
    const int NQ = MTOT * HH;
    const int NTOT = NQ + MTOT * KK;
    if (warp >= NTOT) return;

    const float* ptr;
    const float* w;
    int t;
    bool isq = warp < NQ;
    size_t off;
    if (isq) {
        int bt = warp >> 4;
        int h = warp & 15;
        off = (size_t)bt * (HH * HD) + h * HD;
        ptr = q + off;
        w = qn;
        t = bt & (TT - 1);
    } else {
        int v2 = warp - NQ;
        int bt = v2 >> 3;
        int kh = v2 & 7;
        off = (size_t)bt * (KK * HD) + kh * HD;
        ptr = k + off;
        w = kn;
        t = bt & (TT - 1);
    }

    float2 a  = *(const float2*)(ptr + 2 * lane);
    float2 b2 = *(const float2*)(ptr + 64 + 2 * lane);

    float ss = a.x * a.x + a.y * a.y + b2.x * b2.x + b2.y * b2.y;
#pragma unroll
    for (int o = 16; o; o >>= 1) ss += __shfl_xor_sync(0xFFFFFFFFu, ss, o);
    float rinv = rsqrtf(ss * (1.0f / 128.0f) + 1e-6f);

    float w0 = w[2 * lane], w1 = w[2 * lane + 1];
    float w2 = w[64 + 2 * lane], w3 = w[65 + 2 * lane];
    float n0 = a.x * rinv * w0, n1 = a.y * rinv * w1;
    float n2 = b2.x * rinv * w2, n3 = b2.y * rinv * w3;

    float s0 = sinp[t * 64 + lane],      c0 = cosp[t * 64 + lane];
    float s1 = sinp[t * 64 + lane + 32], c1 = cosp[t * 64 + lane + 32];
    float o0 = n0 * c0 - n1 * s0;
    float o1 = n2 * c1 - n3 * s1;
    float o2 = n0 * s0 + n1 * c0;
    float o3 = n2 * s1 + n3 * c1;

    if (isq) {
        __half h0 = __float2half_rn(o0);
        __half h1 = __float2half_rn(o1);
        __half h2 = __float2half_rn(o2);
        __half h3 = __float2half_rn(o3);
        __half* dhi = Qhi + off;
        __half* dlo = Qlo + off;
        dhi[lane]      = h0;  dlo[lane]      = __float2half_rn(o0 - __half2float(h0));
        dhi[lane + 32] = h1;  dlo[lane + 32] = __float2half_rn(o1 - __half2float(h1));
        dhi[lane + 64] = h2;  dlo[lane + 64] = __float2half_rn(o2 - __half2float(h2));
        dhi[lane + 96] = h3;  dlo[lane + 96] = __float2half_rn(o3 - __half2float(h3));
    } else {
        __half* dhi = Khi + off;
        dhi[lane]      = __float2half_rn(o0);
        dhi[lane + 32] = __float2half_rn(o1);
        dhi[lane + 64] = __float2half_rn(o2);
        dhi[lane + 96] = __float2half_rn(o3);
    }
}

// ---------------------------------------------------------------------------
// Flash attention (FA2-style): 128-row Q tile, 8 warps x 16 rows,
// register-resident softmax + P fragments, cp.async double-buffered K/V,
// one barrier per K-tile. fp16 2-pass compensated.
// ---------------------------------------------------------------------------
#define FK_STRB 272                 // bytes per 128-wide fp16 row (136 halves)
#define FQ_TILE (128 * FK_STRB)     // 34816 (one Q array)
#define FKV_TILE (64 * FK_STRB)     // 17408 (one K or V tile)
#define F3_QH 0
#define F3_QL FQ_TILE
#define F3_KV (2 * FQ_TILE)         // stage s: K at +s*2*FKV_TILE, V at +FKV_TILE
#define FA3_SMEM (2 * FQ_TILE + 2 * 2 * FKV_TILE)   // 139264

__global__ __launch_bounds__(256, 1)
void flash_mma(const __half* __restrict__ Qhi, const __half* __restrict__ Qlo,
               const __half* __restrict__ Khi, const __half* __restrict__ Vhi,
               __half* __restrict__ Ohi, __half* __restrict__ Olo) {
    extern __shared__ char sm[];
    const uint32_t sb = smem_to_u32(sm);

    const int qt = gridDim.x - 1 - blockIdx.x;   // descending work order
    const int bh = blockIdx.y;
    const int b = bh >> 4;
    const int h = bh & 15;
    const int kh = h >> 1;

    const int tid = threadIdx.x;
    const int lane = tid & 31;
    const int wid = tid >> 5;           // warp owns rows wid*16 .. +15
    const int frow = lane >> 2;
    const int fcol = 2 * (lane & 3);
    const float scale = 0.08838834764831845f;  // 1/sqrt(128)

    const int qrow0 = qt * 128 + wid * 16;      // warp's first global q row
    const int ktmax = 2 * qt + 1;

    const __half* qh = Qhi + ((size_t)(b * TT + qt * 128)) * (HH*HD) + h * HD;
    const __half* ql = Qlo + ((size_t)(b * TT + qt * 128)) * (HH*HD) + h * HD;
    const __half* kbase = Khi + ((size_t)(b * TT)) * (KK*HD) + kh * HD;
    const __half* vbase = Vhi + ((size_t)(b * TT)) * (KK*HD) + kh * HD;

    // K/V tile loader (cp.async): 64 rows x 16 segs each for K and V
    auto cp_kv = [&](int kt, int stage) {
        uint32_t st = sb + F3_KV + stage * 2 * FKV_TILE;
        const __half* kp = kbase + (size_t)(kt * 64) * (KK*HD);
        const __half* vp = vbase + (size_t)(kt * 64) * (KK*HD);
#pragma unroll
        for (int j = 0; j < 4; ++j) {
            int idx = tid + j * 256;      // 0..1023
            int r = idx >> 4, s = idx & 15;
            uint32_t so = r * FK_STRB + s * 16;
            cp_async16(st + so,            kp + (size_t)r * (KK*HD) + s * 8);
            cp_async16(st + FKV_TILE + so, vp + (size_t)r * (KK*HD) + s * 8);
        }
        cp_commit();
    };

    // Issue Q (hi/lo) + first K/V via cp.async
    {
#pragma unroll
        for (int j = 0; j < 8; ++j) {
            int idx = tid + j * 256;      // 0..2047
            int r = idx >> 4, s = idx & 15;
            uint32_t so = r * FK_STRB + s * 16;
            cp_async16(sb + F3_QH + so, qh + (size_t)r * (HH*HD) + s * 8);
            cp_async16(sb + F3_QL + so, ql + (size_t)r * (HH*HD) + s * 8);
        }
        cp_commit();
        cp_kv(0, 0);
    }

    float o[16][4];
#pragma unroll
    for (int n = 0; n < 16; ++n)
#pragma unroll
        for (int j = 0; j < 4; ++j) o[n][j] = 0.0f;
    float m0 = -INFINITY, m1 = -INFINITY, l0 = 0.0f, l1 = 0.0f;

    for (int kt = 0; kt <= ktmax; ++kt) {
        asm volatile("cp.async.wait_group 0;" ::: "memory");
        __syncthreads();
        if (kt < ktmax) cp_kv(kt + 1, (kt + 1) & 1);

        const uint32_t kvs = sb + F3_KV + (kt & 1) * 2 * FKV_TILE;

        // ---- S = Q @ K^T (2-pass: Qhi+Qlo vs Khi), m16 x n64 per warp ----
        float s[8][4];
#pragma unroll
        for (int i = 0; i < 8; ++i)
#pragma unroll
            for (int j = 0; j < 4; ++j) s[i][j] = 0.0f;

#pragma unroll
        for (int ks = 0; ks < 8; ++ks) {
            const uint32_t coff = ks * 32 + (lane >> 4) * 16;
            uint32_t aq[4], aql[4];
            {
                uint32_t addr = sb + F3_QH + (wid * 16 + (lane & 15)) * FK_STRB + coff;
                ldsm_x4(aq[0], aq[1], aq[2], aq[3], addr);
                ldsm_x4(aql[0], aql[1], aql[2], aql[3], addr + FQ_TILE);
            }
            uint32_t kb[4][4];
#pragma unroll
            for (int nb = 0; nb < 4; ++nb) {
                uint32_t addr = kvs + (nb * 16 + (lane & 15)) * FK_STRB + coff;
                ldsm_x4(kb[nb][0], kb[nb][1], kb[nb][2], kb[nb][3], addr);
            }
#pragma unroll
            for (int pass = 0; pass < 2; ++pass) {
                const uint32_t* a = pass ? aql : aq;
#pragma unroll
                for (int nb = 0; nb < 4; ++nb) {
                    mma_f16(s[2*nb],   a, kb[nb][0], kb[nb][2]);
                    mma_f16(s[2*nb+1], a, kb[nb][1], kb[nb][3]);
                }
            }
        }

        // ---- scale + causal mask (registers) ----
        bool boundary = (kt * 64 + 63 > qrow0);
#pragma unroll
        for (int nt = 0; nt < 8; ++nt) {
            int c = kt * 64 + nt * 8 + fcol;
            s[nt][0] *= scale; s[nt][1] *= scale;
            s[nt][2] *= scale; s[nt][3] *= scale;
            if (boundary) {
                int r0 = qrow0 + frow, r1 = r0 + 8;
                if (c     > r0) s[nt][0] = -INFINITY;
                if (c + 1 > r0) s[nt][1] = -INFINITY;
                if (c     > r1) s[nt][2] = -INFINITY;
                if (c + 1 > r1) s[nt][3] = -INFINITY;
            }
        }

        // ---- register online softmax (quad shfl reductions) ----
        float mx0 = -INFINITY, mx1 = -INFINITY;
#pragma unroll
        for (int nt = 0; nt < 8; ++nt) {
            mx0 = fmaxf(mx0, fmaxf(s[nt][0], s[nt][1]));
            mx1 = fmaxf(mx1, fmaxf(s[nt][2], s[nt][3]));
        }
        mx0 = fmaxf(mx0, __shfl_xor_sync(0xFFFFFFFFu, mx0, 1));
        mx0 = fmaxf(mx0, __shfl_xor_sync(0xFFFFFFFFu, mx0, 2));
        mx1 = fmaxf(mx1, __shfl_xor_sync(0xFFFFFFFFu, mx1, 1));
        mx1 = fmaxf(mx1, __shfl_xor_sync(0xFFFFFFFFu, mx1, 2));
        mx0 = fmaxf(mx0, m0);
        mx1 = fmaxf(mx1, m1);
        float a0 = __expf(m0 - mx0);
        float a1 = __expf(m1 - mx1);
        float sum0 = 0.0f, sum1 = 0.0f;
#pragma unroll
        for (int nt = 0; nt < 8; ++nt) {
            s[nt][0] = __expf(s[nt][0] - mx0); sum0 += s[nt][0];
            s[nt][1] = __expf(s[nt][1] - mx0); sum0 += s[nt][1];
            s[nt][2] = __expf(s[nt][2] - mx1); sum1 += s[nt][2];
            s[nt][3] = __expf(s[nt][3] - mx1); sum1 += s[nt][3];
        }
        sum0 += __shfl_xor_sync(0xFFFFFFFFu, sum0, 1);
        sum0 += __shfl_xor_sync(0xFFFFFFFFu, sum0, 2);
        sum1 += __shfl_xor_sync(0xFFFFFFFFu, sum1, 1);
        sum1 += __shfl_xor_sync(0xFFFFFFFFu, sum1, 2);
        l0 = l0 * a0 + sum0;  m0 = mx0;
        l1 = l1 * a1 + sum1;  m1 = mx1;

        // rescale O
#pragma unroll
        for (int nt = 0; nt < 16; ++nt) {
            o[nt][0] *= a0; o[nt][1] *= a0;
            o[nt][2] *= a1; o[nt][3] *= a1;
        }

        // ---- O += (Phi + Plo) @ Vhi ; P fragments built from s registers ----
#pragma unroll
        for (int j = 0; j < 4; ++j) {            // k16 step within the 64 K-rows
            // A fragments (m16k16) from C tiles 2j, 2j+1
            uint32_t ap[4], apl[4];
            {
                __half ph[8], pl[8];
#pragma unroll
                for (int e = 0; e < 4; ++e) {
                    float v0 = s[2*j][e];
                    float v1 = s[2*j+1][e];
                    ph[e]     = __float2half_rn(v0);
                    ph[4 + e] = __float2half_rn(v1);
                    pl[e]     = __float2half_rn(v0 - __half2float(ph[e]));
                    pl[4 + e] = __float2half_rn(v1 - __half2float(ph[4 + e]));
                }
                ap[0]  = pack_half2(ph[0], ph[1]);
                ap[1]  = pack_half2(ph[2], ph[3]);
                ap[2]  = pack_half2(ph[4], ph[5]);
                ap[3]  = pack_half2(ph[6], ph[7]);
                apl[0] = pack_half2(pl[0], pl[1]);
                apl[1] = pack_half2(pl[2], pl[3]);
                apl[2] = pack_half2(pl[4], pl[5]);
                apl[3] = pack_half2(pl[6], pl[7]);
            }
            // V fragments: two groups of 4 n16-blocks, pass-major within group
#pragma unroll
            for (int g = 0; g < 2; ++g) {
                uint32_t vh[4][4];
#pragma unroll
                for (int q = 0; q < 4; ++q) {
                    int nb = g * 4 + q;
                    uint32_t addr = kvs + FKV_TILE
                                  + (j * 16 + (lane & 15)) * FK_STRB
                                  + (nb * 16 + (lane >> 4) * 8) * 2;
                    ldsm_x4_trans(vh[q][0], vh[q][1], vh[q][2], vh[q][3], addr);
                }
#pragma unroll
                for (int q = 0; q < 4; ++q) {
                    int nb = g * 4 + q;
                    mma_f16(o[2*nb],   ap, vh[q][0], vh[q][1]);
                    mma_f16(o[2*nb+1], ap, vh[q][2], vh[q][3]);
                }
#pragma unroll
                for (int q = 0; q < 4; ++q) {
                    int nb = g * 4 + q;
                    mma_f16(o[2*nb],   apl, vh[q][0], vh[q][1]);
                    mma_f16(o[2*nb+1], apl, vh[q][2], vh[q][3]);
                }
            }
        }
    }

    // Epilogue: normalize by 1/l, write fp16 hi/lo (b,t,h,d)
    {
        float li0 = 1.0f / l0;
        float li1 = 1.0f / l1;
        int r0g = b * TT + qt * 128 + wid * 16 + frow;
#pragma unroll
        for (int nt = 0; nt < 16; ++nt) {
            int c = nt * 8 + fcol;
            size_t o0 = (size_t)r0g * (HH*HD) + h * HD + c;
            size_t o1 = (size_t)(r0g + 8) * (HH*HD) + h * HD + c;
            float v00 = o[nt][0] * li0, v01 = o[nt][1] * li0;
            float v10 = o[nt][2] * li1, v11 = o[nt][3] * li1;
            __half h00 = __float2half_rn(v00);
            __half h01 = __float2half_rn(v01);
            __half h10 = __float2half_rn(v10);
            __half h11 = __float2half_rn(v11);
            Ohi[o0] = h00; Ohi[o0 + 1] = h01;
            Ohi[o1] = h10; Ohi[o1 + 1] = h11;
            Olo[o0]     = __float2half_rn(v00 - __half2float(h00));
            Olo[o0 + 1] = __float2half_rn(v01 - __half2float(h01));
            Olo[o1]     = __float2half_rn(v10 - __half2float(h10));
            Olo[o1 + 1] = __float2half_rn(v11 - __half2float(h11));
        }
    }
}

// ---------------------------------------------------------------------------
extern "C" void kernel_launch(void* const* d_in, const int* in_sizes, int n_in,
                              void* d_out, int out_size) {
    const float* x    = (const float*)d_in[0];
    const float* Wq   = (const float*)d_in[1];
    const float* Wk   = (const float*)d_in[2];
    const float* Wv   = (const float*)d_in[3];
    const float* Wo   = (const float*)d_in[4];
    const float* qn   = (const float*)d_in[5];
    const float* kn   = (const float*)d_in[6];
    const float* sinp = (const float*)d_in[7];
    const float* cosp = (const float*)d_in[8];
    float* out = (float*)d_out;

    __half *xhi, *xlo, *wqt, *wkt, *wvt, *wot;
    __half *qhi, *qlo, *khi, *vhi, *ohi, *olo;
    float *qr, *kr;
    cudaGetSymbolAddress((void**)&xhi, g_xhi);
    cudaGetSymbolAddress((void**)&xlo, g_xlo);
    cudaGetSymbolAddress((void**)&wqt, g_wqt);
    cudaGetSymbolAddress((void**)&wkt, g_wkt);
    cudaGetSymbolAddress((void**)&wvt, g_wvt);
    cudaGetSymbolAddress((void**)&wot, g_wot);
    cudaGetSymbolAddress((void**)&qr, g_q_raw);
    cudaGetSymbolAddress((void**)&kr, g_k_raw);
    cudaGetSymbolAddress((void**)&qhi, g_qhi);
    cudaGetSymbolAddress((void**)&qlo, g_qlo);
    cudaGetSymbolAddress((void**)&khi, g_khi);
    cudaGetSymbolAddress((void**)&vhi, g_vhi);
    cudaGetSymbolAddress((void**)&ohi, g_ohi);
    cudaGetSymbolAddress((void**)&olo, g_olo);

    // 1. split-convert x
    convert_split_kernel<<<(MTOT * DD / 4 + 255) / 256, 256>>>(x, xhi, xlo, MTOT * DD / 4);

    // 2. transpose weights to fp16 (hi only)
    transpose_half_kernel<<<dim3((HH*HD)/32, DD/32), 256>>>(Wq, wqt, DD, HH*HD);
    transpose_half_kernel<<<dim3((KK*HD)/32, DD/32), 256>>>(Wk, wkt, DD, KK*HD);
    transpose_half_kernel<<<dim3((KK*HD)/32, DD/32), 256>>>(Wv, wvt, DD, KK*HD);
    transpose_half_kernel<<<dim3((HH*HD)/32, (HH*HD)/32), 256>>>(Wo, wot, HH*HD, HH*HD);

    // 3. fused QKV projection (fp16 2-pass, cp.async pipeline; V -> fp16 direct)
    cudaFuncSetAttribute(gemm_qkv, cudaFuncAttributeMaxDynamicSharedMemorySize, GSMEM_DYN);
    gemm_qkv<<<dim3(32, MTOT/128), 256, GSMEM_DYN>>>(xhi, xlo, wqt, wkt, wvt, qr, kr, vhi);

    // 4. RMSNorm + RoPE -> q hi/lo, k hi
    normrope_kernel<<<12288, 256>>>(qr, kr, qhi, qlo, khi, qn, kn, sinp, cosp);

    // 5. causal flash attention (FA2-style register-resident, 128-row Q tiles)
    cudaFuncSetAttribute(flash_mma, cudaFuncAttributeMaxDynamicSharedMemorySize, FA3_SMEM);
    flash_mma<<<dim3(TT / 128, BB * HH), 256, FA3_SMEM>>>(qhi, qlo, khi, vhi, ohi, olo);

    // 6. output projection (fp16 2-pass, cp.async pipeline)
    cudaFuncSetAttribute(gemm_mma, cudaFuncAttributeMaxDynamicSharedMemorySize, GSMEM_DYN);
    gemm_mma<<<dim3((HH*HD)/128, MTOT/128), 256, GSMEM_DYN>>>(ohi, olo, wot, out, HH*HD, HH*HD);
}

// round 10
// speedup vs baseline: 4.0965x; 1.0245x over previous
#include <cuda_runtime.h>
#include <cuda_fp16.h>
#include <math.h>
#include <cstdint>

// Problem constants
#define BB 2
#define TT 2048
#define DD 2048
#define HH 16
#define KK 8
#define HD 128
#define MTOT (BB*TT)   // 4096

// ---------------------------------------------------------------------------
// Scratch (device globals; no allocation allowed)
// ---------------------------------------------------------------------------
__device__ __half g_xhi [(size_t)MTOT * DD];
__device__ __half g_xlo [(size_t)MTOT * DD];
__device__ __half g_wqt [(size_t)(HH*HD) * DD];
__device__ __half g_wkt [(size_t)(KK*HD) * DD];
__device__ __half g_wvt [(size_t)(KK*HD) * DD];
__device__ __half g_wot [(size_t)DD * (HH*HD)];
__device__ float g_q_raw[(size_t)MTOT * (HH*HD)];
__device__ float g_k_raw[(size_t)MTOT * (KK*HD)];
__device__ __half g_qhi [(size_t)MTOT * (HH*HD)];
__device__ __half g_qlo [(size_t)MTOT * (HH*HD)];
__device__ __half g_khi [(size_t)MTOT * (KK*HD)];
__device__ __half g_vhi [(size_t)MTOT * (KK*HD)];
__device__ __half g_ohi [(size_t)MTOT * (HH*HD)];
__device__ __half g_olo [(size_t)MTOT * (HH*HD)];

// ---------------------------------------------------------------------------
// mma.sync / cp.async helpers
// ---------------------------------------------------------------------------
__device__ __forceinline__ uint32_t smem_to_u32(const void* p) {
    uint32_t a;
    asm("{ .reg .u64 t; cvta.to.shared.u64 t, %1; cvt.u32.u64 %0, t; }"
        : "=r"(a) : "l"(p));
    return a;
}

__device__ __forceinline__ uint32_t pack_half2(__half lo, __half hi) {
    return (uint32_t)__half_as_ushort(lo) | ((uint32_t)__half_as_ushort(hi) << 16);
}

__device__ __forceinline__ void ldsm_x4(uint32_t& r0, uint32_t& r1,
                                        uint32_t& r2, uint32_t& r3, uint32_t addr) {
    asm volatile("ldmatrix.sync.aligned.m8n8.x4.shared.b16 {%0,%1,%2,%3}, [%4];"
                 : "=r"(r0), "=r"(r1), "=r"(r2), "=r"(r3) : "r"(addr));
}

__device__ __forceinline__ void ldsm_x4_trans(uint32_t& r0, uint32_t& r1,
                                              uint32_t& r2, uint32_t& r3, uint32_t addr) {
    asm volatile("ldmatrix.sync.aligned.m8n8.x4.trans.shared.b16 {%0,%1,%2,%3}, [%4];"
                 : "=r"(r0), "=r"(r1), "=r"(r2), "=r"(r3) : "r"(addr));
}

__device__ __forceinline__ void mma_f16(float* d, const uint32_t* a,
                                        uint32_t b0, uint32_t b1) {
    asm volatile(
        "mma.sync.aligned.m16n8k16.row.col.f32.f16.f16.f32 "
        "{%0,%1,%2,%3}, {%4,%5,%6,%7}, {%8,%9}, {%0,%1,%2,%3};"
        : "+f"(d[0]), "+f"(d[1]), "+f"(d[2]), "+f"(d[3])
        : "r"(a[0]), "r"(a[1]), "r"(a[2]), "r"(a[3]), "r"(b0), "r"(b1));
}

__device__ __forceinline__ void cp_async16(uint32_t saddr, const void* gaddr) {
    asm volatile("cp.async.cg.shared.global [%0], [%1], 16;"
                 :: "r"(saddr), "l"(gaddr) : "memory");
}
__device__ __forceinline__ void cp_commit() {
    asm volatile("cp.async.commit_group;" ::: "memory");
}

// ---------------------------------------------------------------------------
// Conversion: fp32 -> (fp16 hi, fp16 lo)
// ---------------------------------------------------------------------------
__global__ __launch_bounds__(256)
void convert_split_kernel(const float* __restrict__ X,
                          __half* __restrict__ Hi,
                          __half* __restrict__ Lo, int n4) {
    int i = blockIdx.x * 256 + threadIdx.x;
    if (i >= n4) return;
    float4 v = ((const float4*)X)[i];
    __half h0 = __float2half_rn(v.x), h1 = __float2half_rn(v.y);
    __half h2 = __float2half_rn(v.z), h3 = __float2half_rn(v.w);
    __half l0 = __float2half_rn(v.x - __half2float(h0));
    __half l1 = __float2half_rn(v.y - __half2float(h1));
    __half l2 = __float2half_rn(v.z - __half2float(h2));
    __half l3 = __float2half_rn(v.w - __half2float(h3));
    __half2* hp = (__half2*)(Hi + 4 * (size_t)i);
    __half2* lp = (__half2*)(Lo + 4 * (size_t)i);
    hp[0] = __halves2half2(h0, h1); hp[1] = __halves2half2(h2, h3);
    lp[0] = __halves2half2(l0, l1); lp[1] = __halves2half2(l2, l3);
}

// ---------------------------------------------------------------------------
// Transpose: W[Kd, N] fp32 -> T [N, Kd] fp16 (hi only)
// ---------------------------------------------------------------------------
__global__ __launch_bounds__(256)
void transpose_half_kernel(const float* __restrict__ W,
                           __half* __restrict__ Thi, int Kd, int N) {
    __shared__ float tile[32][33];
    int n0 = blockIdx.x * 32, k0 = blockIdx.y * 32;
    int tx = threadIdx.x & 31, ty = threadIdx.x >> 5;
#pragma unroll
    for (int r = ty; r < 32; r += 8)
        tile[r][tx] = W[(size_t)(k0 + r) * N + n0 + tx];
    __syncthreads();
#pragma unroll
    for (int r = ty; r < 32; r += 8)
        Thi[(size_t)(n0 + r) * Kd + k0 + tx] = __float2half_rn(tile[tx][r]);
}

// ---------------------------------------------------------------------------
// fp16 GEMM with cp.async 3-stage pipeline. use_lo selects 2-pass (A hi+lo)
// or 1-pass (A hi only) accumulation.
// ---------------------------------------------------------------------------
#define GPAD 40
#define GTILE_BYTES (128 * GPAD * 2)      // 10240
#define GSTAGE_BYTES (3 * GTILE_BYTES)    // 30720 (Ahi, Alo, Bhi)
#define GSMEM_DYN (3 * GSTAGE_BYTES)      // 92160 (3 stages)

__device__ __forceinline__ void gemm_core(
    const __half* __restrict__ Ahi, const __half* __restrict__ Alo,
    const __half* __restrict__ Bhi,
    float* __restrict__ C, __half* __restrict__ Ch,
    int N, int Kd, int row0, int col0, char* smg, bool use_lo) {
    const uint32_t sbase0 = smem_to_u32(smg);

    const int tid = threadIdx.x;
    const int lane = tid & 31;
    const int wid = tid >> 5;
    const int wr = wid & 3;
    const int wc = wid >> 2;

    float d[2][8][4];
#pragma unroll
    for (int m = 0; m < 2; ++m)
#pragma unroll
        for (int n = 0; n < 8; ++n)
#pragma unroll
            for (int j = 0; j < 4; ++j) d[m][n][j] = 0.0f;

    const __half* gb[3] = {Ahi, Alo, Bhi};
    int grow[6], gseg[6];
#pragma unroll
    for (int a = 0; a < 3; ++a) {
        int r0 = (a < 2) ? row0 : col0;
        int s0 = tid, s1 = tid + 256;
        grow[2*a]   = r0 + (s0 >> 2); gseg[2*a]   = s0 & 3;
        grow[2*a+1] = r0 + (s1 >> 2); gseg[2*a+1] = s1 & 3;
    }

    auto cp_chunk = [&](int k0, int stage) {
        uint32_t st = sbase0 + stage * GSTAGE_BYTES;
#pragma unroll
        for (int a = 0; a < 3; ++a) {
            if (a == 1 && !use_lo) continue;
#pragma unroll
            for (int j = 0; j < 2; ++j) {
                int e = 2 * a + j;
                int s = tid + j * 256;
                uint32_t sa = st + a * GTILE_BYTES + (s >> 2) * (GPAD*2) + (s & 3) * 16;
                cp_async16(sa, gb[a] + (size_t)grow[e] * Kd + k0 + gseg[e] * 8);
            }
        }
        cp_commit();
    };

    const int NC = Kd / 32;

    cp_chunk(0, 0);
    cp_chunk(32, 1);

    for (int c = 0; c < NC; ++c) {
        if (c + 1 < NC) asm volatile("cp.async.wait_group 1;" ::: "memory");
        else            asm volatile("cp.async.wait_group 0;" ::: "memory");
        __syncthreads();

        if (c + 2 < NC) cp_chunk((c + 2) * 32, (c + 2) % 3);

        const uint32_t sb = sbase0 + (c % 3) * GSTAGE_BYTES;
#pragma unroll
        for (int ks = 0; ks < 2; ++ks) {
            const uint32_t coff = ks * 32 + (lane >> 4) * 16;
            uint32_t ah[2][4], al[2][4];
#pragma unroll
            for (int mb = 0; mb < 2; ++mb) {
                uint32_t addr = sb + (wr * 32 + mb * 16 + (lane & 15)) * (GPAD*2) + coff;
                ldsm_x4(ah[mb][0], ah[mb][1], ah[mb][2], ah[mb][3], addr);
                if (use_lo)
                    ldsm_x4(al[mb][0], al[mb][1], al[mb][2], al[mb][3], addr + GTILE_BYTES);
            }
            uint32_t bh[4][4];
#pragma unroll
            for (int nb = 0; nb < 4; ++nb) {
                uint32_t addr = sb + 2 * GTILE_BYTES +
                                (wc * 64 + nb * 16 + (lane & 15)) * (GPAD*2) + coff;
                ldsm_x4(bh[nb][0], bh[nb][1], bh[nb][2], bh[nb][3], addr);
            }
#pragma unroll
            for (int mb = 0; mb < 2; ++mb) {
#pragma unroll
                for (int nb = 0; nb < 4; ++nb) {
                    mma_f16(d[mb][2*nb],   ah[mb], bh[nb][0], bh[nb][2]);
                    mma_f16(d[mb][2*nb+1], ah[mb], bh[nb][1], bh[nb][3]);
                }
            }
            if (use_lo) {
#pragma unroll
                for (int mb = 0; mb < 2; ++mb) {
#pragma unroll
                    for (int nb = 0; nb < 4; ++nb) {
                        mma_f16(d[mb][2*nb],   al[mb], bh[nb][0], bh[nb][2]);
                        mma_f16(d[mb][2*nb+1], al[mb], bh[nb][1], bh[nb][3]);
                    }
                }
            }
        }
    }

    const int frow = lane >> 2;
    const int fcol = 2 * (lane & 3);
#pragma unroll
    for (int mb = 0; mb < 2; ++mb) {
#pragma unroll
        for (int nt = 0; nt < 8; ++nt) {
            int r = row0 + wr * 32 + mb * 16 + frow;
            int cc = col0 + wc * 64 + nt * 8 + fcol;
            if (Ch) {
                *(__half2*)&Ch[(size_t)r * N + cc] =
                    __halves2half2(__float2half_rn(d[mb][nt][0]), __float2half_rn(d[mb][nt][1]));
                *(__half2*)&Ch[(size_t)(r + 8) * N + cc] =
                    __halves2half2(__float2half_rn(d[mb][nt][2]), __float2half_rn(d[mb][nt][3]));
            } else {
                *(float2*)&C[(size_t)r * N + cc]       = make_float2(d[mb][nt][0], d[mb][nt][1]);
                *(float2*)&C[(size_t)(r + 8) * N + cc] = make_float2(d[mb][nt][2], d[mb][nt][3]);
            }
        }
    }
}

__global__ __launch_bounds__(256, 2)
void gemm_mma(const __half* __restrict__ Ahi, const __half* __restrict__ Alo,
              const __half* __restrict__ Bhi,
              float* __restrict__ C, int N, int Kd) {
    extern __shared__ char smg[];
    gemm_core(Ahi, Alo, Bhi, C, nullptr, N, Kd, blockIdx.y * 128, blockIdx.x * 128, smg, true);
}

// Fused QKV: Q col-tiles 2-pass; K/V col-tiles 1-pass (output rounds to fp16 anyway)
__global__ __launch_bounds__(256, 2)
void gemm_qkv(const __half* __restrict__ Xhi, const __half* __restrict__ Xlo,
              const __half* __restrict__ Wq, const __half* __restrict__ Wk,
              const __half* __restrict__ Wv,
              float* __restrict__ Q, float* __restrict__ Kc, __half* __restrict__ Vh) {
    extern __shared__ char smg[];
    int ct = blockIdx.x;
    if (ct < 16) {
        gemm_core(Xhi, Xlo, Wq, Q, nullptr, HH*HD, DD, blockIdx.y * 128, ct * 128, smg, true);
    } else if (ct < 24) {
        gemm_core(Xhi, Xlo, Wk, Kc, nullptr, KK*HD, DD, blockIdx.y * 128, (ct - 16) * 128, smg, false);
    } else {
        gemm_core(Xhi, Xlo, Wv, nullptr, Vh, KK*HD, DD, blockIdx.y * 128, (ct - 24) * 128, smg, false);
    }
}

// ---------------------------------------------------------------------------
// Fused RMSNorm + RoPE. q -> fp16 hi/lo (unscaled); k -> fp16 hi only.
// ---------------------------------------------------------------------------
__global__ __launch_bounds__(256)
void normrope_kernel(const float* __restrict__ q, const float* __restrict__ k,
                     __half* __restrict__ Qhi, __half* __restrict__ Qlo,
                     __half* __restrict__ Khi,
                     const float* __restrict__ qn, const float* __restrict__ kn,
                     const float* __restrict__ sinp, const float* __restrict__ cosp) {
    int warp = (blockIdx.x * blockDim.x + threadIdx.x) >> 5;
    int lane = threadIdx.x & 31;
    const int NQ = MTOT * HH;
    const int NTOT = NQ + MTOT * KK;
    if (warp >= NTOT) return;

    const float* ptr;
    const float* w;
    int t;
    bool isq = warp < NQ;
    size_t off;
    if (isq) {
        int bt = warp >> 4;
        int h = warp & 15;
        off = (size_t)bt * (HH * HD) + h * HD;
        ptr = q + off;
        w = qn;
        t = bt & (TT - 1);
    } else {
        int v2 = warp - NQ;
        int bt = v2 >> 3;
        int kh = v2 & 7;
        off = (size_t)bt * (KK * HD) + kh * HD;
        ptr = k + off;
        w = kn;
        t = bt & (TT - 1);
    }

    float2 a  = *(const float2*)(ptr + 2 * lane);
    float2 b2 = *(const float2*)(ptr + 64 + 2 * lane);

    float ss = a.x * a.x + a.y * a.y + b2.x * b2.x + b2.y * b2.y;
#pragma unroll
    for (int o = 16; o; o >>= 1) ss += __shfl_xor_sync(0xFFFFFFFFu, ss, o);
    float rinv = rsqrtf(ss * (1.0f / 128.0f) + 1e-6f);

    float w0 = w[2 * lane], w1 = w[2 * lane + 1];
    float w2 = w[64 + 2 * lane], w3 = w[65 + 2 * lane];
    float n0 = a.x * rinv * w0, n1 = a.y * rinv * w1;
    float n2 = b2.x * rinv * w2, n3 = b2.y * rinv * w3;

    float s0 = sinp[t * 64 + lane],      c0 = cosp[t * 64 + lane];
    float s1 = sinp[t * 64 + lane + 32], c1 = cosp[t * 64 + lane + 32];
    float o0 = n0 * c0 - n1 * s0;
    float o1 = n2 * c1 - n3 * s1;
    float o2 = n0 * s0 + n1 * c0;
    float o3 = n2 * s1 + n3 * c1;

    if (isq) {
        __half h0 = __float2half_rn(o0);
        __half h1 = __float2half_rn(o1);
        __half h2 = __float2half_rn(o2);
        __half h3 = __float2half_rn(o3);
        __half* dhi = Qhi + off;
        __half* dlo = Qlo + off;
        dhi[lane]      = h0;  dlo[lane]      = __float2half_rn(o0 - __half2float(h0));
        dhi[lane + 32] = h1;  dlo[lane + 32] = __float2half_rn(o1 - __half2float(h1));
        dhi[lane + 64] = h2;  dlo[lane + 64] = __float2half_rn(o2 - __half2float(h2));
        dhi[lane + 96] = h3;  dlo[lane + 96] = __float2half_rn(o3 - __half2float(h3));
    } else {
        __half* dhi = Khi + off;
        dhi[lane]      = __float2half_rn(o0);
        dhi[lane + 32] = __float2half_rn(o1);
        dhi[lane + 64] = __float2half_rn(o2);
        dhi[lane + 96] = __float2half_rn(o3);
    }
}

// ---------------------------------------------------------------------------
// Flash attention (FA2-style): 128-row Q tile, 8 warps x 16 rows,
// register-resident softmax + P fragments. Single-buffered K/V, 2 CTAs/SM
// (cross-CTA latency hiding instead of double buffering).
// ---------------------------------------------------------------------------
#define FK_STRB 272                 // bytes per 128-wide fp16 row (136 halves)
#define FQ_TILE (128 * FK_STRB)     // 34816 (one Q array)
#define FKV_TILE (64 * FK_STRB)     // 17408 (one K or V tile)
#define F3_QH 0
#define F3_QL FQ_TILE
#define F3_KV (2 * FQ_TILE)         // K at +0, V at +FKV_TILE
#define FA4_SMEM (2 * FQ_TILE + 2 * FKV_TILE)   // 104448 -> 2 CTAs/SM

__global__ __launch_bounds__(256, 2)
void flash_mma(const __half* __restrict__ Qhi, const __half* __restrict__ Qlo,
               const __half* __restrict__ Khi, const __half* __restrict__ Vhi,
               __half* __restrict__ Ohi, __half* __restrict__ Olo) {
    extern __shared__ char sm[];
    const uint32_t sb = smem_to_u32(sm);

    const int qt = gridDim.x - 1 - blockIdx.x;   // descending work order
    const int bh = blockIdx.y;
    const int b = bh >> 4;
    const int h = bh & 15;
    const int kh = h >> 1;

    const int tid = threadIdx.x;
    const int lane = tid & 31;
    const int wid = tid >> 5;           // warp owns rows wid*16 .. +15
    const int frow = lane >> 2;
    const int fcol = 2 * (lane & 3);
    const float scale = 0.08838834764831845f;  // 1/sqrt(128)

    const int qrow0 = qt * 128 + wid * 16;      // warp's first global q row
    const int ktmax = 2 * qt + 1;

    const __half* qh = Qhi + ((size_t)(b * TT + qt * 128)) * (HH*HD) + h * HD;
    const __half* ql = Qlo + ((size_t)(b * TT + qt * 128)) * (HH*HD) + h * HD;
    const __half* kbase = Khi + ((size_t)(b * TT)) * (KK*HD) + kh * HD;
    const __half* vbase = Vhi + ((size_t)(b * TT)) * (KK*HD) + kh * HD;

    // K/V tile loader (cp.async): 64 rows x 16 segs each for K and V
    auto cp_kv = [&](int kt) {
        uint32_t st = sb + F3_KV;
        const __half* kp = kbase + (size_t)(kt * 64) * (KK*HD);
        const __half* vp = vbase + (size_t)(kt * 64) * (KK*HD);
#pragma unroll
        for (int j = 0; j < 4; ++j) {
            int idx = tid + j * 256;      // 0..1023
            int r = idx >> 4, s = idx & 15;
            uint32_t so = r * FK_STRB + s * 16;
            cp_async16(st + so,            kp + (size_t)r * (KK*HD) + s * 8);
            cp_async16(st + FKV_TILE + so, vp + (size_t)r * (KK*HD) + s * 8);
        }
        cp_commit();
    };

    // Issue Q (hi/lo) + first K/V via cp.async
    {
#pragma unroll
        for (int j = 0; j < 8; ++j) {
            int idx = tid + j * 256;      // 0..2047
            int r = idx >> 4, s = idx & 15;
            uint32_t so = r * FK_STRB + s * 16;
            cp_async16(sb + F3_QH + so, qh + (size_t)r * (HH*HD) + s * 8);
            cp_async16(sb + F3_QL + so, ql + (size_t)r * (HH*HD) + s * 8);
        }
        cp_commit();
        cp_kv(0);
    }

    float o[16][4];
#pragma unroll
    for (int n = 0; n < 16; ++n)
#pragma unroll
        for (int j = 0; j < 4; ++j) o[n][j] = 0.0f;
    float m0 = -INFINITY, m1 = -INFINITY, l0 = 0.0f, l1 = 0.0f;

    for (int kt = 0; kt <= ktmax; ++kt) {
        asm volatile("cp.async.wait_group 0;" ::: "memory");
        __syncthreads();

        const uint32_t kvs = sb + F3_KV;

        // ---- S = Q @ K^T (2-pass: Qhi+Qlo vs Khi), m16 x n64 per warp ----
        float s[8][4];
#pragma unroll
        for (int i = 0; i < 8; ++i)
#pragma unroll
            for (int j = 0; j < 4; ++j) s[i][j] = 0.0f;

#pragma unroll
        for (int ks = 0; ks < 8; ++ks) {
            const uint32_t coff = ks * 32 + (lane >> 4) * 16;
            uint32_t aq[4], aql[4];
            {
                uint32_t addr = sb + F3_QH + (wid * 16 + (lane & 15)) * FK_STRB + coff;
                ldsm_x4(aq[0], aq[1], aq[2], aq[3], addr);
                ldsm_x4(aql[0], aql[1], aql[2], aql[3], addr + FQ_TILE);
            }
            uint32_t kb[4][4];
#pragma unroll
            for (int nb = 0; nb < 4; ++nb) {
                uint32_t addr = kvs + (nb * 16 + (lane & 15)) * FK_STRB + coff;
                ldsm_x4(kb[nb][0], kb[nb][1], kb[nb][2], kb[nb][3], addr);
            }
#pragma unroll
            for (int pass = 0; pass < 2; ++pass) {
                const uint32_t* a = pass ? aql : aq;
#pragma unroll
                for (int nb = 0; nb < 4; ++nb) {
                    mma_f16(s[2*nb],   a, kb[nb][0], kb[nb][2]);
                    mma_f16(s[2*nb+1], a, kb[nb][1], kb[nb][3]);
                }
            }
        }

        // ---- scale + causal mask (registers) ----
        bool boundary = (kt * 64 + 63 > qrow0);
#pragma unroll
        for (int nt = 0; nt < 8; ++nt) {
            int c = kt * 64 + nt * 8 + fcol;
            s[nt][0] *= scale; s[nt][1] *= scale;
            s[nt][2] *= scale; s[nt][3] *= scale;
            if (boundary) {
                int r0 = qrow0 + frow, r1 = r0 + 8;
                if (c     > r0) s[nt][0] = -INFINITY;
                if (c + 1 > r0) s[nt][1] = -INFINITY;
                if (c     > r1) s[nt][2] = -INFINITY;
                if (c + 1 > r1) s[nt][3] = -INFINITY;
            }
        }

        // ---- register online softmax (quad shfl reductions) ----
        float mx0 = -INFINITY, mx1 = -INFINITY;
#pragma unroll
        for (int nt = 0; nt < 8; ++nt) {
            mx0 = fmaxf(mx0, fmaxf(s[nt][0], s[nt][1]));
            mx1 = fmaxf(mx1, fmaxf(s[nt][2], s[nt][3]));
        }
        mx0 = fmaxf(mx0, __shfl_xor_sync(0xFFFFFFFFu, mx0, 1));
        mx0 = fmaxf(mx0, __shfl_xor_sync(0xFFFFFFFFu, mx0, 2));
        mx1 = fmaxf(mx1, __shfl_xor_sync(0xFFFFFFFFu, mx1, 1));
        mx1 = fmaxf(mx1, __shfl_xor_sync(0xFFFFFFFFu, mx1, 2));
        mx0 = fmaxf(mx0, m0);
        mx1 = fmaxf(mx1, m1);
        float a0 = __expf(m0 - mx0);
        float a1 = __expf(m1 - mx1);
        float sum0 = 0.0f, sum1 = 0.0f;
#pragma unroll
        for (int nt = 0; nt < 8; ++nt) {
            s[nt][0] = __expf(s[nt][0] - mx0); sum0 += s[nt][0];
            s[nt][1] = __expf(s[nt][1] - mx0); sum0 += s[nt][1];
            s[nt][2] = __expf(s[nt][2] - mx1); sum1 += s[nt][2];
            s[nt][3] = __expf(s[nt][3] - mx1); sum1 += s[nt][3];
        }
        sum0 += __shfl_xor_sync(0xFFFFFFFFu, sum0, 1);
        sum0 += __shfl_xor_sync(0xFFFFFFFFu, sum0, 2);
        sum1 += __shfl_xor_sync(0xFFFFFFFFu, sum1, 1);
        sum1 += __shfl_xor_sync(0xFFFFFFFFu, sum1, 2);
        l0 = l0 * a0 + sum0;  m0 = mx0;
        l1 = l1 * a1 + sum1;  m1 = mx1;

        // rescale O
#pragma unroll
        for (int nt = 0; nt < 16; ++nt) {
            o[nt][0] *= a0; o[nt][1] *= a0;
            o[nt][2] *= a1; o[nt][3] *= a1;
        }

        // ---- O += (Phi + Plo) @ Vhi ; P fragments built from s registers ----
#pragma unroll
        for (int j = 0; j < 4; ++j) {            // k16 step within the 64 K-rows
            uint32_t ap[4], apl[4];
            {
                __half ph[8], pl[8];
#pragma unroll
                for (int e = 0; e < 4; ++e) {
                    float v0 = s[2*j][e];
                    float v1 = s[2*j+1][e];
                    ph[e]     = __float2half_rn(v0);
                    ph[4 + e] = __float2half_rn(v1);
                    pl[e]     = __float2half_rn(v0 - __half2float(ph[e]));
                    pl[4 + e] = __float2half_rn(v1 - __half2float(ph[4 + e]));
                }
                ap[0]  = pack_half2(ph[0], ph[1]);
                ap[1]  = pack_half2(ph[2], ph[3]);
                ap[2]  = pack_half2(ph[4], ph[5]);
                ap[3]  = pack_half2(ph[6], ph[7]);
                apl[0] = pack_half2(pl[0], pl[1]);
                apl[1] = pack_half2(pl[2], pl[3]);
                apl[2] = pack_half2(pl[4], pl[5]);
                apl[3] = pack_half2(pl[6], pl[7]);
            }
#pragma unroll
            for (int g = 0; g < 2; ++g) {
                uint32_t vh[4][4];
#pragma unroll
                for (int q = 0; q < 4; ++q) {
                    int nb = g * 4 + q;
                    uint32_t addr = kvs + FKV_TILE
                                  + (j * 16 + (lane & 15)) * FK_STRB
                                  + (nb * 16 + (lane >> 4) * 8) * 2;
                    ldsm_x4_trans(vh[q][0], vh[q][1], vh[q][2], vh[q][3], addr);
                }
#pragma unroll
                for (int q = 0; q < 4; ++q) {
                    int nb = g * 4 + q;
                    mma_f16(o[2*nb],   ap, vh[q][0], vh[q][1]);
                    mma_f16(o[2*nb+1], ap, vh[q][2], vh[q][3]);
                }
#pragma unroll
                for (int q = 0; q < 4; ++q) {
                    int nb = g * 4 + q;
                    mma_f16(o[2*nb],   apl, vh[q][0], vh[q][1]);
                    mma_f16(o[2*nb+1], apl, vh[q][2], vh[q][3]);
                }
            }
        }

        // single-buffered K/V: all warps done -> issue next tile
        if (kt < ktmax) {
            __syncthreads();
            cp_kv(kt + 1);
        }
    }

    // Epilogue: normalize by 1/l, write fp16 hi/lo (b,t,h,d)
    {
        float li0 = 1.0f / l0;
        float li1 = 1.0f / l1;
        int r0g = b * TT + qt * 128 + wid * 16 + frow;
#pragma unroll
        for (int nt = 0; nt < 16; ++nt) {
            int c = nt * 8 + fcol;
            size_t o0 = (size_t)r0g * (HH*HD) + h * HD + c;
            size_t o1 = (size_t)(r0g + 8) * (HH*HD) + h * HD + c;
            float v00 = o[nt][0] * li0, v01 = o[nt][1] * li0;
            float v10 = o[nt][2] * li1, v11 = o[nt][3] * li1;
            __half h00 = __float2half_rn(v00);
            __half h01 = __float2half_rn(v01);
            __half h10 = __float2half_rn(v10);
            __half h11 = __float2half_rn(v11);
            Ohi[o0] = h00; Ohi[o0 + 1] = h01;
            Ohi[o1] = h10; Ohi[o1 + 1] = h11;
            Olo[o0]     = __float2half_rn(v00 - __half2float(h00));
            Olo[o0 + 1] = __float2half_rn(v01 - __half2float(h01));
            Olo[o1]     = __float2half_rn(v10 - __half2float(h10));
            Olo[o1 + 1] = __float2half_rn(v11 - __half2float(h11));
        }
    }
}

// ---------------------------------------------------------------------------
extern "C" void kernel_launch(void* const* d_in, const int* in_sizes, int n_in,
                              void* d_out, int out_size) {
    const float* x    = (const float*)d_in[0];
    const float* Wq   = (const float*)d_in[1];
    const float* Wk   = (const float*)d_in[2];
    const float* Wv   = (const float*)d_in[3];
    const float* Wo   = (const float*)d_in[4];
    const float* qn   = (const float*)d_in[5];
    const float* kn   = (const float*)d_in[6];
    const float* sinp = (const float*)d_in[7];
    const float* cosp = (const float*)d_in[8];
    float* out = (float*)d_out;

    __half *xhi, *xlo, *wqt, *wkt, *wvt, *wot;
    __half *qhi, *qlo, *khi, *vhi, *ohi, *olo;
    float *qr, *kr;
    cudaGetSymbolAddress((void**)&xhi, g_xhi);
    cudaGetSymbolAddress((void**)&xlo, g_xlo);
    cudaGetSymbolAddress((void**)&wqt, g_wqt);
    cudaGetSymbolAddress((void**)&wkt, g_wkt);
    cudaGetSymbolAddress((void**)&wvt, g_wvt);
    cudaGetSymbolAddress((void**)&wot, g_wot);
    cudaGetSymbolAddress((void**)&qr, g_q_raw);
    cudaGetSymbolAddress((void**)&kr, g_k_raw);
    cudaGetSymbolAddress((void**)&qhi, g_qhi);
    cudaGetSymbolAddress((void**)&qlo, g_qlo);
    cudaGetSymbolAddress((void**)&khi, g_khi);
    cudaGetSymbolAddress((void**)&vhi, g_vhi);
    cudaGetSymbolAddress((void**)&ohi, g_ohi);
    cudaGetSymbolAddress((void**)&olo, g_olo);

    // 1. split-convert x
    convert_split_kernel<<<(MTOT * DD / 4 + 255) / 256, 256>>>(x, xhi, xlo, MTOT * DD / 4);

    // 2. transpose weights to fp16 (hi only)
    transpose_half_kernel<<<dim3((HH*HD)/32, DD/32), 256>>>(Wq, wqt, DD, HH*HD);
    transpose_half_kernel<<<dim3((KK*HD)/32, DD/32), 256>>>(Wk, wkt, DD, KK*HD);
    transpose_half_kernel<<<dim3((KK*HD)/32, DD/32), 256>>>(Wv, wvt, DD, KK*HD);
    transpose_half_kernel<<<dim3((HH*HD)/32, (HH*HD)/32), 256>>>(Wo, wot, HH*HD, HH*HD);

    // 3. fused QKV projection (Q 2-pass; K/V 1-pass; V -> fp16 direct)
    cudaFuncSetAttribute(gemm_qkv, cudaFuncAttributeMaxDynamicSharedMemorySize, GSMEM_DYN);
    gemm_qkv<<<dim3(32, MTOT/128), 256, GSMEM_DYN>>>(xhi, xlo, wqt, wkt, wvt, qr, kr, vhi);

    // 4. RMSNorm + RoPE -> q hi/lo, k hi
    normrope_kernel<<<12288, 256>>>(qr, kr, qhi, qlo, khi, qn, kn, sinp, cosp);

    // 5. causal flash attention (single-buffer K/V, 2 CTAs/SM)
    cudaFuncSetAttribute(flash_mma, cudaFuncAttributeMaxDynamicSharedMemorySize, FA4_SMEM);
    flash_mma<<<dim3(TT / 128, BB * HH), 256, FA4_SMEM>>>(qhi, qlo, khi, vhi, ohi, olo);

    // 6. output projection (fp16 2-pass, cp.async pipeline)
    cudaFuncSetAttribute(gemm_mma, cudaFuncAttributeMaxDynamicSharedMemorySize, GSMEM_DYN);
    gemm_mma<<<dim3((HH*HD)/128, MTOT/128), 256, GSMEM_DYN>>>(ohi, olo, wot, out, HH*HD, HH*HD);
}

// round 11
// speedup vs baseline: 4.7017x; 1.1477x over previous
#include <cuda_runtime.h>
#include <cuda_fp16.h>
#include <math.h>
#include <cstdint>

// Problem constants
#define BB 2
#define TT 2048
#define DD 2048
#define HH 16
#define KK 8
#define HD 128
#define MTOT (BB*TT)   // 4096

// ---------------------------------------------------------------------------
// Scratch (device globals; no allocation allowed)
// ---------------------------------------------------------------------------
__device__ __half g_xhi [(size_t)MTOT * DD];
__device__ __half g_xlo [(size_t)MTOT * DD];
__device__ __half g_wqt [(size_t)(HH*HD) * DD];
__device__ __half g_wkt [(size_t)(KK*HD) * DD];
__device__ __half g_wvt [(size_t)(KK*HD) * DD];
__device__ __half g_wot [(size_t)DD * (HH*HD)];
__device__ float g_q_raw[(size_t)MTOT * (HH*HD)];
__device__ float g_k_raw[(size_t)MTOT * (KK*HD)];
__device__ __half g_qhi [(size_t)MTOT * (HH*HD)];
__device__ __half g_khi [(size_t)MTOT * (KK*HD)];
__device__ __half g_vhi [(size_t)MTOT * (KK*HD)];
__device__ __half g_ohi [(size_t)MTOT * (HH*HD)];
__device__ __half g_olo [(size_t)MTOT * (HH*HD)];

// ---------------------------------------------------------------------------
// mma.sync / cp.async helpers
// ---------------------------------------------------------------------------
__device__ __forceinline__ uint32_t smem_to_u32(const void* p) {
    uint32_t a;
    asm("{ .reg .u64 t; cvta.to.shared.u64 t, %1; cvt.u32.u64 %0, t; }"
        : "=r"(a) : "l"(p));
    return a;
}

__device__ __forceinline__ uint32_t pack_half2(__half lo, __half hi) {
    return (uint32_t)__half_as_ushort(lo) | ((uint32_t)__half_as_ushort(hi) << 16);
}

__device__ __forceinline__ void ldsm_x4(uint32_t& r0, uint32_t& r1,
                                        uint32_t& r2, uint32_t& r3, uint32_t addr) {
    asm volatile("ldmatrix.sync.aligned.m8n8.x4.shared.b16 {%0,%1,%2,%3}, [%4];"
                 : "=r"(r0), "=r"(r1), "=r"(r2), "=r"(r3) : "r"(addr));
}

__device__ __forceinline__ void ldsm_x4_trans(uint32_t& r0, uint32_t& r1,
                                              uint32_t& r2, uint32_t& r3, uint32_t addr) {
    asm volatile("ldmatrix.sync.aligned.m8n8.x4.trans.shared.b16 {%0,%1,%2,%3}, [%4];"
                 : "=r"(r0), "=r"(r1), "=r"(r2), "=r"(r3) : "r"(addr));
}

__device__ __forceinline__ void mma_f16(float* d, const uint32_t* a,
                                        uint32_t b0, uint32_t b1) {
    asm volatile(
        "mma.sync.aligned.m16n8k16.row.col.f32.f16.f16.f32 "
        "{%0,%1,%2,%3}, {%4,%5,%6,%7}, {%8,%9}, {%0,%1,%2,%3};"
        : "+f"(d[0]), "+f"(d[1]), "+f"(d[2]), "+f"(d[3])
        : "r"(a[0]), "r"(a[1]), "r"(a[2]), "r"(a[3]), "r"(b0), "r"(b1));
}

__device__ __forceinline__ void cp_async16(uint32_t saddr, const void* gaddr) {
    asm volatile("cp.async.cg.shared.global [%0], [%1], 16;"
                 :: "r"(saddr), "l"(gaddr) : "memory");
}
__device__ __forceinline__ void cp_commit() {
    asm volatile("cp.async.commit_group;" ::: "memory");
}

// ---------------------------------------------------------------------------
// Conversion: fp32 -> (fp16 hi, fp16 lo)
// ---------------------------------------------------------------------------
__global__ __launch_bounds__(256)
void convert_split_kernel(const float* __restrict__ X,
                          __half* __restrict__ Hi,
                          __half* __restrict__ Lo, int n4) {
    int i = blockIdx.x * 256 + threadIdx.x;
    if (i >= n4) return;
    float4 v = ((const float4*)X)[i];
    __half h0 = __float2half_rn(v.x), h1 = __float2half_rn(v.y);
    __half h2 = __float2half_rn(v.z), h3 = __float2half_rn(v.w);
    __half l0 = __float2half_rn(v.x - __half2float(h0));
    __half l1 = __float2half_rn(v.y - __half2float(h1));
    __half l2 = __float2half_rn(v.z - __half2float(h2));
    __half l3 = __float2half_rn(v.w - __half2float(h3));
    __half2* hp = (__half2*)(Hi + 4 * (size_t)i);
    __half2* lp = (__half2*)(Lo + 4 * (size_t)i);
    hp[0] = __halves2half2(h0, h1); hp[1] = __halves2half2(h2, h3);
    lp[0] = __halves2half2(l0, l1); lp[1] = __halves2half2(l2, l3);
}

// ---------------------------------------------------------------------------
// Transpose: W[Kd, N] fp32 -> T [N, Kd] fp16 (hi only)
// ---------------------------------------------------------------------------
__global__ __launch_bounds__(256)
void transpose_half_kernel(const float* __restrict__ W,
                           __half* __restrict__ Thi, int Kd, int N) {
    __shared__ float tile[32][33];
    int n0 = blockIdx.x * 32, k0 = blockIdx.y * 32;
    int tx = threadIdx.x & 31, ty = threadIdx.x >> 5;
#pragma unroll
    for (int r = ty; r < 32; r += 8)
        tile[r][tx] = W[(size_t)(k0 + r) * N + n0 + tx];
    __syncthreads();
#pragma unroll
    for (int r = ty; r < 32; r += 8)
        Thi[(size_t)(n0 + r) * Kd + k0 + tx] = __float2half_rn(tile[tx][r]);
}

// ---------------------------------------------------------------------------
// fp16 GEMM with cp.async 3-stage pipeline. use_lo selects 2-pass (A hi+lo)
// or 1-pass (A hi only) accumulation.
// ---------------------------------------------------------------------------
#define GPAD 40
#define GTILE_BYTES (128 * GPAD * 2)      // 10240
#define GSTAGE_BYTES (3 * GTILE_BYTES)    // 30720 (Ahi, Alo, Bhi)
#define GSMEM_DYN (3 * GSTAGE_BYTES)      // 92160 (3 stages)

__device__ __forceinline__ void gemm_core(
    const __half* __restrict__ Ahi, const __half* __restrict__ Alo,
    const __half* __restrict__ Bhi,
    float* __restrict__ C, __half* __restrict__ Ch,
    int N, int Kd, int row0, int col0, char* smg, bool use_lo) {
    const uint32_t sbase0 = smem_to_u32(smg);

    const int tid = threadIdx.x;
    const int lane = tid & 31;
    const int wid = tid >> 5;
    const int wr = wid & 3;
    const int wc = wid >> 2;

    float d[2][8][4];
#pragma unroll
    for (int m = 0; m < 2; ++m)
#pragma unroll
        for (int n = 0; n < 8; ++n)
#pragma unroll
            for (int j = 0; j < 4; ++j) d[m][n][j] = 0.0f;

    const __half* gb[3] = {Ahi, Alo, Bhi};
    int grow[6], gseg[6];
#pragma unroll
    for (int a = 0; a < 3; ++a) {
        int r0 = (a < 2) ? row0 : col0;
        int s0 = tid, s1 = tid + 256;
        grow[2*a]   = r0 + (s0 >> 2); gseg[2*a]   = s0 & 3;
        grow[2*a+1] = r0 + (s1 >> 2); gseg[2*a+1] = s1 & 3;
    }

    auto cp_chunk = [&](int k0, int stage) {
        uint32_t st = sbase0 + stage * GSTAGE_BYTES;
#pragma unroll
        for (int a = 0; a < 3; ++a) {
            if (a == 1 && !use_lo) continue;
#pragma unroll
            for (int j = 0; j < 2; ++j) {
                int e = 2 * a + j;
                int s = tid + j * 256;
                uint32_t sa = st + a * GTILE_BYTES + (s >> 2) * (GPAD*2) + (s & 3) * 16;
                cp_async16(sa, gb[a] + (size_t)grow[e] * Kd + k0 + gseg[e] * 8);
            }
        }
        cp_commit();
    };

    const int NC = Kd / 32;

    cp_chunk(0, 0);
    cp_chunk(32, 1);

    for (int c = 0; c < NC; ++c) {
        if (c + 1 < NC) asm volatile("cp.async.wait_group 1;" ::: "memory");
        else            asm volatile("cp.async.wait_group 0;" ::: "memory");
        __syncthreads();

        if (c + 2 < NC) cp_chunk((c + 2) * 32, (c + 2) % 3);

        const uint32_t sb = sbase0 + (c % 3) * GSTAGE_BYTES;
#pragma unroll
        for (int ks = 0; ks < 2; ++ks) {
            const uint32_t coff = ks * 32 + (lane >> 4) * 16;
            uint32_t ah[2][4], al[2][4];
#pragma unroll
            for (int mb = 0; mb < 2; ++mb) {
                uint32_t addr = sb + (wr * 32 + mb * 16 + (lane & 15)) * (GPAD*2) + coff;
                ldsm_x4(ah[mb][0], ah[mb][1], ah[mb][2], ah[mb][3], addr);
                if (use_lo)
                    ldsm_x4(al[mb][0], al[mb][1], al[mb][2], al[mb][3], addr + GTILE_BYTES);
            }
            uint32_t bh[4][4];
#pragma unroll
            for (int nb = 0; nb < 4; ++nb) {
                uint32_t addr = sb + 2 * GTILE_BYTES +
                                (wc * 64 + nb * 16 + (lane & 15)) * (GPAD*2) + coff;
                ldsm_x4(bh[nb][0], bh[nb][1], bh[nb][2], bh[nb][3], addr);
            }
#pragma unroll
            for (int mb = 0; mb < 2; ++mb) {
#pragma unroll
                for (int nb = 0; nb < 4; ++nb) {
                    mma_f16(d[mb][2*nb],   ah[mb], bh[nb][0], bh[nb][2]);
                    mma_f16(d[mb][2*nb+1], ah[mb], bh[nb][1], bh[nb][3]);
                }
            }
            if (use_lo) {
#pragma unroll
                for (int mb = 0; mb < 2; ++mb) {
#pragma unroll
                    for (int nb = 0; nb < 4; ++nb) {
                        mma_f16(d[mb][2*nb],   al[mb], bh[nb][0], bh[nb][2]);
                        mma_f16(d[mb][2*nb+1], al[mb], bh[nb][1], bh[nb][3]);
                    }
                }
            }
        }
    }

    const int frow = lane >> 2;
    const int fcol = 2 * (lane & 3);
#pragma unroll
    for (int mb = 0; mb < 2; ++mb) {
#pragma unroll
        for (int nt = 0; nt < 8; ++nt) {
            int r = row0 + wr * 32 + mb * 16 + frow;
            int cc = col0 + wc * 64 + nt * 8 + fcol;
            if (Ch) {
                *(__half2*)&Ch[(size_t)r * N + cc] =
                    __halves2half2(__float2half_rn(d[mb][nt][0]), __float2half_rn(d[mb][nt][1]));
                *(__half2*)&Ch[(size_t)(r + 8) * N + cc] =
                    __halves2half2(__float2half_rn(d[mb][nt][2]), __float2half_rn(d[mb][nt][3]));
            } else {
                *(float2*)&C[(size_t)r * N + cc]       = make_float2(d[mb][nt][0], d[mb][nt][1]);
                *(float2*)&C[(size_t)(r + 8) * N + cc] = make_float2(d[mb][nt][2], d[mb][nt][3]);
            }
        }
    }
}

__global__ __launch_bounds__(256, 2)
void gemm_mma(const __half* __restrict__ Ahi, const __half* __restrict__ Alo,
              const __half* __restrict__ Bhi,
              float* __restrict__ C, int N, int Kd) {
    extern __shared__ char smg[];
    gemm_core(Ahi, Alo, Bhi, C, nullptr, N, Kd, blockIdx.y * 128, blockIdx.x * 128, smg, true);
}

// Fused QKV: Q col-tiles 2-pass; K/V col-tiles 1-pass (output rounds to fp16 anyway)
__global__ __launch_bounds__(256, 2)
void gemm_qkv(const __half* __restrict__ Xhi, const __half* __restrict__ Xlo,
              const __half* __restrict__ Wq, const __half* __restrict__ Wk,
              const __half* __restrict__ Wv,
              float* __restrict__ Q, float* __restrict__ Kc, __half* __restrict__ Vh) {
    extern __shared__ char smg[];
    int ct = blockIdx.x;
    if (ct < 16) {
        gemm_core(Xhi, Xlo, Wq, Q, nullptr, HH*HD, DD, blockIdx.y * 128, ct * 128, smg, true);
    } else if (ct < 24) {
        gemm_core(Xhi, Xlo, Wk, Kc, nullptr, KK*HD, DD, blockIdx.y * 128, (ct - 16) * 128, smg, false);
    } else {
        gemm_core(Xhi, Xlo, Wv, nullptr, Vh, KK*HD, DD, blockIdx.y * 128, (ct - 24) * 128, smg, false);
    }
}

// ---------------------------------------------------------------------------
// Fused RMSNorm + RoPE. q -> fp16 hi; k -> fp16 hi.
// ---------------------------------------------------------------------------
__global__ __launch_bounds__(256)
void normrope_kernel(const float* __restrict__ q, const float* __restrict__ k,
                     __half* __restrict__ Qhi, __half* __restrict__ Khi,
                     const float* __restrict__ qn, const float* __restrict__ kn,
                     const float* __restrict__ sinp, const float* __restrict__ cosp) {
    int warp = (blockIdx.x * blockDim.x + threadIdx.x) >> 5;
    int lane = threadIdx.x & 31;
    const int NQ = MTOT * HH;
    const int NTOT = NQ + MTOT * KK;
    if (warp >= NTOT) return;

    const float* ptr;
    const float* w;
    int t;
    bool isq = warp < NQ;
    size_t off;
    if (isq) {
        int bt = warp >> 4;
        int h = warp & 15;
        off = (size_t)bt * (HH * HD) + h * HD;
        ptr = q + off;
        w = qn;
        t = bt & (TT - 1);
    } else {
        int v2 = warp - NQ;
        int bt = v2 >> 3;
        int kh = v2 & 7;
        off = (size_t)bt * (KK * HD) + kh * HD;
        ptr = k + off;
        w = kn;
        t = bt & (TT - 1);
    }

    float2 a  = *(const float2*)(ptr + 2 * lane);
    float2 b2 = *(const float2*)(ptr + 64 + 2 * lane);

    float ss = a.x * a.x + a.y * a.y + b2.x * b2.x + b2.y * b2.y;
#pragma unroll
    for (int o = 16; o; o >>= 1) ss += __shfl_xor_sync(0xFFFFFFFFu, ss, o);
    float rinv = rsqrtf(ss * (1.0f / 128.0f) + 1e-6f);

    float w0 = w[2 * lane], w1 = w[2 * lane + 1];
    float w2 = w[64 + 2 * lane], w3 = w[65 + 2 * lane];
    float n0 = a.x * rinv * w0, n1 = a.y * rinv * w1;
    float n2 = b2.x * rinv * w2, n3 = b2.y * rinv * w3;

    float s0 = sinp[t * 64 + lane],      c0 = cosp[t * 64 + lane];
    float s1 = sinp[t * 64 + lane + 32], c1 = cosp[t * 64 + lane + 32];
    float o0 = n0 * c0 - n1 * s0;
    float o1 = n2 * c1 - n3 * s1;
    float o2 = n0 * s0 + n1 * c0;
    float o3 = n2 * s1 + n3 * c1;

    __half* dhi = (isq ? Qhi : Khi) + off;
    dhi[lane]      = __float2half_rn(o0);
    dhi[lane + 32] = __float2half_rn(o1);
    dhi[lane + 64] = __float2half_rn(o2);
    dhi[lane + 96] = __float2half_rn(o3);
}

// ---------------------------------------------------------------------------
// Flash attention: pure-fp16 mma (fp32 softmax/accum), 128-row Q tile,
// 8 warps x 16 rows, register softmax + P fragments, double-buffered K/V,
// ONE barrier per K-tile, 2 CTAs/SM.
// ---------------------------------------------------------------------------
#define FK_STRB 272                 // bytes per 128-wide fp16 row (136 halves)
#define FQ_TILE (128 * FK_STRB)     // 34816
#define FKV_TILE (64 * FK_STRB)     // 17408
#define F4_Q 0
#define F4_KV FQ_TILE               // stage s: K at +s*2*FKV_TILE, V at +FKV_TILE
#define FA5_SMEM (FQ_TILE + 2 * 2 * FKV_TILE)   // 104448 -> 2 CTAs/SM

__global__ __launch_bounds__(256, 2)
void flash_mma(const __half* __restrict__ Qhi,
               const __half* __restrict__ Khi, const __half* __restrict__ Vhi,
               __half* __restrict__ Ohi, __half* __restrict__ Olo) {
    extern __shared__ char sm[];
    const uint32_t sb = smem_to_u32(sm);

    const int qt = gridDim.x - 1 - blockIdx.x;   // descending work order
    const int bh = blockIdx.y;
    const int b = bh >> 4;
    const int h = bh & 15;
    const int kh = h >> 1;

    const int tid = threadIdx.x;
    const int lane = tid & 31;
    const int wid = tid >> 5;           // warp owns rows wid*16 .. +15
    const int frow = lane >> 2;
    const int fcol = 2 * (lane & 3);
    const float scale = 0.08838834764831845f;  // 1/sqrt(128)

    const int qrow0 = qt * 128 + wid * 16;
    const int ktmax = 2 * qt + 1;

    const __half* qh = Qhi + ((size_t)(b * TT + qt * 128)) * (HH*HD) + h * HD;
    const __half* kbase = Khi + ((size_t)(b * TT)) * (KK*HD) + kh * HD;
    const __half* vbase = Vhi + ((size_t)(b * TT)) * (KK*HD) + kh * HD;

    // K/V tile loader (cp.async): 64 rows x 16 segs each for K and V
    auto cp_kv = [&](int kt, int stage) {
        uint32_t st = sb + F4_KV + stage * 2 * FKV_TILE;
        const __half* kp = kbase + (size_t)(kt * 64) * (KK*HD);
        const __half* vp = vbase + (size_t)(kt * 64) * (KK*HD);
#pragma unroll
        for (int j = 0; j < 4; ++j) {
            int idx = tid + j * 256;      // 0..1023
            int r = idx >> 4, s = idx & 15;
            uint32_t so = r * FK_STRB + s * 16;
            cp_async16(st + so,            kp + (size_t)r * (KK*HD) + s * 8);
            cp_async16(st + FKV_TILE + so, vp + (size_t)r * (KK*HD) + s * 8);
        }
        cp_commit();
    };

    // Prologue: Q tile + first K/V
    {
#pragma unroll
        for (int j = 0; j < 8; ++j) {
            int idx = tid + j * 256;      // 0..2047
            int r = idx >> 4, s = idx & 15;
            cp_async16(sb + F4_Q + r * FK_STRB + s * 16,
                       qh + (size_t)r * (HH*HD) + s * 8);
        }
        cp_commit();
        cp_kv(0, 0);
    }

    float o[16][4];
#pragma unroll
    for (int n = 0; n < 16; ++n)
#pragma unroll
        for (int j = 0; j < 4; ++j) o[n][j] = 0.0f;
    float m0 = -INFINITY, m1 = -INFINITY, l0 = 0.0f, l1 = 0.0f;

    for (int kt = 0; kt <= ktmax; ++kt) {
        // all outstanding groups = kv(kt) (+Q on kt==0): wait, then barrier.
        asm volatile("cp.async.wait_group 0;" ::: "memory");
        __syncthreads();
        // Stage (kt+1)&1 was fully consumed in iteration kt-1 (the barrier
        // above proves every warp finished it), so prefetch is safe and
        // overlaps this iteration's compute.
        if (kt < ktmax) cp_kv(kt + 1, (kt + 1) & 1);

        const uint32_t kvs = sb + F4_KV + (kt & 1) * 2 * FKV_TILE;

        // ---- S = Qhi @ Khi^T, m16 x n64 per warp ----
        float s[8][4];
#pragma unroll
        for (int i = 0; i < 8; ++i)
#pragma unroll
            for (int j = 0; j < 4; ++j) s[i][j] = 0.0f;

#pragma unroll
        for (int ks = 0; ks < 8; ++ks) {
            const uint32_t coff = ks * 32 + (lane >> 4) * 16;
            uint32_t aq[4];
            {
                uint32_t addr = sb + F4_Q + (wid * 16 + (lane & 15)) * FK_STRB + coff;
                ldsm_x4(aq[0], aq[1], aq[2], aq[3], addr);
            }
            uint32_t kb[4][4];
#pragma unroll
            for (int nb = 0; nb < 4; ++nb) {
                uint32_t addr = kvs + (nb * 16 + (lane & 15)) * FK_STRB + coff;
                ldsm_x4(kb[nb][0], kb[nb][1], kb[nb][2], kb[nb][3], addr);
            }
#pragma unroll
            for (int nb = 0; nb < 4; ++nb) {
                mma_f16(s[2*nb],   aq, kb[nb][0], kb[nb][2]);
                mma_f16(s[2*nb+1], aq, kb[nb][1], kb[nb][3]);
            }
        }

        // ---- scale + causal mask (registers) ----
        bool boundary = (kt * 64 + 63 > qrow0);
#pragma unroll
        for (int nt = 0; nt < 8; ++nt) {
            int c = kt * 64 + nt * 8 + fcol;
            s[nt][0] *= scale; s[nt][1] *= scale;
            s[nt][2] *= scale; s[nt][3] *= scale;
            if (boundary) {
                int r0 = qrow0 + frow, r1 = r0 + 8;
                if (c     > r0) s[nt][0] = -INFINITY;
                if (c + 1 > r0) s[nt][1] = -INFINITY;
                if (c     > r1) s[nt][2] = -INFINITY;
                if (c + 1 > r1) s[nt][3] = -INFINITY;
            }
        }

        // ---- register online softmax (quad shfl reductions) ----
        float mx0 = -INFINITY, mx1 = -INFINITY;
#pragma unroll
        for (int nt = 0; nt < 8; ++nt) {
            mx0 = fmaxf(mx0, fmaxf(s[nt][0], s[nt][1]));
            mx1 = fmaxf(mx1, fmaxf(s[nt][2], s[nt][3]));
        }
        mx0 = fmaxf(mx0, __shfl_xor_sync(0xFFFFFFFFu, mx0, 1));
        mx0 = fmaxf(mx0, __shfl_xor_sync(0xFFFFFFFFu, mx0, 2));
        mx1 = fmaxf(mx1, __shfl_xor_sync(0xFFFFFFFFu, mx1, 1));
        mx1 = fmaxf(mx1, __shfl_xor_sync(0xFFFFFFFFu, mx1, 2));
        mx0 = fmaxf(mx0, m0);
        mx1 = fmaxf(mx1, m1);
        float a0 = __expf(m0 - mx0);
        float a1 = __expf(m1 - mx1);
        float sum0 = 0.0f, sum1 = 0.0f;
#pragma unroll
        for (int nt = 0; nt < 8; ++nt) {
            s[nt][0] = __expf(s[nt][0] - mx0); sum0 += s[nt][0];
            s[nt][1] = __expf(s[nt][1] - mx0); sum0 += s[nt][1];
            s[nt][2] = __expf(s[nt][2] - mx1); sum1 += s[nt][2];
            s[nt][3] = __expf(s[nt][3] - mx1); sum1 += s[nt][3];
        }
        sum0 += __shfl_xor_sync(0xFFFFFFFFu, sum0, 1);
        sum0 += __shfl_xor_sync(0xFFFFFFFFu, sum0, 2);
        sum1 += __shfl_xor_sync(0xFFFFFFFFu, sum1, 1);
        sum1 += __shfl_xor_sync(0xFFFFFFFFu, sum1, 2);
        l0 = l0 * a0 + sum0;  m0 = mx0;
        l1 = l1 * a1 + sum1;  m1 = mx1;

        // rescale O
#pragma unroll
        for (int nt = 0; nt < 16; ++nt) {
            o[nt][0] *= a0; o[nt][1] *= a0;
            o[nt][2] *= a1; o[nt][3] *= a1;
        }

        // ---- O += Phi @ Vhi ; P fragments built from s registers ----
#pragma unroll
        for (int j = 0; j < 4; ++j) {            // k16 step within the 64 K-rows
            uint32_t ap[4];
            {
                __half ph[8];
#pragma unroll
                for (int e = 0; e < 4; ++e) {
                    ph[e]     = __float2half_rn(s[2*j][e]);
                    ph[4 + e] = __float2half_rn(s[2*j+1][e]);
                }
                ap[0] = pack_half2(ph[0], ph[1]);
                ap[1] = pack_half2(ph[2], ph[3]);
                ap[2] = pack_half2(ph[4], ph[5]);
                ap[3] = pack_half2(ph[6], ph[7]);
            }
#pragma unroll
            for (int g = 0; g < 2; ++g) {
                uint32_t vh[4][4];
#pragma unroll
                for (int q = 0; q < 4; ++q) {
                    int nb = g * 4 + q;
                    uint32_t addr = kvs + FKV_TILE
                                  + (j * 16 + (lane & 15)) * FK_STRB
                                  + (nb * 16 + (lane >> 4) * 8) * 2;
                    ldsm_x4_trans(vh[q][0], vh[q][1], vh[q][2], vh[q][3], addr);
                }
#pragma unroll
                for (int q = 0; q < 4; ++q) {
                    int nb = g * 4 + q;
                    mma_f16(o[2*nb],   ap, vh[q][0], vh[q][1]);
                    mma_f16(o[2*nb+1], ap, vh[q][2], vh[q][3]);
                }
            }
        }
    }

    // Epilogue: normalize by 1/l, write fp16 hi/lo (b,t,h,d)
    {
        float li0 = 1.0f / l0;
        float li1 = 1.0f / l1;
        int r0g = b * TT + qt * 128 + wid * 16 + frow;
#pragma unroll
        for (int nt = 0; nt < 16; ++nt) {
            int c = nt * 8 + fcol;
            size_t o0 = (size_t)r0g * (HH*HD) + h * HD + c;
            size_t o1 = (size_t)(r0g + 8) * (HH*HD) + h * HD + c;
            float v00 = o[nt][0] * li0, v01 = o[nt][1] * li0;
            float v10 = o[nt][2] * li1, v11 = o[nt][3] * li1;
            __half h00 = __float2half_rn(v00);
            __half h01 = __float2half_rn(v01);
            __half h10 = __float2half_rn(v10);
            __half h11 = __float2half_rn(v11);
            Ohi[o0] = h00; Ohi[o0 + 1] = h01;
            Ohi[o1] = h10; Ohi[o1 + 1] = h11;
            Olo[o0]     = __float2half_rn(v00 - __half2float(h00));
            Olo[o0 + 1] = __float2half_rn(v01 - __half2float(h01));
            Olo[o1]     = __float2half_rn(v10 - __half2float(h10));
            Olo[o1 + 1] = __float2half_rn(v11 - __half2float(h11));
        }
    }
}

// ---------------------------------------------------------------------------
extern "C" void kernel_launch(void* const* d_in, const int* in_sizes, int n_in,
                              void* d_out, int out_size) {
    const float* x    = (const float*)d_in[0];
    const float* Wq   = (const float*)d_in[1];
    const float* Wk   = (const float*)d_in[2];
    const float* Wv   = (const float*)d_in[3];
    const float* Wo   = (const float*)d_in[4];
    const float* qn   = (const float*)d_in[5];
    const float* kn   = (const float*)d_in[6];
    const float* sinp = (const float*)d_in[7];
    const float* cosp = (const float*)d_in[8];
    float* out = (float*)d_out;

    __half *xhi, *xlo, *wqt, *wkt, *wvt, *wot;
    __half *qhi, *khi, *vhi, *ohi, *olo;
    float *qr, *kr;
    cudaGetSymbolAddress((void**)&xhi, g_xhi);
    cudaGetSymbolAddress((void**)&xlo, g_xlo);
    cudaGetSymbolAddress((void**)&wqt, g_wqt);
    cudaGetSymbolAddress((void**)&wkt, g_wkt);
    cudaGetSymbolAddress((void**)&wvt, g_wvt);
    cudaGetSymbolAddress((void**)&wot, g_wot);
    cudaGetSymbolAddress((void**)&qr, g_q_raw);
    cudaGetSymbolAddress((void**)&kr, g_k_raw);
    cudaGetSymbolAddress((void**)&qhi, g_qhi);
    cudaGetSymbolAddress((void**)&khi, g_khi);
    cudaGetSymbolAddress((void**)&vhi, g_vhi);
    cudaGetSymbolAddress((void**)&ohi, g_ohi);
    cudaGetSymbolAddress((void**)&olo, g_olo);

    // 1. split-convert x
    convert_split_kernel<<<(MTOT * DD / 4 + 255) / 256, 256>>>(x, xhi, xlo, MTOT * DD / 4);

    // 2. transpose weights to fp16 (hi only)
    transpose_half_kernel<<<dim3((HH*HD)/32, DD/32), 256>>>(Wq, wqt, DD, HH*HD);
    transpose_half_kernel<<<dim3((KK*HD)/32, DD/32), 256>>>(Wk, wkt, DD, KK*HD);
    transpose_half_kernel<<<dim3((KK*HD)/32, DD/32), 256>>>(Wv, wvt, DD, KK*HD);
    transpose_half_kernel<<<dim3((HH*HD)/32, (HH*HD)/32), 256>>>(Wo, wot, HH*HD, HH*HD);

    // 3. fused QKV projection (Q 2-pass; K/V 1-pass; V -> fp16 direct)
    cudaFuncSetAttribute(gemm_qkv, cudaFuncAttributeMaxDynamicSharedMemorySize, GSMEM_DYN);
    gemm_qkv<<<dim3(32, MTOT/128), 256, GSMEM_DYN>>>(xhi, xlo, wqt, wkt, wvt, qr, kr, vhi);

    // 4. RMSNorm + RoPE -> q hi, k hi
    normrope_kernel<<<12288, 256>>>(qr, kr, qhi, khi, qn, kn, sinp, cosp);

    // 5. causal flash attention (pure-fp16 mma, double-buffered, 2 CTAs/SM)
    cudaFuncSetAttribute(flash_mma, cudaFuncAttributeMaxDynamicSharedMemorySize, FA5_SMEM);
    flash_mma<<<dim3(TT / 128, BB * HH), 256, FA5_SMEM>>>(qhi, khi, vhi, ohi, olo);

    // 6. output projection (fp16 2-pass, cp.async pipeline)
    cudaFuncSetAttribute(gemm_mma, cudaFuncAttributeMaxDynamicSharedMemorySize, GSMEM_DYN);
    gemm_mma<<<dim3((HH*HD)/128, MTOT/128), 256, GSMEM_DYN>>>(ohi, olo, wot, out, HH*HD, HH*HD);
}

// round 12
// speedup vs baseline: 6.6857x; 1.4220x over previous
#include <cuda_runtime.h>
#include <cuda_fp16.h>
#include <math.h>
#include <cstdint>

// Problem constants
#define BB 2
#define TT 2048
#define DD 2048
#define HH 16
#define KK 8
#define HD 128
#define MTOT (BB*TT)   // 4096

// ---------------------------------------------------------------------------
// Scratch (device globals; no allocation allowed)
// ---------------------------------------------------------------------------
__device__ __half g_xhi [(size_t)MTOT * DD];
__device__ __half g_wqt [(size_t)(HH*HD) * DD];
__device__ __half g_wkt [(size_t)(KK*HD) * DD];
__device__ __half g_wvt [(size_t)(KK*HD) * DD];
__device__ __half g_wot [(size_t)DD * (HH*HD)];
__device__ float g_q_raw[(size_t)MTOT * (HH*HD)];
__device__ float g_k_raw[(size_t)MTOT * (KK*HD)];
__device__ __half g_qhi [(size_t)MTOT * (HH*HD)];
__device__ __half g_khi [(size_t)MTOT * (KK*HD)];
__device__ __half g_vhi [(size_t)MTOT * (KK*HD)];
__device__ __half g_ohi [(size_t)MTOT * (HH*HD)];

// ---------------------------------------------------------------------------
// mma.sync / cp.async helpers
// ---------------------------------------------------------------------------
__device__ __forceinline__ uint32_t smem_to_u32(const void* p) {
    uint32_t a;
    asm("{ .reg .u64 t; cvta.to.shared.u64 t, %1; cvt.u32.u64 %0, t; }"
        : "=r"(a) : "l"(p));
    return a;
}

__device__ __forceinline__ uint32_t pack_half2(__half lo, __half hi) {
    return (uint32_t)__half_as_ushort(lo) | ((uint32_t)__half_as_ushort(hi) << 16);
}

__device__ __forceinline__ void ldsm_x4(uint32_t& r0, uint32_t& r1,
                                        uint32_t& r2, uint32_t& r3, uint32_t addr) {
    asm volatile("ldmatrix.sync.aligned.m8n8.x4.shared.b16 {%0,%1,%2,%3}, [%4];"
                 : "=r"(r0), "=r"(r1), "=r"(r2), "=r"(r3) : "r"(addr));
}

__device__ __forceinline__ void ldsm_x4_trans(uint32_t& r0, uint32_t& r1,
                                              uint32_t& r2, uint32_t& r3, uint32_t addr) {
    asm volatile("ldmatrix.sync.aligned.m8n8.x4.trans.shared.b16 {%0,%1,%2,%3}, [%4];"
                 : "=r"(r0), "=r"(r1), "=r"(r2), "=r"(r3) : "r"(addr));
}

__device__ __forceinline__ void mma_f16(float* d, const uint32_t* a,
                                        uint32_t b0, uint32_t b1) {
    asm volatile(
        "mma.sync.aligned.m16n8k16.row.col.f32.f16.f16.f32 "
        "{%0,%1,%2,%3}, {%4,%5,%6,%7}, {%8,%9}, {%0,%1,%2,%3};"
        : "+f"(d[0]), "+f"(d[1]), "+f"(d[2]), "+f"(d[3])
        : "r"(a[0]), "r"(a[1]), "r"(a[2]), "r"(a[3]), "r"(b0), "r"(b1));
}

__device__ __forceinline__ void cp_async16(uint32_t saddr, const void* gaddr) {
    asm volatile("cp.async.cg.shared.global [%0], [%1], 16;"
                 :: "r"(saddr), "l"(gaddr) : "memory");
}
__device__ __forceinline__ void cp_commit() {
    asm volatile("cp.async.commit_group;" ::: "memory");
}

// ---------------------------------------------------------------------------
// Conversion: fp32 -> fp16
// ---------------------------------------------------------------------------
__global__ __launch_bounds__(256)
void convert_half_kernel(const float* __restrict__ X, __half* __restrict__ Hi, int n4) {
    int i = blockIdx.x * 256 + threadIdx.x;
    if (i >= n4) return;
    float4 v = ((const float4*)X)[i];
    __half2* hp = (__half2*)(Hi + 4 * (size_t)i);
    hp[0] = __halves2half2(__float2half_rn(v.x), __float2half_rn(v.y));
    hp[1] = __halves2half2(__float2half_rn(v.z), __float2half_rn(v.w));
}

// ---------------------------------------------------------------------------
// Transpose: W[Kd, N] fp32 -> T [N, Kd] fp16
// ---------------------------------------------------------------------------
__global__ __launch_bounds__(256)
void transpose_half_kernel(const float* __restrict__ W,
                           __half* __restrict__ Thi, int Kd, int N) {
    __shared__ float tile[32][33];
    int n0 = blockIdx.x * 32, k0 = blockIdx.y * 32;
    int tx = threadIdx.x & 31, ty = threadIdx.x >> 5;
#pragma unroll
    for (int r = ty; r < 32; r += 8)
        tile[r][tx] = W[(size_t)(k0 + r) * N + n0 + tx];
    __syncthreads();
#pragma unroll
    for (int r = ty; r < 32; r += 8)
        Thi[(size_t)(n0 + r) * Kd + k0 + tx] = __float2half_rn(tile[tx][r]);
}

// ---------------------------------------------------------------------------
// Pure fp16 GEMM with cp.async 3-stage pipeline.
// C[M,N] = A[M,K] @ B[N,K]^T ; output fp32 (C) or fp16 (Ch).
// 128x128 CTA tile, 8 warps, K-chunk 32, 2 CTAs/SM.
// ---------------------------------------------------------------------------
#define GPAD 40
#define GTILE_BYTES (128 * GPAD * 2)      // 10240
#define GSTAGE_BYTES (2 * GTILE_BYTES)    // 20480 (A, B)
#define GSMEM_DYN (3 * GSTAGE_BYTES)      // 61440 (3 stages)

__device__ __forceinline__ void gemm_core(
    const __half* __restrict__ A, const __half* __restrict__ B,
    float* __restrict__ C, __half* __restrict__ Ch,
    int N, int Kd, int row0, int col0, char* smg) {
    const uint32_t sbase0 = smem_to_u32(smg);

    const int tid = threadIdx.x;
    const int lane = tid & 31;
    const int wid = tid >> 5;
    const int wr = wid & 3;
    const int wc = wid >> 2;

    float d[2][8][4];
#pragma unroll
    for (int m = 0; m < 2; ++m)
#pragma unroll
        for (int n = 0; n < 8; ++n)
#pragma unroll
            for (int j = 0; j < 4; ++j) d[m][n][j] = 0.0f;

    const __half* gb[2] = {A, B};
    int grow[4], gseg[4];
#pragma unroll
    for (int a = 0; a < 2; ++a) {
        int r0 = (a == 0) ? row0 : col0;
        int s0 = tid, s1 = tid + 256;
        grow[2*a]   = r0 + (s0 >> 2); gseg[2*a]   = s0 & 3;
        grow[2*a+1] = r0 + (s1 >> 2); gseg[2*a+1] = s1 & 3;
    }

    auto cp_chunk = [&](int k0, int stage) {
        uint32_t st = sbase0 + stage * GSTAGE_BYTES;
#pragma unroll
        for (int a = 0; a < 2; ++a) {
#pragma unroll
            for (int j = 0; j < 2; ++j) {
                int e = 2 * a + j;
                int s = tid + j * 256;
                uint32_t sa = st + a * GTILE_BYTES + (s >> 2) * (GPAD*2) + (s & 3) * 16;
                cp_async16(sa, gb[a] + (size_t)grow[e] * Kd + k0 + gseg[e] * 8);
            }
        }
        cp_commit();
    };

    const int NC = Kd / 32;

    cp_chunk(0, 0);
    cp_chunk(32, 1);

    for (int c = 0; c < NC; ++c) {
        if (c + 1 < NC) asm volatile("cp.async.wait_group 1;" ::: "memory");
        else            asm volatile("cp.async.wait_group 0;" ::: "memory");
        __syncthreads();

        if (c + 2 < NC) cp_chunk((c + 2) * 32, (c + 2) % 3);

        const uint32_t sb = sbase0 + (c % 3) * GSTAGE_BYTES;
#pragma unroll
        for (int ks = 0; ks < 2; ++ks) {
            const uint32_t coff = ks * 32 + (lane >> 4) * 16;
            uint32_t ah[2][4];
#pragma unroll
            for (int mb = 0; mb < 2; ++mb) {
                uint32_t addr = sb + (wr * 32 + mb * 16 + (lane & 15)) * (GPAD*2) + coff;
                ldsm_x4(ah[mb][0], ah[mb][1], ah[mb][2], ah[mb][3], addr);
            }
            uint32_t bh[4][4];
#pragma unroll
            for (int nb = 0; nb < 4; ++nb) {
                uint32_t addr = sb + GTILE_BYTES +
                                (wc * 64 + nb * 16 + (lane & 15)) * (GPAD*2) + coff;
                ldsm_x4(bh[nb][0], bh[nb][1], bh[nb][2], bh[nb][3], addr);
            }
#pragma unroll
            for (int mb = 0; mb < 2; ++mb) {
#pragma unroll
                for (int nb = 0; nb < 4; ++nb) {
                    mma_f16(d[mb][2*nb],   ah[mb], bh[nb][0], bh[nb][2]);
                    mma_f16(d[mb][2*nb+1], ah[mb], bh[nb][1], bh[nb][3]);
                }
            }
        }
    }

    const int frow = lane >> 2;
    const int fcol = 2 * (lane & 3);
#pragma unroll
    for (int mb = 0; mb < 2; ++mb) {
#pragma unroll
        for (int nt = 0; nt < 8; ++nt) {
            int r = row0 + wr * 32 + mb * 16 + frow;
            int cc = col0 + wc * 64 + nt * 8 + fcol;
            if (Ch) {
                *(__half2*)&Ch[(size_t)r * N + cc] =
                    __halves2half2(__float2half_rn(d[mb][nt][0]), __float2half_rn(d[mb][nt][1]));
                *(__half2*)&Ch[(size_t)(r + 8) * N + cc] =
                    __halves2half2(__float2half_rn(d[mb][nt][2]), __float2half_rn(d[mb][nt][3]));
            } else {
                *(float2*)&C[(size_t)r * N + cc]       = make_float2(d[mb][nt][0], d[mb][nt][1]);
                *(float2*)&C[(size_t)(r + 8) * N + cc] = make_float2(d[mb][nt][2], d[mb][nt][3]);
            }
        }
    }
}

__global__ __launch_bounds__(256, 2)
void gemm_mma(const __half* __restrict__ A, const __half* __restrict__ B,
              float* __restrict__ C, int N, int Kd) {
    extern __shared__ char smg[];
    gemm_core(A, B, C, nullptr, N, Kd, blockIdx.y * 128, blockIdx.x * 128, smg);
}

// Fused QKV: col-tiles 0-15 -> Wq/qr(f32), 16-23 -> Wk/kr(f32), 24-31 -> Wv/vhi
__global__ __launch_bounds__(256, 2)
void gemm_qkv(const __half* __restrict__ Xhi,
              const __half* __restrict__ Wq, const __half* __restrict__ Wk,
              const __half* __restrict__ Wv,
              float* __restrict__ Q, float* __restrict__ Kc, __half* __restrict__ Vh) {
    extern __shared__ char smg[];
    int ct = blockIdx.x;
    if (ct < 16) {
        gemm_core(Xhi, Wq, Q, nullptr, HH*HD, DD, blockIdx.y * 128, ct * 128, smg);
    } else if (ct < 24) {
        gemm_core(Xhi, Wk, Kc, nullptr, KK*HD, DD, blockIdx.y * 128, (ct - 16) * 128, smg);
    } else {
        gemm_core(Xhi, Wv, nullptr, Vh, KK*HD, DD, blockIdx.y * 128, (ct - 24) * 128, smg);
    }
}

// ---------------------------------------------------------------------------
// Fused RMSNorm + RoPE. q -> fp16; k -> fp16.
// ---------------------------------------------------------------------------
__global__ __launch_bounds__(256)
void normrope_kernel(const float* __restrict__ q, const float* __restrict__ k,
                     __half* __restrict__ Qhi, __half* __restrict__ Khi,
                     const float* __restrict__ qn, const float* __restrict__ kn,
                     const float* __restrict__ sinp, const float* __restrict__ cosp) {
    int warp = (blockIdx.x * blockDim.x + threadIdx.x) >> 5;
    int lane = threadIdx.x & 31;
    const int NQ = MTOT * HH;
    const int NTOT = NQ + MTOT * KK;
    if (warp >= NTOT) return;

    const float* ptr;
    const float* w;
    int t;
    bool isq = warp < NQ;
    size_t off;
    if (isq) {
        int bt = warp >> 4;
        int h = warp & 15;
        off = (size_t)bt * (HH * HD) + h * HD;
        ptr = q + off;
        w = qn;
        t = bt & (TT - 1);
    } else {
        int v2 = warp - NQ;
        int bt = v2 >> 3;
        int kh = v2 & 7;
        off = (size_t)bt * (KK * HD) + kh * HD;
        ptr = k + off;
        w = kn;
        t = bt & (TT - 1);
    }

    float2 a  = *(const float2*)(ptr + 2 * lane);
    float2 b2 = *(const float2*)(ptr + 64 + 2 * lane);

    float ss = a.x * a.x + a.y * a.y + b2.x * b2.x + b2.y * b2.y;
#pragma unroll
    for (int o = 16; o; o >>= 1) ss += __shfl_xor_sync(0xFFFFFFFFu, ss, o);
    float rinv = rsqrtf(ss * (1.0f / 128.0f) + 1e-6f);

    float w0 = w[2 * lane], w1 = w[2 * lane + 1];
    float w2 = w[64 + 2 * lane], w3 = w[65 + 2 * lane];
    float n0 = a.x * rinv * w0, n1 = a.y * rinv * w1;
    float n2 = b2.x * rinv * w2, n3 = b2.y * rinv * w3;

    float s0 = sinp[t * 64 + lane],      c0 = cosp[t * 64 + lane];
    float s1 = sinp[t * 64 + lane + 32], c1 = cosp[t * 64 + lane + 32];
    float o0 = n0 * c0 - n1 * s0;
    float o1 = n2 * c1 - n3 * s1;
    float o2 = n0 * s0 + n1 * c0;
    float o3 = n2 * s1 + n3 * c1;

    __half* dhi = (isq ? Qhi : Khi) + off;
    dhi[lane]      = __float2half_rn(o0);
    dhi[lane + 32] = __float2half_rn(o1);
    dhi[lane + 64] = __float2half_rn(o2);
    dhi[lane + 96] = __float2half_rn(o3);
}

// ---------------------------------------------------------------------------
// Flash attention: pure-fp16 mma (fp32 softmax/accum), 128-row Q tile,
// 8 warps x 16 rows, register softmax + P fragments, double-buffered K/V,
// ONE barrier per K-tile, 2 CTAs/SM.
// ---------------------------------------------------------------------------
#define FK_STRB 272                 // bytes per 128-wide fp16 row (136 halves)
#define FQ_TILE (128 * FK_STRB)     // 34816
#define FKV_TILE (64 * FK_STRB)     // 17408
#define F4_Q 0
#define F4_KV FQ_TILE               // stage s: K at +s*2*FKV_TILE, V at +FKV_TILE
#define FA5_SMEM (FQ_TILE + 2 * 2 * FKV_TILE)   // 104448 -> 2 CTAs/SM

__global__ __launch_bounds__(256, 2)
void flash_mma(const __half* __restrict__ Qhi,
               const __half* __restrict__ Khi, const __half* __restrict__ Vhi,
               __half* __restrict__ Ohi) {
    extern __shared__ char sm[];
    const uint32_t sb = smem_to_u32(sm);

    const int qt = gridDim.x - 1 - blockIdx.x;   // descending work order
    const int bh = blockIdx.y;
    const int b = bh >> 4;
    const int h = bh & 15;
    const int kh = h >> 1;

    const int tid = threadIdx.x;
    const int lane = tid & 31;
    const int wid = tid >> 5;           // warp owns rows wid*16 .. +15
    const int frow = lane >> 2;
    const int fcol = 2 * (lane & 3);
    const float scale = 0.08838834764831845f;  // 1/sqrt(128)

    const int qrow0 = qt * 128 + wid * 16;
    const int ktmax = 2 * qt + 1;

    const __half* qh = Qhi + ((size_t)(b * TT + qt * 128)) * (HH*HD) + h * HD;
    const __half* kbase = Khi + ((size_t)(b * TT)) * (KK*HD) + kh * HD;
    const __half* vbase = Vhi + ((size_t)(b * TT)) * (KK*HD) + kh * HD;

    auto cp_kv = [&](int kt, int stage) {
        uint32_t st = sb + F4_KV + stage * 2 * FKV_TILE;
        const __half* kp = kbase + (size_t)(kt * 64) * (KK*HD);
        const __half* vp = vbase + (size_t)(kt * 64) * (KK*HD);
#pragma unroll
        for (int j = 0; j < 4; ++j) {
            int idx = tid + j * 256;      // 0..1023
            int r = idx >> 4, s = idx & 15;
            uint32_t so = r * FK_STRB + s * 16;
            cp_async16(st + so,            kp + (size_t)r * (KK*HD) + s * 8);
            cp_async16(st + FKV_TILE + so, vp + (size_t)r * (KK*HD) + s * 8);
        }
        cp_commit();
    };

    // Prologue: Q tile + first K/V
    {
#pragma unroll
        for (int j = 0; j < 8; ++j) {
            int idx = tid + j * 256;      // 0..2047
            int r = idx >> 4, s = idx & 15;
            cp_async16(sb + F4_Q + r * FK_STRB + s * 16,
                       qh + (size_t)r * (HH*HD) + s * 8);
        }
        cp_commit();
        cp_kv(0, 0);
    }

    float o[16][4];
#pragma unroll
    for (int n = 0; n < 16; ++n)
#pragma unroll
        for (int j = 0; j < 4; ++j) o[n][j] = 0.0f;
    float m0 = -INFINITY, m1 = -INFINITY, l0 = 0.0f, l1 = 0.0f;

    for (int kt = 0; kt <= ktmax; ++kt) {
        asm volatile("cp.async.wait_group 0;" ::: "memory");
        __syncthreads();
        if (kt < ktmax) cp_kv(kt + 1, (kt + 1) & 1);

        const uint32_t kvs = sb + F4_KV + (kt & 1) * 2 * FKV_TILE;

        // ---- S = Qhi @ Khi^T, m16 x n64 per warp ----
        float s[8][4];
#pragma unroll
        for (int i = 0; i < 8; ++i)
#pragma unroll
            for (int j = 0; j < 4; ++j) s[i][j] = 0.0f;

#pragma unroll
        for (int ks = 0; ks < 8; ++ks) {
            const uint32_t coff = ks * 32 + (lane >> 4) * 16;
            uint32_t aq[4];
            {
                uint32_t addr = sb + F4_Q + (wid * 16 + (lane & 15)) * FK_STRB + coff;
                ldsm_x4(aq[0], aq[1], aq[2], aq[3], addr);
            }
            uint32_t kb[4][4];
#pragma unroll
            for (int nb = 0; nb < 4; ++nb) {
                uint32_t addr = kvs + (nb * 16 + (lane & 15)) * FK_STRB + coff;
                ldsm_x4(kb[nb][0], kb[nb][1], kb[nb][2], kb[nb][3], addr);
            }
#pragma unroll
            for (int nb = 0; nb < 4; ++nb) {
                mma_f16(s[2*nb],   aq, kb[nb][0], kb[nb][2]);
                mma_f16(s[2*nb+1], aq, kb[nb][1], kb[nb][3]);
            }
        }

        // ---- scale + causal mask (registers) ----
        bool boundary = (kt * 64 + 63 > qrow0);
#pragma unroll
        for (int nt = 0; nt < 8; ++nt) {
            int c = kt * 64 + nt * 8 + fcol;
            s[nt][0] *= scale; s[nt][1] *= scale;
            s[nt][2] *= scale; s[nt][3] *= scale;
            if (boundary) {
                int r0 = qrow0 + frow, r1 = r0 + 8;
                if (c     > r0) s[nt][0] = -INFINITY;
                if (c + 1 > r0) s[nt][1] = -INFINITY;
                if (c     > r1) s[nt][2] = -INFINITY;
                if (c + 1 > r1) s[nt][3] = -INFINITY;
            }
        }

        // ---- register online softmax (quad shfl reductions) ----
        float mx0 = -INFINITY, mx1 = -INFINITY;
#pragma unroll
        for (int nt = 0; nt < 8; ++nt) {
            mx0 = fmaxf(mx0, fmaxf(s[nt][0], s[nt][1]));
            mx1 = fmaxf(mx1, fmaxf(s[nt][2], s[nt][3]));
        }
        mx0 = fmaxf(mx0, __shfl_xor_sync(0xFFFFFFFFu, mx0, 1));
        mx0 = fmaxf(mx0, __shfl_xor_sync(0xFFFFFFFFu, mx0, 2));
        mx1 = fmaxf(mx1, __shfl_xor_sync(0xFFFFFFFFu, mx1, 1));
        mx1 = fmaxf(mx1, __shfl_xor_sync(0xFFFFFFFFu, mx1, 2));
        mx0 = fmaxf(mx0, m0);
        mx1 = fmaxf(mx1, m1);
        float a0 = __expf(m0 - mx0);
        float a1 = __expf(m1 - mx1);
        float sum0 = 0.0f, sum1 = 0.0f;
#pragma unroll
        for (int nt = 0; nt < 8; ++nt) {
            s[nt][0] = __expf(s[nt][0] - mx0); sum0 += s[nt][0];
            s[nt][1] = __expf(s[nt][1] - mx0); sum0 += s[nt][1];
            s[nt][2] = __expf(s[nt][2] - mx1); sum1 += s[nt][2];
            s[nt][3] = __expf(s[nt][3] - mx1); sum1 += s[nt][3];
        }
        sum0 += __shfl_xor_sync(0xFFFFFFFFu, sum0, 1);
        sum0 += __shfl_xor_sync(0xFFFFFFFFu, sum0, 2);
        sum1 += __shfl_xor_sync(0xFFFFFFFFu, sum1, 1);
        sum1 += __shfl_xor_sync(0xFFFFFFFFu, sum1, 2);
        l0 = l0 * a0 + sum0;  m0 = mx0;
        l1 = l1 * a1 + sum1;  m1 = mx1;

        // rescale O
#pragma unroll
        for (int nt = 0; nt < 16; ++nt) {
            o[nt][0] *= a0; o[nt][1] *= a0;
            o[nt][2] *= a1; o[nt][3] *= a1;
        }

        // ---- O += Phi @ Vhi ; P fragments built from s registers ----
#pragma unroll
        for (int j = 0; j < 4; ++j) {
            uint32_t ap[4];
            {
                __half ph[8];
#pragma unroll
                for (int e = 0; e < 4; ++e) {
                    ph[e]     = __float2half_rn(s[2*j][e]);
                    ph[4 + e] = __float2half_rn(s[2*j+1][e]);
                }
                ap[0] = pack_half2(ph[0], ph[1]);
                ap[1] = pack_half2(ph[2], ph[3]);
                ap[2] = pack_half2(ph[4], ph[5]);
                ap[3] = pack_half2(ph[6], ph[7]);
            }
#pragma unroll
            for (int g = 0; g < 2; ++g) {
                uint32_t vh[4][4];
#pragma unroll
                for (int q = 0; q < 4; ++q) {
                    int nb = g * 4 + q;
                    uint32_t addr = kvs + FKV_TILE
                                  + (j * 16 + (lane & 15)) * FK_STRB
                                  + (nb * 16 + (lane >> 4) * 8) * 2;
                    ldsm_x4_trans(vh[q][0], vh[q][1], vh[q][2], vh[q][3], addr);
                }
#pragma unroll
                for (int q = 0; q < 4; ++q) {
                    int nb = g * 4 + q;
                    mma_f16(o[2*nb],   ap, vh[q][0], vh[q][1]);
                    mma_f16(o[2*nb+1], ap, vh[q][2], vh[q][3]);
                }
            }
        }
    }

    // Epilogue: normalize by 1/l, write fp16 (b,t,h,d)
    {
        float li0 = 1.0f / l0;
        float li1 = 1.0f / l1;
        int r0g = b * TT + qt * 128 + wid * 16 + frow;
#pragma unroll
        for (int nt = 0; nt < 16; ++nt) {
            int c = nt * 8 + fcol;
            size_t o0 = (size_t)r0g * (HH*HD) + h * HD + c;
            size_t o1 = (size_t)(r0g + 8) * (HH*HD) + h * HD + c;
            *(__half2*)&Ohi[o0] = __halves2half2(__float2half_rn(o[nt][0] * li0),
                                                 __float2half_rn(o[nt][1] * li0));
            *(__half2*)&Ohi[o1] = __halves2half2(__float2half_rn(o[nt][2] * li1),
                                                 __float2half_rn(o[nt][3] * li1));
        }
    }
}

// ---------------------------------------------------------------------------
extern "C" void kernel_launch(void* const* d_in, const int* in_sizes, int n_in,
                              void* d_out, int out_size) {
    const float* x    = (const float*)d_in[0];
    const float* Wq   = (const float*)d_in[1];
    const float* Wk   = (const float*)d_in[2];
    const float* Wv   = (const float*)d_in[3];
    const float* Wo   = (const float*)d_in[4];
    const float* qn   = (const float*)d_in[5];
    const float* kn   = (const float*)d_in[6];
    const float* sinp = (const float*)d_in[7];
    const float* cosp = (const float*)d_in[8];
    float* out = (float*)d_out;

    __half *xhi, *wqt, *wkt, *wvt, *wot;
    __half *qhi, *khi, *vhi, *ohi;
    float *qr, *kr;
    cudaGetSymbolAddress((void**)&xhi, g_xhi);
    cudaGetSymbolAddress((void**)&wqt, g_wqt);
    cudaGetSymbolAddress((void**)&wkt, g_wkt);
    cudaGetSymbolAddress((void**)&wvt, g_wvt);
    cudaGetSymbolAddress((void**)&wot, g_wot);
    cudaGetSymbolAddress((void**)&qr, g_q_raw);
    cudaGetSymbolAddress((void**)&kr, g_k_raw);
    cudaGetSymbolAddress((void**)&qhi, g_qhi);
    cudaGetSymbolAddress((void**)&khi, g_khi);
    cudaGetSymbolAddress((void**)&vhi, g_vhi);
    cudaGetSymbolAddress((void**)&ohi, g_ohi);

    // 1. convert x to fp16
    convert_half_kernel<<<(MTOT * DD / 4 + 255) / 256, 256>>>(x, xhi, MTOT * DD / 4);

    // 2. transpose weights to fp16
    transpose_half_kernel<<<dim3((HH*HD)/32, DD/32), 256>>>(Wq, wqt, DD, HH*HD);
    transpose_half_kernel<<<dim3((KK*HD)/32, DD/32), 256>>>(Wk, wkt, DD, KK*HD);
    transpose_half_kernel<<<dim3((KK*HD)/32, DD/32), 256>>>(Wv, wvt, DD, KK*HD);
    transpose_half_kernel<<<dim3((HH*HD)/32, (HH*HD)/32), 256>>>(Wo, wot, HH*HD, HH*HD);

    // 3. fused QKV projection (pure fp16, 1-pass; V -> fp16 direct)
    cudaFuncSetAttribute(gemm_qkv, cudaFuncAttributeMaxDynamicSharedMemorySize, GSMEM_DYN);
    gemm_qkv<<<dim3(32, MTOT/128), 256, GSMEM_DYN>>>(xhi, wqt, wkt, wvt, qr, kr, vhi);

    // 4. RMSNorm + RoPE -> q hi, k hi
    normrope_kernel<<<12288, 256>>>(qr, kr, qhi, khi, qn, kn, sinp, cosp);

    // 5. causal flash attention (pure-fp16 mma, double-buffered, 2 CTAs/SM)
    cudaFuncSetAttribute(flash_mma, cudaFuncAttributeMaxDynamicSharedMemorySize, FA5_SMEM);
    flash_mma<<<dim3(TT / 128, BB * HH), 256, FA5_SMEM>>>(qhi, khi, vhi, ohi);

    // 6. output projection (pure fp16, 1-pass)
    cudaFuncSetAttribute(gemm_mma, cudaFuncAttributeMaxDynamicSharedMemorySize, GSMEM_DYN);
    gemm_mma<<<dim3((HH*HD)/128, MTOT/128), 256, GSMEM_DYN>>>(ohi, wot, out, HH*HD, HH*HD);
}

// round 13
// speedup vs baseline: 6.8233x; 1.0206x over previous
#include <cuda_runtime.h>
#include <cuda_fp16.h>
#include <math.h>
#include <cstdint>

// Problem constants
#define BB 2
#define TT 2048
#define DD 2048
#define HH 16
#define KK 8
#define HD 128
#define MTOT (BB*TT)   // 4096

// ---------------------------------------------------------------------------
// Scratch (device globals; no allocation allowed)
// ---------------------------------------------------------------------------
__device__ __half g_xhi [(size_t)MTOT * DD];
__device__ __half g_wqt [(size_t)(HH*HD) * DD];
__device__ __half g_wkt [(size_t)(KK*HD) * DD];
__device__ __half g_wvt [(size_t)(KK*HD) * DD];
__device__ __half g_wot [(size_t)DD * (HH*HD)];
__device__ __half g_qhi [(size_t)MTOT * (HH*HD)];
__device__ __half g_khi [(size_t)MTOT * (KK*HD)];
__device__ __half g_vhi [(size_t)MTOT * (KK*HD)];
__device__ __half g_ohi [(size_t)MTOT * (HH*HD)];

// ---------------------------------------------------------------------------
// mma.sync / cp.async helpers
// ---------------------------------------------------------------------------
__device__ __forceinline__ uint32_t smem_to_u32(const void* p) {
    uint32_t a;
    asm("{ .reg .u64 t; cvta.to.shared.u64 t, %1; cvt.u32.u64 %0, t; }"
        : "=r"(a) : "l"(p));
    return a;
}

__device__ __forceinline__ uint32_t pack_half2(__half lo, __half hi) {
    return (uint32_t)__half_as_ushort(lo) | ((uint32_t)__half_as_ushort(hi) << 16);
}

__device__ __forceinline__ void ldsm_x4(uint32_t& r0, uint32_t& r1,
                                        uint32_t& r2, uint32_t& r3, uint32_t addr) {
    asm volatile("ldmatrix.sync.aligned.m8n8.x4.shared.b16 {%0,%1,%2,%3}, [%4];"
                 : "=r"(r0), "=r"(r1), "=r"(r2), "=r"(r3) : "r"(addr));
}

__device__ __forceinline__ void ldsm_x4_trans(uint32_t& r0, uint32_t& r1,
                                              uint32_t& r2, uint32_t& r3, uint32_t addr) {
    asm volatile("ldmatrix.sync.aligned.m8n8.x4.trans.shared.b16 {%0,%1,%2,%3}, [%4];"
                 : "=r"(r0), "=r"(r1), "=r"(r2), "=r"(r3) : "r"(addr));
}

__device__ __forceinline__ void mma_f16(float* d, const uint32_t* a,
                                        uint32_t b0, uint32_t b1) {
    asm volatile(
        "mma.sync.aligned.m16n8k16.row.col.f32.f16.f16.f32 "
        "{%0,%1,%2,%3}, {%4,%5,%6,%7}, {%8,%9}, {%0,%1,%2,%3};"
        : "+f"(d[0]), "+f"(d[1]), "+f"(d[2]), "+f"(d[3])
        : "r"(a[0]), "r"(a[1]), "r"(a[2]), "r"(a[3]), "r"(b0), "r"(b1));
}

__device__ __forceinline__ void cp_async16(uint32_t saddr, const void* gaddr) {
    asm volatile("cp.async.cg.shared.global [%0], [%1], 16;"
                 :: "r"(saddr), "l"(gaddr) : "memory");
}
__device__ __forceinline__ void cp_commit() {
    asm volatile("cp.async.commit_group;" ::: "memory");
}

// ---------------------------------------------------------------------------
// Fused prep: convert x to fp16 + transpose all 4 weights to fp16 [N, Kd].
// 1-D grid, range-routed tasks.
//   [0, 8192)               : convert x (float4 per thread)
//   [8192, 12288)           : Wq transpose  (64 x 64 blocks)
//   [12288, 14336)          : Wk transpose  (32 x 64)
//   [14336, 16384)          : Wv transpose  (32 x 64)
//   [16384, 20480)          : Wo transpose  (64 x 64)
// ---------------------------------------------------------------------------
__device__ __forceinline__ void transpose_body(const float* __restrict__ W,
                                               __half* __restrict__ T,
                                               int Kd, int N, int n0, int k0) {
    __shared__ float tile[32][33];
    int tx = threadIdx.x & 31, ty = threadIdx.x >> 5;
#pragma unroll
    for (int r = ty; r < 32; r += 8)
        tile[r][tx] = W[(size_t)(k0 + r) * N + n0 + tx];
    __syncthreads();
#pragma unroll
    for (int r = ty; r < 32; r += 8)
        T[(size_t)(n0 + r) * Kd + k0 + tx] = __float2half_rn(tile[tx][r]);
}

__global__ __launch_bounds__(256)
void prep_kernel(const float* __restrict__ x,
                 const float* __restrict__ Wq, const float* __restrict__ Wk,
                 const float* __restrict__ Wv, const float* __restrict__ Wo,
                 __half* __restrict__ Xh, __half* __restrict__ Tq,
                 __half* __restrict__ Tk, __half* __restrict__ Tv,
                 __half* __restrict__ To) {
    int bid = blockIdx.x;
    if (bid < 8192) {
        int i = bid * 256 + threadIdx.x;           // < 2M float4s
        float4 v = ((const float4*)x)[i];
        __half2* hp = (__half2*)(Xh + 4 * (size_t)i);
        hp[0] = __halves2half2(__float2half_rn(v.x), __float2half_rn(v.y));
        hp[1] = __halves2half2(__float2half_rn(v.z), __float2half_rn(v.w));
    } else if (bid < 12288) {
        int l = bid - 8192;
        transpose_body(Wq, Tq, DD, HH*HD, (l & 63) * 32, (l >> 6) * 32);
    } else if (bid < 14336) {
        int l = bid - 12288;
        transpose_body(Wk, Tk, DD, KK*HD, (l & 31) * 32, (l >> 5) * 32);
    } else if (bid < 16384) {
        int l = bid - 14336;
        transpose_body(Wv, Tv, DD, KK*HD, (l & 31) * 32, (l >> 5) * 32);
    } else {
        int l = bid - 16384;
        transpose_body(Wo, To, HH*HD, HH*HD, (l & 63) * 32, (l >> 6) * 32);
    }
}

// ---------------------------------------------------------------------------
// Pure fp16 GEMM with cp.async 3-stage pipeline.
// C[M,N] = A[M,K] @ B[N,K]^T ; output fp32 (C) or fp16 (Ch).
// ---------------------------------------------------------------------------
#define GPAD 40
#define GTILE_BYTES (128 * GPAD * 2)      // 10240
#define GSTAGE_BYTES (2 * GTILE_BYTES)    // 20480 (A, B)
#define GSMEM_DYN (3 * GSTAGE_BYTES)      // 61440 (3 stages)

__device__ __forceinline__ void gemm_core(
    const __half* __restrict__ A, const __half* __restrict__ B,
    float* __restrict__ C, __half* __restrict__ Ch,
    int N, int Kd, int row0, int col0, char* smg) {
    const uint32_t sbase0 = smem_to_u32(smg);

    const int tid = threadIdx.x;
    const int lane = tid & 31;
    const int wid = tid >> 5;
    const int wr = wid & 3;
    const int wc = wid >> 2;

    float d[2][8][4];
#pragma unroll
    for (int m = 0; m < 2; ++m)
#pragma unroll
        for (int n = 0; n < 8; ++n)
#pragma unroll
            for (int j = 0; j < 4; ++j) d[m][n][j] = 0.0f;

    const __half* gb[2] = {A, B};
    int grow[4], gseg[4];
#pragma unroll
    for (int a = 0; a < 2; ++a) {
        int r0 = (a == 0) ? row0 : col0;
        int s0 = tid, s1 = tid + 256;
        grow[2*a]   = r0 + (s0 >> 2); gseg[2*a]   = s0 & 3;
        grow[2*a+1] = r0 + (s1 >> 2); gseg[2*a+1] = s1 & 3;
    }

    auto cp_chunk = [&](int k0, int stage) {
        uint32_t st = sbase0 + stage * GSTAGE_BYTES;
#pragma unroll
        for (int a = 0; a < 2; ++a) {
#pragma unroll
            for (int j = 0; j < 2; ++j) {
                int e = 2 * a + j;
                int s = tid + j * 256;
                uint32_t sa = st + a * GTILE_BYTES + (s >> 2) * (GPAD*2) + (s & 3) * 16;
                cp_async16(sa, gb[a] + (size_t)grow[e] * Kd + k0 + gseg[e] * 8);
            }
        }
        cp_commit();
    };

    const int NC = Kd / 32;

    cp_chunk(0, 0);
    cp_chunk(32, 1);

    for (int c = 0; c < NC; ++c) {
        if (c + 1 < NC) asm volatile("cp.async.wait_group 1;" ::: "memory");
        else            asm volatile("cp.async.wait_group 0;" ::: "memory");
        __syncthreads();

        if (c + 2 < NC) cp_chunk((c + 2) * 32, (c + 2) % 3);

        const uint32_t sb = sbase0 + (c % 3) * GSTAGE_BYTES;
#pragma unroll
        for (int ks = 0; ks < 2; ++ks) {
            const uint32_t coff = ks * 32 + (lane >> 4) * 16;
            uint32_t ah[2][4];
#pragma unroll
            for (int mb = 0; mb < 2; ++mb) {
                uint32_t addr = sb + (wr * 32 + mb * 16 + (lane & 15)) * (GPAD*2) + coff;
                ldsm_x4(ah[mb][0], ah[mb][1], ah[mb][2], ah[mb][3], addr);
            }
            uint32_t bh[4][4];
#pragma unroll
            for (int nb = 0; nb < 4; ++nb) {
                uint32_t addr = sb + GTILE_BYTES +
                                (wc * 64 + nb * 16 + (lane & 15)) * (GPAD*2) + coff;
                ldsm_x4(bh[nb][0], bh[nb][1], bh[nb][2], bh[nb][3], addr);
            }
#pragma unroll
            for (int mb = 0; mb < 2; ++mb) {
#pragma unroll
                for (int nb = 0; nb < 4; ++nb) {
                    mma_f16(d[mb][2*nb],   ah[mb], bh[nb][0], bh[nb][2]);
                    mma_f16(d[mb][2*nb+1], ah[mb], bh[nb][1], bh[nb][3]);
                }
            }
        }
    }

    const int frow = lane >> 2;
    const int fcol = 2 * (lane & 3);
#pragma unroll
    for (int mb = 0; mb < 2; ++mb) {
#pragma unroll
        for (int nt = 0; nt < 8; ++nt) {
            int r = row0 + wr * 32 + mb * 16 + frow;
            int cc = col0 + wc * 64 + nt * 8 + fcol;
            if (Ch) {
                *(__half2*)&Ch[(size_t)r * N + cc] =
                    __halves2half2(__float2half_rn(d[mb][nt][0]), __float2half_rn(d[mb][nt][1]));
                *(__half2*)&Ch[(size_t)(r + 8) * N + cc] =
                    __halves2half2(__float2half_rn(d[mb][nt][2]), __float2half_rn(d[mb][nt][3]));
            } else {
                *(float2*)&C[(size_t)r * N + cc]       = make_float2(d[mb][nt][0], d[mb][nt][1]);
                *(float2*)&C[(size_t)(r + 8) * N + cc] = make_float2(d[mb][nt][2], d[mb][nt][3]);
            }
        }
    }
}

__global__ __launch_bounds__(256, 2)
void gemm_mma(const __half* __restrict__ A, const __half* __restrict__ B,
              float* __restrict__ C, int N, int Kd) {
    extern __shared__ char smg[];
    gemm_core(A, B, C, nullptr, N, Kd, blockIdx.y * 128, blockIdx.x * 128, smg);
}

// Fused QKV: all outputs fp16 direct (q/k normed+roped afterwards in-place)
__global__ __launch_bounds__(256, 2)
void gemm_qkv(const __half* __restrict__ Xhi,
              const __half* __restrict__ Wq, const __half* __restrict__ Wk,
              const __half* __restrict__ Wv,
              __half* __restrict__ Qh, __half* __restrict__ Kh, __half* __restrict__ Vh) {
    extern __shared__ char smg[];
    int ct = blockIdx.x;
    if (ct < 16) {
        gemm_core(Xhi, Wq, nullptr, Qh, HH*HD, DD, blockIdx.y * 128, ct * 128, smg);
    } else if (ct < 24) {
        gemm_core(Xhi, Wk, nullptr, Kh, KK*HD, DD, blockIdx.y * 128, (ct - 16) * 128, smg);
    } else {
        gemm_core(Xhi, Wv, nullptr, Vh, KK*HD, DD, blockIdx.y * 128, (ct - 24) * 128, smg);
    }
}

// ---------------------------------------------------------------------------
// Fused RMSNorm + RoPE, IN-PLACE on fp16 q/k. Q pre-scaled by 1/sqrt(128).
// One warp per (b,t,head) 128-vector.
// ---------------------------------------------------------------------------
__global__ __launch_bounds__(256)
void normrope_kernel(__half* __restrict__ Qh, __half* __restrict__ Kh,
                     const float* __restrict__ qn, const float* __restrict__ kn,
                     const float* __restrict__ sinp, const float* __restrict__ cosp) {
    int warp = (blockIdx.x * blockDim.x + threadIdx.x) >> 5;
    int lane = threadIdx.x & 31;
    const int NQ = MTOT * HH;
    const int NTOT = NQ + MTOT * KK;
    if (warp >= NTOT) return;

    __half* ptr;
    const float* w;
    int t;
    float oscale;
    if (warp < NQ) {
        int bt = warp >> 4;
        int h = warp & 15;
        ptr = Qh + (size_t)bt * (HH * HD) + h * HD;
        w = qn;
        t = bt & (TT - 1);
        oscale = 0.08838834764831845f;   // 1/sqrt(128) folded into Q
    } else {
        int v2 = warp - NQ;
        int bt = v2 >> 3;
        int kh = v2 & 7;
        ptr = Kh + (size_t)bt * (KK * HD) + kh * HD;
        w = kn;
        t = bt & (TT - 1);
        oscale = 1.0f;
    }

    __half2 a2 = ((const __half2*)ptr)[lane];        // elems 2l, 2l+1
    __half2 c2 = ((const __half2*)ptr)[32 + lane];   // elems 64+2l, 65+2l
    float ax = __low2float(a2), ay = __high2float(a2);
    float bx = __low2float(c2), by = __high2float(c2);

    float ss = ax * ax + ay * ay + bx * bx + by * by;
#pragma unroll
    for (int o = 16; o; o >>= 1) ss += __shfl_xor_sync(0xFFFFFFFFu, ss, o);
    float rinv = rsqrtf(ss * (1.0f / 128.0f) + 1e-6f);

    float w0 = w[2 * lane], w1 = w[2 * lane + 1];
    float w2 = w[64 + 2 * lane], w3 = w[65 + 2 * lane];
    float n0 = ax * rinv * w0, n1 = ay * rinv * w1;
    float n2 = bx * rinv * w2, n3 = by * rinv * w3;

    float s0 = sinp[t * 64 + lane],      c0 = cosp[t * 64 + lane];
    float s1 = sinp[t * 64 + lane + 32], c1 = cosp[t * 64 + lane + 32];
    float o0 = (n0 * c0 - n1 * s0) * oscale;
    float o1 = (n2 * c1 - n3 * s1) * oscale;
    float o2 = (n0 * s0 + n1 * c0) * oscale;
    float o3 = (n2 * s1 + n3 * c1) * oscale;

    // In-place: ALL lanes must finish reading before any lane writes
    __syncwarp();
    ptr[lane]      = __float2half_rn(o0);
    ptr[lane + 32] = __float2half_rn(o1);
    ptr[lane + 64] = __float2half_rn(o2);
    ptr[lane + 96] = __float2half_rn(o3);
}

// ---------------------------------------------------------------------------
// Flash attention: pure-fp16 mma (fp32 softmax/accum), 128-row Q tile,
// 8 warps x 16 rows, register softmax + P fragments, double-buffered K/V,
// ONE barrier per K-tile, 2 CTAs/SM. Q arrives pre-scaled.
// ---------------------------------------------------------------------------
#define FK_STRB 272                 // bytes per 128-wide fp16 row (136 halves)
#define FQ_TILE (128 * FK_STRB)     // 34816
#define FKV_TILE (64 * FK_STRB)     // 17408
#define F4_Q 0
#define F4_KV FQ_TILE               // stage s: K at +s*2*FKV_TILE, V at +FKV_TILE
#define FA5_SMEM (FQ_TILE + 2 * 2 * FKV_TILE)   // 104448 -> 2 CTAs/SM

__global__ __launch_bounds__(256, 2)
void flash_mma(const __half* __restrict__ Qhi,
               const __half* __restrict__ Khi, const __half* __restrict__ Vhi,
               __half* __restrict__ Ohi) {
    extern __shared__ char sm[];
    const uint32_t sb = smem_to_u32(sm);

    const int qt = gridDim.x - 1 - blockIdx.x;   // descending work order
    const int bh = blockIdx.y;
    const int b = bh >> 4;
    const int h = bh & 15;
    const int kh = h >> 1;

    const int tid = threadIdx.x;
    const int lane = tid & 31;
    const int wid = tid >> 5;
    const int frow = lane >> 2;
    const int fcol = 2 * (lane & 3);

    const int qrow0 = qt * 128 + wid * 16;
    const int ktmax = 2 * qt + 1;

    const __half* qh = Qhi + ((size_t)(b * TT + qt * 128)) * (HH*HD) + h * HD;
    const __half* kbase = Khi + ((size_t)(b * TT)) * (KK*HD) + kh * HD;
    const __half* vbase = Vhi + ((size_t)(b * TT)) * (KK*HD) + kh * HD;

    auto cp_kv = [&](int kt, int stage) {
        uint32_t st = sb + F4_KV + stage * 2 * FKV_TILE;
        const __half* kp = kbase + (size_t)(kt * 64) * (KK*HD);
        const __half* vp = vbase + (size_t)(kt * 64) * (KK*HD);
#pragma unroll
        for (int j = 0; j < 4; ++j) {
            int idx = tid + j * 256;
            int r = idx >> 4, s = idx & 15;
            uint32_t so = r * FK_STRB + s * 16;
            cp_async16(st + so,            kp + (size_t)r * (KK*HD) + s * 8);
            cp_async16(st + FKV_TILE + so, vp + (size_t)r * (KK*HD) + s * 8);
        }
        cp_commit();
    };

    // Prologue: Q tile + first K/V
    {
#pragma unroll
        for (int j = 0; j < 8; ++j) {
            int idx = tid + j * 256;
            int r = idx >> 4, s = idx & 15;
            cp_async16(sb + F4_Q + r * FK_STRB + s * 16,
                       qh + (size_t)r * (HH*HD) + s * 8);
        }
        cp_commit();
        cp_kv(0, 0);
    }

    float o[16][4];
#pragma unroll
    for (int n = 0; n < 16; ++n)
#pragma unroll
        for (int j = 0; j < 4; ++j) o[n][j] = 0.0f;
    float m0 = -INFINITY, m1 = -INFINITY, l0 = 0.0f, l1 = 0.0f;

    for (int kt = 0; kt <= ktmax; ++kt) {
        asm volatile("cp.async.wait_group 0;" ::: "memory");
        __syncthreads();
        if (kt < ktmax) cp_kv(kt + 1, (kt + 1) & 1);

        const uint32_t kvs = sb + F4_KV + (kt & 1) * 2 * FKV_TILE;

        // ---- S = Q @ K^T (Q pre-scaled), m16 x n64 per warp ----
        float s[8][4];
#pragma unroll
        for (int i = 0; i < 8; ++i)
#pragma unroll
            for (int j = 0; j < 4; ++j) s[i][j] = 0.0f;

#pragma unroll
        for (int ks = 0; ks < 8; ++ks) {
            const uint32_t coff = ks * 32 + (lane >> 4) * 16;
            uint32_t aq[4];
            {
                uint32_t addr = sb + F4_Q + (wid * 16 + (lane & 15)) * FK_STRB + coff;
                ldsm_x4(aq[0], aq[1], aq[2], aq[3], addr);
            }
            uint32_t kb[4][4];
#pragma unroll
            for (int nb = 0; nb < 4; ++nb) {
                uint32_t addr = kvs + (nb * 16 + (lane & 15)) * FK_STRB + coff;
                ldsm_x4(kb[nb][0], kb[nb][1], kb[nb][2], kb[nb][3], addr);
            }
#pragma unroll
            for (int nb = 0; nb < 4; ++nb) {
                mma_f16(s[2*nb],   aq, kb[nb][0], kb[nb][2]);
                mma_f16(s[2*nb+1], aq, kb[nb][1], kb[nb][3]);
            }
        }

        // ---- causal mask (registers) ----
        bool boundary = (kt * 64 + 63 > qrow0);
        if (boundary) {
#pragma unroll
            for (int nt = 0; nt < 8; ++nt) {
                int c = kt * 64 + nt * 8 + fcol;
                int r0 = qrow0 + frow, r1 = r0 + 8;
                if (c     > r0) s[nt][0] = -INFINITY;
                if (c + 1 > r0) s[nt][1] = -INFINITY;
                if (c     > r1) s[nt][2] = -INFINITY;
                if (c + 1 > r1) s[nt][3] = -INFINITY;
            }
        }

        // ---- register online softmax (quad shfl reductions) ----
        float mx0 = -INFINITY, mx1 = -INFINITY;
#pragma unroll
        for (int nt = 0; nt < 8; ++nt) {
            mx0 = fmaxf(mx0, fmaxf(s[nt][0], s[nt][1]));
            mx1 = fmaxf(mx1, fmaxf(s[nt][2], s[nt][3]));
        }
        mx0 = fmaxf(mx0, __shfl_xor_sync(0xFFFFFFFFu, mx0, 1));
        mx0 = fmaxf(mx0, __shfl_xor_sync(0xFFFFFFFFu, mx0, 2));
        mx1 = fmaxf(mx1, __shfl_xor_sync(0xFFFFFFFFu, mx1, 1));
        mx1 = fmaxf(mx1, __shfl_xor_sync(0xFFFFFFFFu, mx1, 2));
        mx0 = fmaxf(mx0, m0);
        mx1 = fmaxf(mx1, m1);
        float a0 = __expf(m0 - mx0);
        float a1 = __expf(m1 - mx1);
        float sum0 = 0.0f, sum1 = 0.0f;
#pragma unroll
        for (int nt = 0; nt < 8; ++nt) {
            s[nt][0] = __expf(s[nt][0] - mx0); sum0 += s[nt][0];
            s[nt][1] = __expf(s[nt][1] - mx0); sum0 += s[nt][1];
            s[nt][2] = __expf(s[nt][2] - mx1); sum1 += s[nt][2];
            s[nt][3] = __expf(s[nt][3] - mx1); sum1 += s[nt][3];
        }
        sum0 += __shfl_xor_sync(0xFFFFFFFFu, sum0, 1);
        sum0 += __shfl_xor_sync(0xFFFFFFFFu, sum0, 2);
        sum1 += __shfl_xor_sync(0xFFFFFFFFu, sum1, 1);
        sum1 += __shfl_xor_sync(0xFFFFFFFFu, sum1, 2);
        l0 = l0 * a0 + sum0;  m0 = mx0;
        l1 = l1 * a1 + sum1;  m1 = mx1;

        // rescale O
#pragma unroll
        for (int nt = 0; nt < 16; ++nt) {
            o[nt][0] *= a0; o[nt][1] *= a0;
            o[nt][2] *= a1; o[nt][3] *= a1;
        }

        // ---- O += P @ V ; P fragments built from s registers ----
#pragma unroll
        for (int j = 0; j < 4; ++j) {
            uint32_t ap[4];
            {
                __half ph[8];
#pragma unroll
                for (int e = 0; e < 4; ++e) {
                    ph[e]     = __float2half_rn(s[2*j][e]);
                    ph[4 + e] = __float2half_rn(s[2*j+1][e]);
                }
                ap[0] = pack_half2(ph[0], ph[1]);
                ap[1] = pack_half2(ph[2], ph[3]);
                ap[2] = pack_half2(ph[4], ph[5]);
                ap[3] = pack_half2(ph[6], ph[7]);
            }
#pragma unroll
            for (int g = 0; g < 2; ++g) {
                uint32_t vh[4][4];
#pragma unroll
                for (int q = 0; q < 4; ++q) {
                    int nb = g * 4 + q;
                    uint32_t addr = kvs + FKV_TILE
                                  + (j * 16 + (lane & 15)) * FK_STRB
                                  + (nb * 16 + (lane >> 4) * 8) * 2;
                    ldsm_x4_trans(vh[q][0], vh[q][1], vh[q][2], vh[q][3], addr);
                }
#pragma unroll
                for (int q = 0; q < 4; ++q) {
                    int nb = g * 4 + q;
                    mma_f16(o[2*nb],   ap, vh[q][0], vh[q][1]);
                    mma_f16(o[2*nb+1], ap, vh[q][2], vh[q][3]);
                }
            }
        }
    }

    // Epilogue: normalize by 1/l, write fp16 (b,t,h,d)
    {
        float li0 = 1.0f / l0;
        float li1 = 1.0f / l1;
        int r0g = b * TT + qt * 128 + wid * 16 + frow;
#pragma unroll
        for (int nt = 0; nt < 16; ++nt) {
            int c = nt * 8 + fcol;
            size_t o0 = (size_t)r0g * (HH*HD) + h * HD + c;
            size_t o1 = (size_t)(r0g + 8) * (HH*HD) + h * HD + c;
            *(__half2*)&Ohi[o0] = __halves2half2(__float2half_rn(o[nt][0] * li0),
                                                 __float2half_rn(o[nt][1] * li0));
            *(__half2*)&Ohi[o1] = __halves2half2(__float2half_rn(o[nt][2] * li1),
                                                 __float2half_rn(o[nt][3] * li1));
        }
    }
}

// ---------------------------------------------------------------------------
extern "C" void kernel_launch(void* const* d_in, const int* in_sizes, int n_in,
                              void* d_out, int out_size) {
    const float* x    = (const float*)d_in[0];
    const float* Wq   = (const float*)d_in[1];
    const float* Wk   = (const float*)d_in[2];
    const float* Wv   = (const float*)d_in[3];
    const float* Wo   = (const float*)d_in[4];
    const float* qn   = (const float*)d_in[5];
    const float* kn   = (const float*)d_in[6];
    const float* sinp = (const float*)d_in[7];
    const float* cosp = (const float*)d_in[8];
    float* out = (float*)d_out;

    __half *xhi, *wqt, *wkt, *wvt, *wot;
    __half *qhi, *khi, *vhi, *ohi;
    cudaGetSymbolAddress((void**)&xhi, g_xhi);
    cudaGetSymbolAddress((void**)&wqt, g_wqt);
    cudaGetSymbolAddress((void**)&wkt, g_wkt);
    cudaGetSymbolAddress((void**)&wvt, g_wvt);
    cudaGetSymbolAddress((void**)&wot, g_wot);
    cudaGetSymbolAddress((void**)&qhi, g_qhi);
    cudaGetSymbolAddress((void**)&khi, g_khi);
    cudaGetSymbolAddress((void**)&vhi, g_vhi);
    cudaGetSymbolAddress((void**)&ohi, g_ohi);

    // 1. fused prep: convert x + transpose all weights
    prep_kernel<<<20480, 256>>>(x, Wq, Wk, Wv, Wo, xhi, wqt, wkt, wvt, wot);

    // 2. fused QKV projection (pure fp16 in/out)
    cudaFuncSetAttribute(gemm_qkv, cudaFuncAttributeMaxDynamicSharedMemorySize, GSMEM_DYN);
    gemm_qkv<<<dim3(32, MTOT/128), 256, GSMEM_DYN>>>(xhi, wqt, wkt, wvt, qhi, khi, vhi);

    // 3. RMSNorm + RoPE in-place on fp16 q/k (Q pre-scaled by 1/sqrt(128))
    normrope_kernel<<<12288, 256>>>(qhi, khi, qn, kn, sinp, cosp);

    // 4. causal flash attention (pure-fp16 mma, double-buffered, 2 CTAs/SM)
    cudaFuncSetAttribute(flash_mma, cudaFuncAttributeMaxDynamicSharedMemorySize, FA5_SMEM);
    flash_mma<<<dim3(TT / 128, BB * HH), 256, FA5_SMEM>>>(qhi, khi, vhi, ohi);

    // 5. output projection (pure fp16, fp32 out)
    cudaFuncSetAttribute(gemm_mma, cudaFuncAttributeMaxDynamicSharedMemorySize, GSMEM_DYN);
    gemm_mma<<<dim3((HH*HD)/128, MTOT/128), 256, GSMEM_DYN>>>(ohi, wot, out, HH*HD, HH*HD);
}

// round 14
// speedup vs baseline: 6.9880x; 1.0241x over previous
#include <cuda_runtime.h>
#include <cuda_fp16.h>
#include <math.h>
#include <cstdint>

// Problem constants
#define BB 2
#define TT 2048
#define DD 2048
#define HH 16
#define KK 8
#define HD 128
#define MTOT (BB*TT)   // 4096

// ---------------------------------------------------------------------------
// Scratch (device globals; no allocation allowed)
// ---------------------------------------------------------------------------
__device__ __half g_xhi [(size_t)MTOT * DD];
__device__ __half g_wqt [(size_t)(HH*HD) * DD];
__device__ __half g_wkt [(size_t)(KK*HD) * DD];
__device__ __half g_wvt [(size_t)(KK*HD) * DD];
__device__ __half g_wot [(size_t)DD * (HH*HD)];
__device__ __half g_qhi [(size_t)MTOT * (HH*HD)];
__device__ __half g_khi [(size_t)MTOT * (KK*HD)];
__device__ __half g_vhi [(size_t)MTOT * (KK*HD)];
__device__ __half g_ohi [(size_t)MTOT * (HH*HD)];

// 1/sqrt(128) * log2(e)  — folded into Q so flash can use exp2
#define QSCALE (0.08838834764831845f * 1.4426950408889634f)

// ---------------------------------------------------------------------------
// mma.sync / cp.async helpers
// ---------------------------------------------------------------------------
__device__ __forceinline__ uint32_t smem_to_u32(const void* p) {
    uint32_t a;
    asm("{ .reg .u64 t; cvta.to.shared.u64 t, %1; cvt.u32.u64 %0, t; }"
        : "=r"(a) : "l"(p));
    return a;
}

__device__ __forceinline__ uint32_t pack_half2(__half lo, __half hi) {
    return (uint32_t)__half_as_ushort(lo) | ((uint32_t)__half_as_ushort(hi) << 16);
}

__device__ __forceinline__ void ldsm_x4(uint32_t& r0, uint32_t& r1,
                                        uint32_t& r2, uint32_t& r3, uint32_t addr) {
    asm volatile("ldmatrix.sync.aligned.m8n8.x4.shared.b16 {%0,%1,%2,%3}, [%4];"
                 : "=r"(r0), "=r"(r1), "=r"(r2), "=r"(r3) : "r"(addr));
}

__device__ __forceinline__ void ldsm_x4_trans(uint32_t& r0, uint32_t& r1,
                                              uint32_t& r2, uint32_t& r3, uint32_t addr) {
    asm volatile("ldmatrix.sync.aligned.m8n8.x4.trans.shared.b16 {%0,%1,%2,%3}, [%4];"
                 : "=r"(r0), "=r"(r1), "=r"(r2), "=r"(r3) : "r"(addr));
}

__device__ __forceinline__ void mma_f16(float* d, const uint32_t* a,
                                        uint32_t b0, uint32_t b1) {
    asm volatile(
        "mma.sync.aligned.m16n8k16.row.col.f32.f16.f16.f32 "
        "{%0,%1,%2,%3}, {%4,%5,%6,%7}, {%8,%9}, {%0,%1,%2,%3};"
        : "+f"(d[0]), "+f"(d[1]), "+f"(d[2]), "+f"(d[3])
        : "r"(a[0]), "r"(a[1]), "r"(a[2]), "r"(a[3]), "r"(b0), "r"(b1));
}

__device__ __forceinline__ void cp_async16(uint32_t saddr, const void* gaddr) {
    asm volatile("cp.async.cg.shared.global [%0], [%1], 16;"
                 :: "r"(saddr), "l"(gaddr) : "memory");
}
__device__ __forceinline__ void cp_commit() {
    asm volatile("cp.async.commit_group;" ::: "memory");
}

// ---------------------------------------------------------------------------
// Fused prep: convert x to fp16 + transpose all 4 weights (coalesced writes).
// Transpose tile: 32 n-rows x 128 k-cols per block.
// ---------------------------------------------------------------------------
__device__ __forceinline__ void transpose_body(const float* __restrict__ W,
                                               __half* __restrict__ T,
                                               int Kd, int N, int n0, int k0) {
    __shared__ float ts[32][129];
    int lane = threadIdx.x & 31, w = threadIdx.x >> 5;
    // read: 128 k-rows, warp w reads rows w*16 .. +15 (128B per row per warp)
#pragma unroll
    for (int i = 0; i < 16; ++i) {
        int k = w * 16 + i;
        ts[lane][k] = W[(size_t)(k0 + k) * N + n0 + lane];
    }
    __syncthreads();
    // write: 32 output rows; warp w writes rows w*4..+3, 4 halves per lane (256B/row)
#pragma unroll
    for (int j = 0; j < 4; ++j) {
        int n = w * 4 + j;
        float f0 = ts[n][4*lane], f1 = ts[n][4*lane+1];
        float f2 = ts[n][4*lane+2], f3 = ts[n][4*lane+3];
        __half2* dst = (__half2*)(T + (size_t)(n0 + n) * Kd + k0 + 4 * lane);
        dst[0] = __halves2half2(__float2half_rn(f0), __float2half_rn(f1));
        dst[1] = __halves2half2(__float2half_rn(f2), __float2half_rn(f3));
    }
}

__global__ __launch_bounds__(256)
void prep_kernel(const float* __restrict__ x,
                 const float* __restrict__ Wq, const float* __restrict__ Wk,
                 const float* __restrict__ Wv, const float* __restrict__ Wo,
                 __half* __restrict__ Xh, __half* __restrict__ Tq,
                 __half* __restrict__ Tk, __half* __restrict__ Tv,
                 __half* __restrict__ To) {
    int bid = blockIdx.x;
    if (bid < 8192) {
        int i = bid * 256 + threadIdx.x;
        float4 v = ((const float4*)x)[i];
        __half2* hp = (__half2*)(Xh + 4 * (size_t)i);
        hp[0] = __halves2half2(__float2half_rn(v.x), __float2half_rn(v.y));
        hp[1] = __halves2half2(__float2half_rn(v.z), __float2half_rn(v.w));
    } else if (bid < 9216) {
        int l = bid - 8192;                       // Wq: 64 n-blocks x 16 k-blocks
        transpose_body(Wq, Tq, DD, HH*HD, (l & 63) * 32, (l >> 6) * 128);
    } else if (bid < 9728) {
        int l = bid - 9216;                       // Wk: 32 x 16
        transpose_body(Wk, Tk, DD, KK*HD, (l & 31) * 32, (l >> 5) * 128);
    } else if (bid < 10240) {
        int l = bid - 9728;                       // Wv: 32 x 16
        transpose_body(Wv, Tv, DD, KK*HD, (l & 31) * 32, (l >> 5) * 128);
    } else {
        int l = bid - 10240;                      // Wo: 64 x 16
        transpose_body(Wo, To, HH*HD, HH*HD, (l & 63) * 32, (l >> 6) * 128);
    }
}

// ---------------------------------------------------------------------------
// Pure fp16 GEMM with cp.async 3-stage pipeline.
// mode 0: fp32 out (C) ; mode 1: fp16 out (Ch) ;
// mode 2: fused RMSNorm+RoPE epilogue -> fp16 out (Ch), col-tile == one head.
// ---------------------------------------------------------------------------
#define GPAD 40
#define GTILE_BYTES (128 * GPAD * 2)      // 10240
#define GSTAGE_BYTES (2 * GTILE_BYTES)    // 20480 (A, B)
#define GSMEM_DYN (3 * GSTAGE_BYTES)      // 61440 (3 stages)

__device__ __forceinline__ void gemm_core(
    const __half* __restrict__ A, const __half* __restrict__ B,
    float* __restrict__ C, __half* __restrict__ Ch,
    int N, int Kd, int row0, int col0, char* smg, int mode,
    const float* __restrict__ nw, const float* __restrict__ sinp,
    const float* __restrict__ cosp, float oscale) {
    const uint32_t sbase0 = smem_to_u32(smg);

    const int tid = threadIdx.x;
    const int lane = tid & 31;
    const int wid = tid >> 5;
    const int wr = wid & 3;
    const int wc = wid >> 2;

    float d[2][8][4];
#pragma unroll
    for (int m = 0; m < 2; ++m)
#pragma unroll
        for (int n = 0; n < 8; ++n)
#pragma unroll
            for (int j = 0; j < 4; ++j) d[m][n][j] = 0.0f;

    const __half* gb[2] = {A, B};
    int grow[4], gseg[4];
#pragma unroll
    for (int a = 0; a < 2; ++a) {
        int r0 = (a == 0) ? row0 : col0;
        int s0 = tid, s1 = tid + 256;
        grow[2*a]   = r0 + (s0 >> 2); gseg[2*a]   = s0 & 3;
        grow[2*a+1] = r0 + (s1 >> 2); gseg[2*a+1] = s1 & 3;
    }

    auto cp_chunk = [&](int k0, int stage) {
        uint32_t st = sbase0 + stage * GSTAGE_BYTES;
#pragma unroll
        for (int a = 0; a < 2; ++a) {
#pragma unroll
            for (int j = 0; j < 2; ++j) {
                int e = 2 * a + j;
                int s = tid + j * 256;
                uint32_t sa = st + a * GTILE_BYTES + (s >> 2) * (GPAD*2) + (s & 3) * 16;
                cp_async16(sa, gb[a] + (size_t)grow[e] * Kd + k0 + gseg[e] * 8);
            }
        }
        cp_commit();
    };

    const int NC = Kd / 32;

    cp_chunk(0, 0);
    cp_chunk(32, 1);

    for (int c = 0; c < NC; ++c) {
        if (c + 1 < NC) asm volatile("cp.async.wait_group 1;" ::: "memory");
        else            asm volatile("cp.async.wait_group 0;" ::: "memory");
        __syncthreads();

        if (c + 2 < NC) cp_chunk((c + 2) * 32, (c + 2) % 3);

        const uint32_t sb = sbase0 + (c % 3) * GSTAGE_BYTES;
#pragma unroll
        for (int ks = 0; ks < 2; ++ks) {
            const uint32_t coff = ks * 32 + (lane >> 4) * 16;
            uint32_t ah[2][4];
#pragma unroll
            for (int mb = 0; mb < 2; ++mb) {
                uint32_t addr = sb + (wr * 32 + mb * 16 + (lane & 15)) * (GPAD*2) + coff;
                ldsm_x4(ah[mb][0], ah[mb][1], ah[mb][2], ah[mb][3], addr);
            }
            uint32_t bh[4][4];
#pragma unroll
            for (int nb = 0; nb < 4; ++nb) {
                uint32_t addr = sb + GTILE_BYTES +
                                (wc * 64 + nb * 16 + (lane & 15)) * (GPAD*2) + coff;
                ldsm_x4(bh[nb][0], bh[nb][1], bh[nb][2], bh[nb][3], addr);
            }
#pragma unroll
            for (int mb = 0; mb < 2; ++mb) {
#pragma unroll
                for (int nb = 0; nb < 4; ++nb) {
                    mma_f16(d[mb][2*nb],   ah[mb], bh[nb][0], bh[nb][2]);
                    mma_f16(d[mb][2*nb+1], ah[mb], bh[nb][1], bh[nb][3]);
                }
            }
        }
    }

    const int frow = lane >> 2;
    const int fcol = 2 * (lane & 3);

    if (mode == 2) {
        // -------- fused RMSNorm + RoPE epilogue (tile == one head) --------
        __syncthreads();   // all warps done with pipeline smem -> reuse as staging
        __half* stg = (__half*)smg;
        const int SSTR = 132;  // halves per staged row
#pragma unroll
        for (int mb = 0; mb < 2; ++mb) {
#pragma unroll
            for (int nt = 0; nt < 8; ++nt) {
                int r = wr * 32 + mb * 16 + frow;
                int cc = wc * 64 + nt * 8 + fcol;
                *(__half2*)&stg[r * SSTR + cc] =
                    __halves2half2(__float2half_rn(d[mb][nt][0]), __float2half_rn(d[mb][nt][1]));
                *(__half2*)&stg[(r + 8) * SSTR + cc] =
                    __halves2half2(__float2half_rn(d[mb][nt][2]), __float2half_rn(d[mb][nt][3]));
            }
        }
        __syncthreads();

        float w0 = nw[2 * lane],      w1 = nw[2 * lane + 1];
        float w2 = nw[64 + 2 * lane], w3 = nw[65 + 2 * lane];
#pragma unroll 4
        for (int i = 0; i < 16; ++i) {
            int r = wid * 16 + i;
            int grow_t = row0 + r;
            int t = grow_t & (TT - 1);
            __half2 a2 = *(__half2*)&stg[r * SSTR + 2 * lane];
            __half2 c2 = *(__half2*)&stg[r * SSTR + 64 + 2 * lane];
            float ax = __low2float(a2), ay = __high2float(a2);
            float bx = __low2float(c2), by = __high2float(c2);

            float ss = ax * ax + ay * ay + bx * bx + by * by;
#pragma unroll
            for (int o = 16; o; o >>= 1) ss += __shfl_xor_sync(0xFFFFFFFFu, ss, o);
            float rinv = rsqrtf(ss * (1.0f / 128.0f) + 1e-6f);

            float n0 = ax * rinv * w0, n1 = ay * rinv * w1;
            float n2 = bx * rinv * w2, n3 = by * rinv * w3;

            float s0 = sinp[t * 64 + lane],      c0 = cosp[t * 64 + lane];
            float s1 = sinp[t * 64 + lane + 32], c1 = cosp[t * 64 + lane + 32];
            float o0 = (n0 * c0 - n1 * s0) * oscale;
            float o1 = (n2 * c1 - n3 * s1) * oscale;
            float o2 = (n0 * s0 + n1 * c0) * oscale;
            float o3 = (n2 * s1 + n3 * c1) * oscale;

            __half* ptr = Ch + (size_t)grow_t * N + col0;
            ptr[lane]      = __float2half_rn(o0);
            ptr[lane + 32] = __float2half_rn(o1);
            ptr[lane + 64] = __float2half_rn(o2);
            ptr[lane + 96] = __float2half_rn(o3);
        }
        return;
    }

#pragma unroll
    for (int mb = 0; mb < 2; ++mb) {
#pragma unroll
        for (int nt = 0; nt < 8; ++nt) {
            int r = row0 + wr * 32 + mb * 16 + frow;
            int cc = col0 + wc * 64 + nt * 8 + fcol;
            if (mode == 1) {
                *(__half2*)&Ch[(size_t)r * N + cc] =
                    __halves2half2(__float2half_rn(d[mb][nt][0]), __float2half_rn(d[mb][nt][1]));
                *(__half2*)&Ch[(size_t)(r + 8) * N + cc] =
                    __halves2half2(__float2half_rn(d[mb][nt][2]), __float2half_rn(d[mb][nt][3]));
            } else {
                *(float2*)&C[(size_t)r * N + cc]       = make_float2(d[mb][nt][0], d[mb][nt][1]);
                *(float2*)&C[(size_t)(r + 8) * N + cc] = make_float2(d[mb][nt][2], d[mb][nt][3]);
            }
        }
    }
}

__global__ __launch_bounds__(256, 2)
void gemm_mma(const __half* __restrict__ A, const __half* __restrict__ B,
              float* __restrict__ C, int N, int Kd) {
    extern __shared__ char smg[];
    gemm_core(A, B, C, nullptr, N, Kd, blockIdx.y * 128, blockIdx.x * 128, smg,
              0, nullptr, nullptr, nullptr, 1.0f);
}

// Fused QKV + normrope epilogue: ct 0-15 Q (norm+rope, QSCALE), 16-23 K
// (norm+rope), 24-31 V (plain fp16).
__global__ __launch_bounds__(256, 2)
void gemm_qkv(const __half* __restrict__ Xhi,
              const __half* __restrict__ Wq, const __half* __restrict__ Wk,
              const __half* __restrict__ Wv,
              __half* __restrict__ Qh, __half* __restrict__ Kh, __half* __restrict__ Vh,
              const float* __restrict__ qn, const float* __restrict__ kn,
              const float* __restrict__ sinp, const float* __restrict__ cosp) {
    extern __shared__ char smg[];
    int ct = blockIdx.x;
    if (ct < 16) {
        gemm_core(Xhi, Wq, nullptr, Qh, HH*HD, DD, blockIdx.y * 128, ct * 128, smg,
                  2, qn, sinp, cosp, QSCALE);
    } else if (ct < 24) {
        gemm_core(Xhi, Wk, nullptr, Kh, KK*HD, DD, blockIdx.y * 128, (ct - 16) * 128, smg,
                  2, kn, sinp, cosp, 1.0f);
    } else {
        gemm_core(Xhi, Wv, nullptr, Vh, KK*HD, DD, blockIdx.y * 128, (ct - 24) * 128, smg,
                  1, nullptr, nullptr, nullptr, 1.0f);
    }
}

// ---------------------------------------------------------------------------
// Flash attention: pure-fp16 mma (fp32 softmax/accum, exp2 units — Q carries
// scale*log2e), 128-row Q tile, 8 warps x 16 rows, register softmax + P
// fragments, double-buffered K/V, ONE barrier per K-tile, 2 CTAs/SM.
// ---------------------------------------------------------------------------
#define FK_STRB 272                 // bytes per 128-wide fp16 row (136 halves)
#define FQ_TILE (128 * FK_STRB)     // 34816
#define FKV_TILE (64 * FK_STRB)     // 17408
#define F4_Q 0
#define F4_KV FQ_TILE
#define FA5_SMEM (FQ_TILE + 2 * 2 * FKV_TILE)   // 104448 -> 2 CTAs/SM

__global__ __launch_bounds__(256, 2)
void flash_mma(const __half* __restrict__ Qhi,
               const __half* __restrict__ Khi, const __half* __restrict__ Vhi,
               __half* __restrict__ Ohi) {
    extern __shared__ char sm[];
    const uint32_t sb = smem_to_u32(sm);

    const int qt = gridDim.x - 1 - blockIdx.x;
    const int bh = blockIdx.y;
    const int b = bh >> 4;
    const int h = bh & 15;
    const int kh = h >> 1;

    const int tid = threadIdx.x;
    const int lane = tid & 31;
    const int wid = tid >> 5;
    const int frow = lane >> 2;
    const int fcol = 2 * (lane & 3);

    const int qrow0 = qt * 128 + wid * 16;
    const int ktmax = 2 * qt + 1;

    const __half* qh = Qhi + ((size_t)(b * TT + qt * 128)) * (HH*HD) + h * HD;
    const __half* kbase = Khi + ((size_t)(b * TT)) * (KK*HD) + kh * HD;
    const __half* vbase = Vhi + ((size_t)(b * TT)) * (KK*HD) + kh * HD;

    auto cp_kv = [&](int kt, int stage) {
        uint32_t st = sb + F4_KV + stage * 2 * FKV_TILE;
        const __half* kp = kbase + (size_t)(kt * 64) * (KK*HD);
        const __half* vp = vbase + (size_t)(kt * 64) * (KK*HD);
#pragma unroll
        for (int j = 0; j < 4; ++j) {
            int idx = tid + j * 256;
            int r = idx >> 4, s = idx & 15;
            uint32_t so = r * FK_STRB + s * 16;
            cp_async16(st + so,            kp + (size_t)r * (KK*HD) + s * 8);
            cp_async16(st + FKV_TILE + so, vp + (size_t)r * (KK*HD) + s * 8);
        }
        cp_commit();
    };

    {
#pragma unroll
        for (int j = 0; j < 8; ++j) {
            int idx = tid + j * 256;
            int r = idx >> 4, s = idx & 15;
            cp_async16(sb + F4_Q + r * FK_STRB + s * 16,
                       qh + (size_t)r * (HH*HD) + s * 8);
        }
        cp_commit();
        cp_kv(0, 0);
    }

    float o[16][4];
#pragma unroll
    for (int n = 0; n < 16; ++n)
#pragma unroll
        for (int j = 0; j < 4; ++j) o[n][j] = 0.0f;
    float m0 = -INFINITY, m1 = -INFINITY, l0 = 0.0f, l1 = 0.0f;

    for (int kt = 0; kt <= ktmax; ++kt) {
        asm volatile("cp.async.wait_group 0;" ::: "memory");
        __syncthreads();
        if (kt < ktmax) cp_kv(kt + 1, (kt + 1) & 1);

        const uint32_t kvs = sb + F4_KV + (kt & 1) * 2 * FKV_TILE;

        // ---- S = Q @ K^T (Q pre-scaled, exp2 units) ----
        float s[8][4];
#pragma unroll
        for (int i = 0; i < 8; ++i)
#pragma unroll
            for (int j = 0; j < 4; ++j) s[i][j] = 0.0f;

#pragma unroll
        for (int ks = 0; ks < 8; ++ks) {
            const uint32_t coff = ks * 32 + (lane >> 4) * 16;
            uint32_t aq[4];
            {
                uint32_t addr = sb + F4_Q + (wid * 16 + (lane & 15)) * FK_STRB + coff;
                ldsm_x4(aq[0], aq[1], aq[2], aq[3], addr);
            }
            uint32_t kb[4][4];
#pragma unroll
            for (int nb = 0; nb < 4; ++nb) {
                uint32_t addr = kvs + (nb * 16 + (lane & 15)) * FK_STRB + coff;
                ldsm_x4(kb[nb][0], kb[nb][1], kb[nb][2], kb[nb][3], addr);
            }
#pragma unroll
            for (int nb = 0; nb < 4; ++nb) {
                mma_f16(s[2*nb],   aq, kb[nb][0], kb[nb][2]);
                mma_f16(s[2*nb+1], aq, kb[nb][1], kb[nb][3]);
            }
        }

        // ---- causal mask ----
        bool boundary = (kt * 64 + 63 > qrow0);
        if (boundary) {
#pragma unroll
            for (int nt = 0; nt < 8; ++nt) {
                int c = kt * 64 + nt * 8 + fcol;
                int r0 = qrow0 + frow, r1 = r0 + 8;
                if (c     > r0) s[nt][0] = -INFINITY;
                if (c + 1 > r0) s[nt][1] = -INFINITY;
                if (c     > r1) s[nt][2] = -INFINITY;
                if (c + 1 > r1) s[nt][3] = -INFINITY;
            }
        }

        // ---- register online softmax (exp2) ----
        float mx0 = -INFINITY, mx1 = -INFINITY;
#pragma unroll
        for (int nt = 0; nt < 8; ++nt) {
            mx0 = fmaxf(mx0, fmaxf(s[nt][0], s[nt][1]));
            mx1 = fmaxf(mx1, fmaxf(s[nt][2], s[nt][3]));
        }
        mx0 = fmaxf(mx0, __shfl_xor_sync(0xFFFFFFFFu, mx0, 1));
        mx0 = fmaxf(mx0, __shfl_xor_sync(0xFFFFFFFFu, mx0, 2));
        mx1 = fmaxf(mx1, __shfl_xor_sync(0xFFFFFFFFu, mx1, 1));
        mx1 = fmaxf(mx1, __shfl_xor_sync(0xFFFFFFFFu, mx1, 2));
        mx0 = fmaxf(mx0, m0);
        mx1 = fmaxf(mx1, m1);
        float a0 = exp2f(m0 - mx0);
        float a1 = exp2f(m1 - mx1);
        float sum0 = 0.0f, sum1 = 0.0f;
#pragma unroll
        for (int nt = 0; nt < 8; ++nt) {
            s[nt][0] = exp2f(s[nt][0] - mx0); sum0 += s[nt][0];
            s[nt][1] = exp2f(s[nt][1] - mx0); sum0 += s[nt][1];
            s[nt][2] = exp2f(s[nt][2] - mx1); sum1 += s[nt][2];
            s[nt][3] = exp2f(s[nt][3] - mx1); sum1 += s[nt][3];
        }
        sum0 += __shfl_xor_sync(0xFFFFFFFFu, sum0, 1);
        sum0 += __shfl_xor_sync(0xFFFFFFFFu, sum0, 2);
        sum1 += __shfl_xor_sync(0xFFFFFFFFu, sum1, 1);
        sum1 += __shfl_xor_sync(0xFFFFFFFFu, sum1, 2);
        l0 = l0 * a0 + sum0;  m0 = mx0;
        l1 = l1 * a1 + sum1;  m1 = mx1;

#pragma unroll
        for (int nt = 0; nt < 16; ++nt) {
            o[nt][0] *= a0; o[nt][1] *= a0;
            o[nt][2] *= a1; o[nt][3] *= a1;
        }

        // ---- O += P @ V ----
#pragma unroll
        for (int j = 0; j < 4; ++j) {
            uint32_t ap[4];
            {
                __half ph[8];
#pragma unroll
                for (int e = 0; e < 4; ++e) {
                    ph[e]     = __float2half_rn(s[2*j][e]);
                    ph[4 + e] = __float2half_rn(s[2*j+1][e]);
                }
                ap[0] = pack_half2(ph[0], ph[1]);
                ap[1] = pack_half2(ph[2], ph[3]);
                ap[2] = pack_half2(ph[4], ph[5]);
                ap[3] = pack_half2(ph[6], ph[7]);
            }
#pragma unroll
            for (int g = 0; g < 2; ++g) {
                uint32_t vh[4][4];
#pragma unroll
                for (int q = 0; q < 4; ++q) {
                    int nb = g * 4 + q;
                    uint32_t addr = kvs + FKV_TILE
                                  + (j * 16 + (lane & 15)) * FK_STRB
                                  + (nb * 16 + (lane >> 4) * 8) * 2;
                    ldsm_x4_trans(vh[q][0], vh[q][1], vh[q][2], vh[q][3], addr);
                }
#pragma unroll
                for (int q = 0; q < 4; ++q) {
                    int nb = g * 4 + q;
                    mma_f16(o[2*nb],   ap, vh[q][0], vh[q][1]);
                    mma_f16(o[2*nb+1], ap, vh[q][2], vh[q][3]);
                }
            }
        }
    }

    // Epilogue
    {
        float li0 = 1.0f / l0;
        float li1 = 1.0f / l1;
        int r0g = b * TT + qt * 128 + wid * 16 + frow;
#pragma unroll
        for (int nt = 0; nt < 16; ++nt) {
            int c = nt * 8 + fcol;
            size_t o0 = (size_t)r0g * (HH*HD) + h * HD + c;
            size_t o1 = (size_t)(r0g + 8) * (HH*HD) + h * HD + c;
            *(__half2*)&Ohi[o0] = __halves2half2(__float2half_rn(o[nt][0] * li0),
                                                 __float2half_rn(o[nt][1] * li0));
            *(__half2*)&Ohi[o1] = __halves2half2(__float2half_rn(o[nt][2] * li1),
                                                 __float2half_rn(o[nt][3] * li1));
        }
    }
}

// ---------------------------------------------------------------------------
extern "C" void kernel_launch(void* const* d_in, const int* in_sizes, int n_in,
                              void* d_out, int out_size) {
    const float* x    = (const float*)d_in[0];
    const float* Wq   = (const float*)d_in[1];
    const float* Wk   = (const float*)d_in[2];
    const float* Wv   = (const float*)d_in[3];
    const float* Wo   = (const float*)d_in[4];
    const float* qn   = (const float*)d_in[5];
    const float* kn   = (const float*)d_in[6];
    const float* sinp = (const float*)d_in[7];
    const float* cosp = (const float*)d_in[8];
    float* out = (float*)d_out;

    __half *xhi, *wqt, *wkt, *wvt, *wot;
    __half *qhi, *khi, *vhi, *ohi;
    cudaGetSymbolAddress((void**)&xhi, g_xhi);
    cudaGetSymbolAddress((void**)&wqt, g_wqt);
    cudaGetSymbolAddress((void**)&wkt, g_wkt);
    cudaGetSymbolAddress((void**)&wvt, g_wvt);
    cudaGetSymbolAddress((void**)&wot, g_wot);
    cudaGetSymbolAddress((void**)&qhi, g_qhi);
    cudaGetSymbolAddress((void**)&khi, g_khi);
    cudaGetSymbolAddress((void**)&vhi, g_vhi);
    cudaGetSymbolAddress((void**)&ohi, g_ohi);

    // 1. fused prep: convert x + transpose all weights (coalesced)
    prep_kernel<<<11264, 256>>>(x, Wq, Wk, Wv, Wo, xhi, wqt, wkt, wvt, wot);

    // 2. fused QKV projection + RMSNorm/RoPE epilogue (Q pre-scaled for exp2)
    cudaFuncSetAttribute(gemm_qkv, cudaFuncAttributeMaxDynamicSharedMemorySize, GSMEM_DYN);
    gemm_qkv<<<dim3(32, MTOT/128), 256, GSMEM_DYN>>>(xhi, wqt, wkt, wvt,
                                                     qhi, khi, vhi,
                                                     qn, kn, sinp, cosp);

    // 3. causal flash attention (exp2 softmax, double-buffered, 2 CTAs/SM)
    cudaFuncSetAttribute(flash_mma, cudaFuncAttributeMaxDynamicSharedMemorySize, FA5_SMEM);
    flash_mma<<<dim3(TT / 128, BB * HH), 256, FA5_SMEM>>>(qhi, khi, vhi, ohi);

    // 4. output projection (pure fp16, fp32 out)
    cudaFuncSetAttribute(gemm_mma, cudaFuncAttributeMaxDynamicSharedMemorySize, GSMEM_DYN);
    gemm_mma<<<dim3((HH*HD)/128, MTOT/128), 256, GSMEM_DYN>>>(ohi, wot, out, HH*HD, HH*HD);
}

// round 15
// speedup vs baseline: 7.6593x; 1.0961x over previous
#include <cuda_runtime.h>
#include <cuda_fp16.h>
#include <math.h>
#include <cstdint>

// Problem constants
#define BB 2
#define TT 2048
#define DD 2048
#define HH 16
#define KK 8
#define HD 128
#define MTOT (BB*TT)   // 4096

// ---------------------------------------------------------------------------
// Scratch (device globals; no allocation allowed)
// ---------------------------------------------------------------------------
__device__ __half g_xhi [(size_t)MTOT * DD];
__device__ __half g_wqt [(size_t)(HH*HD) * DD];
__device__ __half g_wkt [(size_t)(KK*HD) * DD];
__device__ __half g_wvt [(size_t)(KK*HD) * DD];
__device__ __half g_wot [(size_t)DD * (HH*HD)];
__device__ __half g_qhi [(size_t)MTOT * (HH*HD)];
__device__ __half g_khi [(size_t)MTOT * (KK*HD)];
__device__ __half g_vhi [(size_t)MTOT * (KK*HD)];
__device__ __half g_ohi [(size_t)MTOT * (HH*HD)];

// 1/sqrt(128) * log2(e)  — folded into Q so flash can use exp2
#define QSCALE (0.08838834764831845f * 1.4426950408889634f)

// ---------------------------------------------------------------------------
// mma.sync / cp.async helpers
// ---------------------------------------------------------------------------
__device__ __forceinline__ uint32_t smem_to_u32(const void* p) {
    uint32_t a;
    asm("{ .reg .u64 t; cvta.to.shared.u64 t, %1; cvt.u32.u64 %0, t; }"
        : "=r"(a) : "l"(p));
    return a;
}

__device__ __forceinline__ uint32_t pack_half2(__half lo, __half hi) {
    return (uint32_t)__half_as_ushort(lo) | ((uint32_t)__half_as_ushort(hi) << 16);
}

__device__ __forceinline__ void ldsm_x4(uint32_t& r0, uint32_t& r1,
                                        uint32_t& r2, uint32_t& r3, uint32_t addr) {
    asm volatile("ldmatrix.sync.aligned.m8n8.x4.shared.b16 {%0,%1,%2,%3}, [%4];"
                 : "=r"(r0), "=r"(r1), "=r"(r2), "=r"(r3) : "r"(addr));
}

__device__ __forceinline__ void ldsm_x4_trans(uint32_t& r0, uint32_t& r1,
                                              uint32_t& r2, uint32_t& r3, uint32_t addr) {
    asm volatile("ldmatrix.sync.aligned.m8n8.x4.trans.shared.b16 {%0,%1,%2,%3}, [%4];"
                 : "=r"(r0), "=r"(r1), "=r"(r2), "=r"(r3) : "r"(addr));
}

__device__ __forceinline__ void mma_f16(float* d, const uint32_t* a,
                                        uint32_t b0, uint32_t b1) {
    asm volatile(
        "mma.sync.aligned.m16n8k16.row.col.f32.f16.f16.f32 "
        "{%0,%1,%2,%3}, {%4,%5,%6,%7}, {%8,%9}, {%0,%1,%2,%3};"
        : "+f"(d[0]), "+f"(d[1]), "+f"(d[2]), "+f"(d[3])
        : "r"(a[0]), "r"(a[1]), "r"(a[2]), "r"(a[3]), "r"(b0), "r"(b1));
}

__device__ __forceinline__ void cp_async16(uint32_t saddr, const void* gaddr) {
    asm volatile("cp.async.cg.shared.global [%0], [%1], 16;"
                 :: "r"(saddr), "l"(gaddr) : "memory");
}
__device__ __forceinline__ void cp_commit() {
    asm volatile("cp.async.commit_group;" ::: "memory");
}

// ---------------------------------------------------------------------------
// Fused prep: convert x to fp16 + transpose all 4 weights (coalesced writes).
// ---------------------------------------------------------------------------
__device__ __forceinline__ void transpose_body(const float* __restrict__ W,
                                               __half* __restrict__ T,
                                               int Kd, int N, int n0, int k0) {
    __shared__ float ts[32][129];
    int lane = threadIdx.x & 31, w = threadIdx.x >> 5;
#pragma unroll
    for (int i = 0; i < 16; ++i) {
        int k = w * 16 + i;
        ts[lane][k] = W[(size_t)(k0 + k) * N + n0 + lane];
    }
    __syncthreads();
#pragma unroll
    for (int j = 0; j < 4; ++j) {
        int n = w * 4 + j;
        float f0 = ts[n][4*lane], f1 = ts[n][4*lane+1];
        float f2 = ts[n][4*lane+2], f3 = ts[n][4*lane+3];
        __half2* dst = (__half2*)(T + (size_t)(n0 + n) * Kd + k0 + 4 * lane);
        dst[0] = __halves2half2(__float2half_rn(f0), __float2half_rn(f1));
        dst[1] = __halves2half2(__float2half_rn(f2), __float2half_rn(f3));
    }
}

__global__ __launch_bounds__(256)
void prep_kernel(const float* __restrict__ x,
                 const float* __restrict__ Wq, const float* __restrict__ Wk,
                 const float* __restrict__ Wv, const float* __restrict__ Wo,
                 __half* __restrict__ Xh, __half* __restrict__ Tq,
                 __half* __restrict__ Tk, __half* __restrict__ Tv,
                 __half* __restrict__ To) {
    int bid = blockIdx.x;
    if (bid < 8192) {
        int i = bid * 256 + threadIdx.x;
        float4 v = ((const float4*)x)[i];
        __half2* hp = (__half2*)(Xh + 4 * (size_t)i);
        hp[0] = __halves2half2(__float2half_rn(v.x), __float2half_rn(v.y));
        hp[1] = __halves2half2(__float2half_rn(v.z), __float2half_rn(v.w));
    } else if (bid < 9216) {
        int l = bid - 8192;                       // Wq: 64 n x 16 k
        transpose_body(Wq, Tq, DD, HH*HD, (l & 63) * 32, (l >> 6) * 128);
    } else if (bid < 9728) {
        int l = bid - 9216;                       // Wk: 32 x 16
        transpose_body(Wk, Tk, DD, KK*HD, (l & 31) * 32, (l >> 5) * 128);
    } else if (bid < 10240) {
        int l = bid - 9728;                       // Wv: 32 x 16
        transpose_body(Wv, Tv, DD, KK*HD, (l & 31) * 32, (l >> 5) * 128);
    } else {
        int l = bid - 10240;                      // Wo: 64 x 16
        transpose_body(Wo, To, HH*HD, HH*HD, (l & 63) * 32, (l >> 6) * 128);
    }
}

// ---------------------------------------------------------------------------
// Pure fp16 GEMM, K-chunk 64, 2-stage double buffer, ONE barrier per chunk.
// mode 0: fp32 out ; mode 1: fp16 out ; mode 2: fused RMSNorm+RoPE epilogue.
// Row stride 144B: ldsm phase banks = 4r mod 32, conflict-free.
// ---------------------------------------------------------------------------
#define GPADH 72                            // halves per smem row (64 data + 8 pad)
#define GTILE_BYTES (128 * GPADH * 2)       // 18432
#define GSTAGE_BYTES (2 * GTILE_BYTES)      // 36864 (A, B)
#define GSMEM_DYN (2 * GSTAGE_BYTES)        // 73728 (2 stages) -> 2 CTAs/SM

__device__ __forceinline__ void gemm_core(
    const __half* __restrict__ A, const __half* __restrict__ B,
    float* __restrict__ C, __half* __restrict__ Ch,
    int N, int Kd, int row0, int col0, char* smg, int mode,
    const float* __restrict__ nw, const float* __restrict__ sinp,
    const float* __restrict__ cosp, float oscale) {
    const uint32_t sbase0 = smem_to_u32(smg);

    const int tid = threadIdx.x;
    const int lane = tid & 31;
    const int wid = tid >> 5;
    const int wr = wid & 3;
    const int wc = wid >> 2;

    float d[2][8][4];
#pragma unroll
    for (int m = 0; m < 2; ++m)
#pragma unroll
        for (int n = 0; n < 8; ++n)
#pragma unroll
            for (int j = 0; j < 4; ++j) d[m][n][j] = 0.0f;

    // per-thread load plan: 4 uint4 per tile per chunk (128 rows x 8 segs)
    const int lrow = tid >> 3;          // 0..31 (+32*j)
    const int lseg = tid & 7;           // 0..7

    auto cp_chunk = [&](int k0, int stage) {
        uint32_t st = sbase0 + stage * GSTAGE_BYTES;
#pragma unroll
        for (int j = 0; j < 4; ++j) {
            int r = lrow + j * 32;
            uint32_t so = r * (GPADH * 2) + lseg * 16;
            cp_async16(st + so,
                       A + (size_t)(row0 + r) * Kd + k0 + lseg * 8);
            cp_async16(st + GTILE_BYTES + so,
                       B + (size_t)(col0 + r) * Kd + k0 + lseg * 8);
        }
        cp_commit();
    };

    const int NC = Kd / 64;

    cp_chunk(0, 0);

    for (int c = 0; c < NC; ++c) {
        asm volatile("cp.async.wait_group 0;" ::: "memory");
        __syncthreads();
        if (c + 1 < NC) cp_chunk((c + 1) * 64, (c + 1) & 1);

        const uint32_t sb = sbase0 + (c & 1) * GSTAGE_BYTES;
#pragma unroll
        for (int ks = 0; ks < 4; ++ks) {
            const uint32_t coff = ks * 32 + (lane >> 4) * 16;
            uint32_t ah[2][4];
#pragma unroll
            for (int mb = 0; mb < 2; ++mb) {
                uint32_t addr = sb + (wr * 32 + mb * 16 + (lane & 15)) * (GPADH*2) + coff;
                ldsm_x4(ah[mb][0], ah[mb][1], ah[mb][2], ah[mb][3], addr);
            }
            uint32_t bh[4][4];
#pragma unroll
            for (int nb = 0; nb < 4; ++nb) {
                uint32_t addr = sb + GTILE_BYTES +
                                (wc * 64 + nb * 16 + (lane & 15)) * (GPADH*2) + coff;
                ldsm_x4(bh[nb][0], bh[nb][1], bh[nb][2], bh[nb][3], addr);
            }
#pragma unroll
            for (int mb = 0; mb < 2; ++mb) {
#pragma unroll
                for (int nb = 0; nb < 4; ++nb) {
                    mma_f16(d[mb][2*nb],   ah[mb], bh[nb][0], bh[nb][2]);
                    mma_f16(d[mb][2*nb+1], ah[mb], bh[nb][1], bh[nb][3]);
                }
            }
        }
    }

    const int frow = lane >> 2;
    const int fcol = 2 * (lane & 3);

    if (mode == 2) {
        // -------- fused RMSNorm + RoPE epilogue (tile == one head) --------
        __syncthreads();
        __half* stg = (__half*)smg;
        const int SSTR = 132;
#pragma unroll
        for (int mb = 0; mb < 2; ++mb) {
#pragma unroll
            for (int nt = 0; nt < 8; ++nt) {
                int r = wr * 32 + mb * 16 + frow;
                int cc = wc * 64 + nt * 8 + fcol;
                *(__half2*)&stg[r * SSTR + cc] =
                    __halves2half2(__float2half_rn(d[mb][nt][0]), __float2half_rn(d[mb][nt][1]));
                *(__half2*)&stg[(r + 8) * SSTR + cc] =
                    __halves2half2(__float2half_rn(d[mb][nt][2]), __float2half_rn(d[mb][nt][3]));
            }
        }
        __syncthreads();

        float w0 = nw[2 * lane],      w1 = nw[2 * lane + 1];
        float w2 = nw[64 + 2 * lane], w3 = nw[65 + 2 * lane];
#pragma unroll 4
        for (int i = 0; i < 16; ++i) {
            int r = wid * 16 + i;
            int grow_t = row0 + r;
            int t = grow_t & (TT - 1);
            __half2 a2 = *(__half2*)&stg[r * SSTR + 2 * lane];
            __half2 c2 = *(__half2*)&stg[r * SSTR + 64 + 2 * lane];
            float ax = __low2float(a2), ay = __high2float(a2);
            float bx = __low2float(c2), by = __high2float(c2);

            float ss = ax * ax + ay * ay + bx * bx + by * by;
#pragma unroll
            for (int o = 16; o; o >>= 1) ss += __shfl_xor_sync(0xFFFFFFFFu, ss, o);
            float rinv = rsqrtf(ss * (1.0f / 128.0f) + 1e-6f);

            float n0 = ax * rinv * w0, n1 = ay * rinv * w1;
            float n2 = bx * rinv * w2, n3 = by * rinv * w3;

            float s0 = sinp[t * 64 + lane],      c0 = cosp[t * 64 + lane];
            float s1 = sinp[t * 64 + lane + 32], c1 = cosp[t * 64 + lane + 32];
            float o0 = (n0 * c0 - n1 * s0) * oscale;
            float o1 = (n2 * c1 - n3 * s1) * oscale;
            float o2 = (n0 * s0 + n1 * c0) * oscale;
            float o3 = (n2 * s1 + n3 * c1) * oscale;

            __half* ptr = Ch + (size_t)grow_t * N + col0;
            ptr[lane]      = __float2half_rn(o0);
            ptr[lane + 32] = __float2half_rn(o1);
            ptr[lane + 64] = __float2half_rn(o2);
            ptr[lane + 96] = __float2half_rn(o3);
        }
        return;
    }

#pragma unroll
    for (int mb = 0; mb < 2; ++mb) {
#pragma unroll
        for (int nt = 0; nt < 8; ++nt) {
            int r = row0 + wr * 32 + mb * 16 + frow;
            int cc = col0 + wc * 64 + nt * 8 + fcol;
            if (mode == 1) {
                *(__half2*)&Ch[(size_t)r * N + cc] =
                    __halves2half2(__float2half_rn(d[mb][nt][0]), __float2half_rn(d[mb][nt][1]));
                *(__half2*)&Ch[(size_t)(r + 8) * N + cc] =
                    __halves2half2(__float2half_rn(d[mb][nt][2]), __float2half_rn(d[mb][nt][3]));
            } else {
                *(float2*)&C[(size_t)r * N + cc]       = make_float2(d[mb][nt][0], d[mb][nt][1]);
                *(float2*)&C[(size_t)(r + 8) * N + cc] = make_float2(d[mb][nt][2], d[mb][nt][3]);
            }
        }
    }
}

__global__ __launch_bounds__(256, 2)
void gemm_mma(const __half* __restrict__ A, const __half* __restrict__ B,
              float* __restrict__ C, int N, int Kd) {
    extern __shared__ char smg[];
    gemm_core(A, B, C, nullptr, N, Kd, blockIdx.y * 128, blockIdx.x * 128, smg,
              0, nullptr, nullptr, nullptr, 1.0f);
}

__global__ __launch_bounds__(256, 2)
void gemm_qkv(const __half* __restrict__ Xhi,
              const __half* __restrict__ Wq, const __half* __restrict__ Wk,
              const __half* __restrict__ Wv,
              __half* __restrict__ Qh, __half* __restrict__ Kh, __half* __restrict__ Vh,
              const float* __restrict__ qn, const float* __restrict__ kn,
              const float* __restrict__ sinp, const float* __restrict__ cosp) {
    extern __shared__ char smg[];
    int ct = blockIdx.x;
    if (ct < 16) {
        gemm_core(Xhi, Wq, nullptr, Qh, HH*HD, DD, blockIdx.y * 128, ct * 128, smg,
                  2, qn, sinp, cosp, QSCALE);
    } else if (ct < 24) {
        gemm_core(Xhi, Wk, nullptr, Kh, KK*HD, DD, blockIdx.y * 128, (ct - 16) * 128, smg,
                  2, kn, sinp, cosp, 1.0f);
    } else {
        gemm_core(Xhi, Wv, nullptr, Vh, KK*HD, DD, blockIdx.y * 128, (ct - 24) * 128, smg,
                  1, nullptr, nullptr, nullptr, 1.0f);
    }
}

// ---------------------------------------------------------------------------
// Flash attention: pure-fp16 mma (fp32 softmax/accum, exp2 units), 128-row
// Q tile, 8 warps x 16 rows, register softmax + P fragments, double-buffered
// K/V, ONE barrier per K-tile, 2 CTAs/SM. (unchanged from R14)
// ---------------------------------------------------------------------------
#define FK_STRB 272
#define FQ_TILE (128 * FK_STRB)
#define FKV_TILE (64 * FK_STRB)
#define F4_Q 0
#define F4_KV FQ_TILE
#define FA5_SMEM (FQ_TILE + 2 * 2 * FKV_TILE)   // 104448 -> 2 CTAs/SM

__global__ __launch_bounds__(256, 2)
void flash_mma(const __half* __restrict__ Qhi,
               const __half* __restrict__ Khi, const __half* __restrict__ Vhi,
               __half* __restrict__ Ohi) {
    extern __shared__ char sm[];
    const uint32_t sb = smem_to_u32(sm);

    const int qt = gridDim.x - 1 - blockIdx.x;
    const int bh = blockIdx.y;
    const int b = bh >> 4;
    const int h = bh & 15;
    const int kh = h >> 1;

    const int tid = threadIdx.x;
    const int lane = tid & 31;
    const int wid = tid >> 5;
    const int frow = lane >> 2;
    const int fcol = 2 * (lane & 3);

    const int qrow0 = qt * 128 + wid * 16;
    const int ktmax = 2 * qt + 1;

    const __half* qh = Qhi + ((size_t)(b * TT + qt * 128)) * (HH*HD) + h * HD;
    const __half* kbase = Khi + ((size_t)(b * TT)) * (KK*HD) + kh * HD;
    const __half* vbase = Vhi + ((size_t)(b * TT)) * (KK*HD) + kh * HD;

    auto cp_kv = [&](int kt, int stage) {
        uint32_t st = sb + F4_KV + stage * 2 * FKV_TILE;
        const __half* kp = kbase + (size_t)(kt * 64) * (KK*HD);
        const __half* vp = vbase + (size_t)(kt * 64) * (KK*HD);
#pragma unroll
        for (int j = 0; j < 4; ++j) {
            int idx = tid + j * 256;
            int r = idx >> 4, s = idx & 15;
            uint32_t so = r * FK_STRB + s * 16;
            cp_async16(st + so,            kp + (size_t)r * (KK*HD) + s * 8);
            cp_async16(st + FKV_TILE + so, vp + (size_t)r * (KK*HD) + s * 8);
        }
        cp_commit();
    };

    {
#pragma unroll
        for (int j = 0; j < 8; ++j) {
            int idx = tid + j * 256;
            int r = idx >> 4, s = idx & 15;
            cp_async16(sb + F4_Q + r * FK_STRB + s * 16,
                       qh + (size_t)r * (HH*HD) + s * 8);
        }
        cp_commit();
        cp_kv(0, 0);
    }

    float o[16][4];
#pragma unroll
    for (int n = 0; n < 16; ++n)
#pragma unroll
        for (int j = 0; j < 4; ++j) o[n][j] = 0.0f;
    float m0 = -INFINITY, m1 = -INFINITY, l0 = 0.0f, l1 = 0.0f;

    for (int kt = 0; kt <= ktmax; ++kt) {
        asm volatile("cp.async.wait_group 0;" ::: "memory");
        __syncthreads();
        if (kt < ktmax) cp_kv(kt + 1, (kt + 1) & 1);

        const uint32_t kvs = sb + F4_KV + (kt & 1) * 2 * FKV_TILE;

        float s[8][4];
#pragma unroll
        for (int i = 0; i < 8; ++i)
#pragma unroll
            for (int j = 0; j < 4; ++j) s[i][j] = 0.0f;

#pragma unroll
        for (int ks = 0; ks < 8; ++ks) {
            const uint32_t coff = ks * 32 + (lane >> 4) * 16;
            uint32_t aq[4];
            {
                uint32_t addr = sb + F4_Q + (wid * 16 + (lane & 15)) * FK_STRB + coff;
                ldsm_x4(aq[0], aq[1], aq[2], aq[3], addr);
            }
            uint32_t kb[4][4];
#pragma unroll
            for (int nb = 0; nb < 4; ++nb) {
                uint32_t addr = kvs + (nb * 16 + (lane & 15)) * FK_STRB + coff;
                ldsm_x4(kb[nb][0], kb[nb][1], kb[nb][2], kb[nb][3], addr);
            }
#pragma unroll
            for (int nb = 0; nb < 4; ++nb) {
                mma_f16(s[2*nb],   aq, kb[nb][0], kb[nb][2]);
                mma_f16(s[2*nb+1], aq, kb[nb][1], kb[nb][3]);
            }
        }

        bool boundary = (kt * 64 + 63 > qrow0);
        if (boundary) {
#pragma unroll
            for (int nt = 0; nt < 8; ++nt) {
                int c = kt * 64 + nt * 8 + fcol;
                int r0 = qrow0 + frow, r1 = r0 + 8;
                if (c     > r0) s[nt][0] = -INFINITY;
                if (c + 1 > r0) s[nt][1] = -INFINITY;
                if (c     > r1) s[nt][2] = -INFINITY;
                if (c + 1 > r1) s[nt][3] = -INFINITY;
            }
        }

        float mx0 = -INFINITY, mx1 = -INFINITY;
#pragma unroll
        for (int nt = 0; nt < 8; ++nt) {
            mx0 = fmaxf(mx0, fmaxf(s[nt][0], s[nt][1]));
            mx1 = fmaxf(mx1, fmaxf(s[nt][2], s[nt][3]));
        }
        mx0 = fmaxf(mx0, __shfl_xor_sync(0xFFFFFFFFu, mx0, 1));
        mx0 = fmaxf(mx0, __shfl_xor_sync(0xFFFFFFFFu, mx0, 2));
        mx1 = fmaxf(mx1, __shfl_xor_sync(0xFFFFFFFFu, mx1, 1));
        mx1 = fmaxf(mx1, __shfl_xor_sync(0xFFFFFFFFu, mx1, 2));
        mx0 = fmaxf(mx0, m0);
        mx1 = fmaxf(mx1, m1);
        float a0 = exp2f(m0 - mx0);
        float a1 = exp2f(m1 - mx1);
        float sum0 = 0.0f, sum1 = 0.0f;
#pragma unroll
        for (int nt = 0; nt < 8; ++nt) {
            s[nt][0] = exp2f(s[nt][0] - mx0); sum0 += s[nt][0];
            s[nt][1] = exp2f(s[nt][1] - mx0); sum0 += s[nt][1];
            s[nt][2] = exp2f(s[nt][2] - mx1); sum1 += s[nt][2];
            s[nt][3] = exp2f(s[nt][3] - mx1); sum1 += s[nt][3];
        }
        sum0 += __shfl_xor_sync(0xFFFFFFFFu, sum0, 1);
        sum0 += __shfl_xor_sync(0xFFFFFFFFu, sum0, 2);
        sum1 += __shfl_xor_sync(0xFFFFFFFFu, sum1, 1);
        sum1 += __shfl_xor_sync(0xFFFFFFFFu, sum1, 2);
        l0 = l0 * a0 + sum0;  m0 = mx0;
        l1 = l1 * a1 + sum1;  m1 = mx1;

#pragma unroll
        for (int nt = 0; nt < 16; ++nt) {
            o[nt][0] *= a0; o[nt][1] *= a0;
            o[nt][2] *= a1; o[nt][3] *= a1;
        }

#pragma unroll
        for (int j = 0; j < 4; ++j) {
            uint32_t ap[4];
            {
                __half ph[8];
#pragma unroll
                for (int e = 0; e < 4; ++e) {
                    ph[e]     = __float2half_rn(s[2*j][e]);
                    ph[4 + e] = __float2half_rn(s[2*j+1][e]);
                }
                ap[0] = pack_half2(ph[0], ph[1]);
                ap[1] = pack_half2(ph[2], ph[3]);
                ap[2] = pack_half2(ph[4], ph[5]);
                ap[3] = pack_half2(ph[6], ph[7]);
            }
#pragma unroll
            for (int g = 0; g < 2; ++g) {
                uint32_t vh[4][4];
#pragma unroll
                for (int q = 0; q < 4; ++q) {
                    int nb = g * 4 + q;
                    uint32_t addr = kvs + FKV_TILE
                                  + (j * 16 + (lane & 15)) * FK_STRB
                                  + (nb * 16 + (lane >> 4) * 8) * 2;
                    ldsm_x4_trans(vh[q][0], vh[q][1], vh[q][2], vh[q][3], addr);
                }
#pragma unroll
                for (int q = 0; q < 4; ++q) {
                    int nb = g * 4 + q;
                    mma_f16(o[2*nb],   ap, vh[q][0], vh[q][1]);
                    mma_f16(o[2*nb+1], ap, vh[q][2], vh[q][3]);
                }
            }
        }
    }

    {
        float li0 = 1.0f / l0;
        float li1 = 1.0f / l1;
        int r0g = b * TT + qt * 128 + wid * 16 + frow;
#pragma unroll
        for (int nt = 0; nt < 16; ++nt) {
            int c = nt * 8 + fcol;
            size_t o0 = (size_t)r0g * (HH*HD) + h * HD + c;
            size_t o1 = (size_t)(r0g + 8) * (HH*HD) + h * HD + c;
            *(__half2*)&Ohi[o0] = __halves2half2(__float2half_rn(o[nt][0] * li0),
                                                 __float2half_rn(o[nt][1] * li0));
            *(__half2*)&Ohi[o1] = __halves2half2(__float2half_rn(o[nt][2] * li1),
                                                 __float2half_rn(o[nt][3] * li1));
        }
    }
}

// ---------------------------------------------------------------------------
extern "C" void kernel_launch(void* const* d_in, const int* in_sizes, int n_in,
                              void* d_out, int out_size) {
    const float* x    = (const float*)d_in[0];
    const float* Wq   = (const float*)d_in[1];
    const float* Wk   = (const float*)d_in[2];
    const float* Wv   = (const float*)d_in[3];
    const float* Wo   = (const float*)d_in[4];
    const float* qn   = (const float*)d_in[5];
    const float* kn   = (const float*)d_in[6];
    const float* sinp = (const float*)d_in[7];
    const float* cosp = (const float*)d_in[8];
    float* out = (float*)d_out;

    __half *xhi, *wqt, *wkt, *wvt, *wot;
    __half *qhi, *khi, *vhi, *ohi;
    cudaGetSymbolAddress((void**)&xhi, g_xhi);
    cudaGetSymbolAddress((void**)&wqt, g_wqt);
    cudaGetSymbolAddress((void**)&wkt, g_wkt);
    cudaGetSymbolAddress((void**)&wvt, g_wvt);
    cudaGetSymbolAddress((void**)&wot, g_wot);
    cudaGetSymbolAddress((void**)&qhi, g_qhi);
    cudaGetSymbolAddress((void**)&khi, g_khi);
    cudaGetSymbolAddress((void**)&vhi, g_vhi);
    cudaGetSymbolAddress((void**)&ohi, g_ohi);

    // 1. fused prep
    prep_kernel<<<11264, 256>>>(x, Wq, Wk, Wv, Wo, xhi, wqt, wkt, wvt, wot);

    // 2. fused QKV projection + RMSNorm/RoPE epilogue
    cudaFuncSetAttribute(gemm_qkv, cudaFuncAttributeMaxDynamicSharedMemorySize, GSMEM_DYN);
    gemm_qkv<<<dim3(32, MTOT/128), 256, GSMEM_DYN>>>(xhi, wqt, wkt, wvt,
                                                     qhi, khi, vhi,
                                                     qn, kn, sinp, cosp);

    // 3. causal flash attention
    cudaFuncSetAttribute(flash_mma, cudaFuncAttributeMaxDynamicSharedMemorySize, FA5_SMEM);
    flash_mma<<<dim3(TT / 128, BB * HH), 256, FA5_SMEM>>>(qhi, khi, vhi, ohi);

    // 4. output projection
    cudaFuncSetAttribute(gemm_mma, cudaFuncAttributeMaxDynamicSharedMemorySize, GSMEM_DYN);
    gemm_mma<<<dim3((HH*HD)/128, MTOT/128), 256, GSMEM_DYN>>>(ohi, wot, out, HH*HD, HH*HD);
}